// round 3
// baseline (speedup 1.0000x reference)
#include <cuda_runtime.h>
#include <cuda_bf16.h>
#include <math.h>

// ---------------- problem constants ----------------
#define NB   32
#define NC   320
#define HH   64
#define WW   64
#define CTX  1024
#define NP   256      // 16x16 ctx spatial
#define NI   81       // 9x9 roi points
#define XNC  322      // 320 + 2 indicator channels
#define OUT_ATTN_OFF 41943040  // 32*320*64*64

// ---------------- device scratch (static, no allocation) ----------------
__device__ float g_ctx_t[NB * CTX * NP];    // raw context transposed [b][c][p]
__device__ float g_kmap [NB * CTX * NP];    // groupnormed ctx        [b][c][p]
__device__ float g_xn   [NB * XNC * NI];    // roi features (normed + indicator) [b][c][i]
__device__ float g_q    [NB * NC * NI];     // q_t [b][o][i]
__device__ float g_k    [NB * NC * NP];     // k_t [b][o][p]
__device__ float g_v    [NB * NC * NP];     // v_t [b][o][p]
__device__ float g_sim  [NB * NI * NP];     // sim [b][i][p]
__device__ float g_xo   [NB * NC * NI];     // xo  [b][o][i]

// ================= kernel 1: ctx transpose + group norm ==================
// grid 32*32 blocks (b,g), 256 threads. group = 32 channels x 256 p = 8192 elems.
__global__ __launch_bounds__(256) void k_ctx(const float* __restrict__ context,
                                             const float* __restrict__ cn_g,
                                             const float* __restrict__ cn_b) {
    int b = blockIdx.x >> 5, g = blockIdx.x & 31;
    __shared__ float s[32 * 257];
    __shared__ float redA[8], redB[8];
    __shared__ float stats[2];
    const float* src = context + (size_t)b * (NP * CTX) + g * 32;
    float sum = 0.f, sq = 0.f;
    for (int i = threadIdx.x; i < 8192; i += 256) {
        int cl = i & 31, p = i >> 5;
        float v = src[(size_t)p * CTX + cl];
        s[cl * 257 + p] = v;
        sum += v; sq += v * v;
    }
    #pragma unroll
    for (int off = 16; off; off >>= 1) {
        sum += __shfl_down_sync(0xffffffffu, sum, off);
        sq  += __shfl_down_sync(0xffffffffu, sq,  off);
    }
    if ((threadIdx.x & 31) == 0) { redA[threadIdx.x >> 5] = sum; redB[threadIdx.x >> 5] = sq; }
    __syncthreads();
    if (threadIdx.x == 0) {
        float a = 0.f, b2 = 0.f;
        #pragma unroll
        for (int w = 0; w < 8; w++) { a += redA[w]; b2 += redB[w]; }
        float mean = a * (1.f / 8192.f);
        float var  = b2 * (1.f / 8192.f) - mean * mean;
        stats[0] = mean; stats[1] = rsqrtf(var + 1e-6f);
    }
    __syncthreads();
    float mean = stats[0], rstd = stats[1];
    for (int i = threadIdx.x; i < 8192; i += 256) {
        int cl = i >> 8, p = i & 255;
        float v = s[cl * 257 + p];
        int c = g * 32 + cl;
        size_t o = (size_t)b * (CTX * NP) + (size_t)c * NP + p;
        g_ctx_t[o] = v;
        g_kmap[o]  = (v - mean) * rstd * cn_g[c] + cn_b[c];
    }
}

// ================= kernel 2a: roi bilinear samples (raw) ================
__global__ __launch_bounds__(256) void k_roi(const float* __restrict__ gx,
                                             const float* __restrict__ bbox,
                                             const float* __restrict__ indicator) {
    int idx = blockIdx.x * 256 + threadIdx.x;
    if (idx >= NB * XNC * NI) return;
    int b = idx / (XNC * NI);
    int r = idx - b * (XNC * NI);
    int c = r / NI;
    int i = r - c * NI;
    float out;
    if (c >= NC) {
        out = indicator[b * 2 + (c - NC)];
    } else {
        float x1 = bbox[b * 4 + 0], y1 = bbox[b * 4 + 1];
        float x2 = bbox[b * 4 + 2], y2 = bbox[b * 4 + 3];
        float rw = fmaxf(x2 - x1, 1.0f), rh = fmaxf(y2 - y1, 1.0f);
        int iy = i / 9, ix = i - iy * 9;
        float xs = x1 + ((float)ix + 0.5f) * (rw * (1.f / 9.f));
        float ys = y1 + ((float)iy + 0.5f) * (rh * (1.f / 9.f));
        float yv = fminf(fmaxf(ys, 0.f), 63.f);
        float xv = fminf(fmaxf(xs, 0.f), 63.f);
        int y0 = (int)floorf(yv), x0 = (int)floorf(xv);
        int y1i = min(y0 + 1, 63), x1i = min(x0 + 1, 63);
        float ly = yv - (float)y0, lx = xv - (float)x0;
        const float* im = gx + (size_t)b * (NC * HH * WW) + (size_t)c * (HH * WW);
        float g00 = im[y0 * WW + x0],  g01 = im[y0 * WW + x1i];
        float g10 = im[y1i * WW + x0], g11 = im[y1i * WW + x1i];
        out = g00 * (1.f - ly) * (1.f - lx) + g01 * (1.f - ly) * lx
            + g10 * ly * (1.f - lx)        + g11 * ly * lx;
    }
    g_xn[idx] = out;
}

// ============ kernel 2b: group norm over roi features (in place) =========
// grid 32*32 (b,g), group = 10 channels x 81 = 810 contiguous floats
__global__ __launch_bounds__(256) void k_gn_roi(const float* __restrict__ ln_g,
                                                const float* __restrict__ ln_b) {
    int b = blockIdx.x >> 5, g = blockIdx.x & 31;
    float* base = g_xn + (size_t)b * (XNC * NI) + g * 810;
    __shared__ float s[810];
    __shared__ float redA[8], redB[8];
    __shared__ float stats[2];
    float sum = 0.f, sq = 0.f;
    for (int i = threadIdx.x; i < 810; i += 256) {
        float v = base[i];
        s[i] = v; sum += v; sq += v * v;
    }
    #pragma unroll
    for (int off = 16; off; off >>= 1) {
        sum += __shfl_down_sync(0xffffffffu, sum, off);
        sq  += __shfl_down_sync(0xffffffffu, sq,  off);
    }
    if ((threadIdx.x & 31) == 0) { redA[threadIdx.x >> 5] = sum; redB[threadIdx.x >> 5] = sq; }
    __syncthreads();
    if (threadIdx.x == 0) {
        float a = 0.f, b2 = 0.f;
        #pragma unroll
        for (int w = 0; w < 8; w++) { a += redA[w]; b2 += redB[w]; }
        float mean = a * (1.f / 810.f);
        float var  = b2 * (1.f / 810.f) - mean * mean;
        stats[0] = mean; stats[1] = rsqrtf(var + 1e-6f);
    }
    __syncthreads();
    float mean = stats[0], rstd = stats[1];
    for (int i = threadIdx.x; i < 810; i += 256) {
        int c = g * 10 + i / 81;
        base[i] = (s[i] - mean) * rstd * ln_g[c] + ln_b[c];
    }
}

// ================= templated tiled SGEMM (BM=64, BN=128, Kc=16) ==========
// MODE 0: q  = w_in  @ xn      K=322,  N=81  per image, grid (32, 5)
// MODE 1: k  = w_ctx @ kmap    K=1024, N=256 per image, grid (64, 5)
// MODE 2: v  = w_out (*) ctx   K=9216 (implicit im2col), grid (64, 5)
template <int MODE>
__global__ __launch_bounds__(256) void k_gemm(const float* __restrict__ A,
                                              const float* __restrict__ bias) {
    constexpr int K = (MODE == 0) ? 322 : (MODE == 1 ? 1024 : 9216);
    __shared__ float sA[16][68];
    __shared__ float sB[16][128];
    int tid = threadIdx.x;
    int b, pbase;
    if (MODE == 0) { b = blockIdx.x; pbase = 0; }
    else           { b = blockIdx.x >> 1; pbase = (blockIdx.x & 1) * 128; }
    int mbase = blockIdx.y * 64;

    float acc[4][8];
    #pragma unroll
    for (int x = 0; x < 4; x++)
        #pragma unroll
        for (int y = 0; y < 8; y++) acc[x][y] = 0.f;

    int am = tid >> 2;        // 0..63
    int ak = (tid & 3) * 4;   // 0,4,8,12
    int bk = tid >> 4;        // 0..15
    int bn = (tid & 15) * 8;  // 0..120
    int tm = tid >> 4, tn = tid & 15;

    const float* abase = A + (size_t)(mbase + am) * K + ak;

    for (int k0 = 0; k0 < K; k0 += 16) {
        // ---- stage A (w matrix), transposed into sA[k][m] ----
        if (MODE == 0) {
            #pragma unroll
            for (int j = 0; j < 4; j++) {
                float v = 0.f;
                if (k0 + ak + j < 322) v = abase[k0 + j];
                sA[ak + j][am] = v;
            }
        } else {
            float4 a4 = *(const float4*)(abase + k0);
            sA[ak + 0][am] = a4.x; sA[ak + 1][am] = a4.y;
            sA[ak + 2][am] = a4.z; sA[ak + 3][am] = a4.w;
        }
        // ---- stage B ----
        int kk = k0 + bk;
        if (MODE == 0) {
            const float* bp = g_xn + (size_t)b * (XNC * NI) + (size_t)kk * NI;
            bool kok = kk < 322;
            #pragma unroll
            for (int j = 0; j < 8; j++) {
                int n = bn + j;
                sB[bk][bn + j] = (kok && n < NI) ? bp[n] : 0.f;
            }
        } else if (MODE == 1) {
            const float4* bp = (const float4*)(g_kmap + (size_t)b * (CTX * NP)
                                               + (size_t)kk * NP + pbase + bn);
            *(float4*)&sB[bk][bn]     = bp[0];
            *(float4*)&sB[bk][bn + 4] = bp[1];
        } else {
            int c = kk / 9, tap = kk - c * 9;
            int t3 = tap / 3;
            int dy = t3 - 1, dx = (tap - t3 * 3) - 1;
            const float* bp = g_ctx_t + (size_t)b * (CTX * NP) + (size_t)c * NP;
            #pragma unroll
            for (int j = 0; j < 8; j++) {
                int p = pbase + bn + j;
                int y = p >> 4, x = p & 15;
                int yy = y + dy, xx = x + dx;
                float v = 0.f;
                if ((unsigned)yy < 16u && (unsigned)xx < 16u) v = bp[yy * 16 + xx];
                sB[bk][bn + j] = v;
            }
        }
        __syncthreads();
        #pragma unroll
        for (int k = 0; k < 16; k++) {
            float4 a4 = *(const float4*)&sA[k][tm * 4];
            float4 b0 = *(const float4*)&sB[k][tn * 8];
            float4 b1 = *(const float4*)&sB[k][tn * 8 + 4];
            float a[4]  = {a4.x, a4.y, a4.z, a4.w};
            float bb[8] = {b0.x, b0.y, b0.z, b0.w, b1.x, b1.y, b1.z, b1.w};
            #pragma unroll
            for (int x = 0; x < 4; x++)
                #pragma unroll
                for (int y = 0; y < 8; y++)
                    acc[x][y] = fmaf(a[x], bb[y], acc[x][y]);
        }
        __syncthreads();
    }
    // ---- epilogue ----
    #pragma unroll
    for (int x = 0; x < 4; x++) {
        int o = mbase + tm * 4 + x;
        float bs = bias[o];
        #pragma unroll
        for (int y = 0; y < 8; y++) {
            int n = tn * 8 + y;
            float v = acc[x][y] + bs;
            if (MODE == 0) {
                if (n < NI) g_q[(size_t)b * (NC * NI) + (size_t)o * NI + n] = v;
            } else if (MODE == 1) {
                g_k[(size_t)b * (NC * NP) + (size_t)o * NP + pbase + n] = v;
            } else {
                g_v[(size_t)b * (NC * NP) + (size_t)o * NP + pbase + n] = v;
            }
        }
    }
}

// ================= kernel: sim = q^T k (81x256, K=320), per image =========
__global__ __launch_bounds__(256) void k_sim() {
    int b = blockIdx.x;
    __shared__ float sq[8][96];
    __shared__ float sk[8][256];
    int tid = threadIdx.x;
    int ti = tid >> 4;   // i block: 6 rows each
    int tp = tid & 15;   // p block: 16 cols each
    float acc[6][16];
    #pragma unroll
    for (int x = 0; x < 6; x++)
        #pragma unroll
        for (int y = 0; y < 16; y++) acc[x][y] = 0.f;

    for (int o0 = 0; o0 < NC; o0 += 8) {
        for (int idx = tid; idx < 8 * NI; idx += 256) {
            int ko = idx / NI, i = idx - ko * NI;
            sq[ko][i] = g_q[(size_t)b * (NC * NI) + (size_t)(o0 + ko) * NI + i];
        }
        {
            int ko = tid >> 5;
            int pp = (tid & 31) * 8;
            const float4* kp = (const float4*)(g_k + (size_t)b * (NC * NP)
                                               + (size_t)(o0 + ko) * NP + pp);
            *(float4*)&sk[ko][pp]     = kp[0];
            *(float4*)&sk[ko][pp + 4] = kp[1];
        }
        __syncthreads();
        #pragma unroll
        for (int ko = 0; ko < 8; ko++) {
            float a[6];
            #pragma unroll
            for (int x = 0; x < 6; x++) a[x] = sq[ko][ti * 6 + x];
            float4 b0 = *(const float4*)&sk[ko][tp * 16];
            float4 b1 = *(const float4*)&sk[ko][tp * 16 + 4];
            float4 b2 = *(const float4*)&sk[ko][tp * 16 + 8];
            float4 b3 = *(const float4*)&sk[ko][tp * 16 + 12];
            float bb[16] = {b0.x, b0.y, b0.z, b0.w, b1.x, b1.y, b1.z, b1.w,
                            b2.x, b2.y, b2.z, b2.w, b3.x, b3.y, b3.z, b3.w};
            #pragma unroll
            for (int x = 0; x < 6; x++)
                #pragma unroll
                for (int y = 0; y < 16; y++)
                    acc[x][y] = fmaf(a[x], bb[y], acc[x][y]);
        }
        __syncthreads();
    }
    #pragma unroll
    for (int x = 0; x < 6; x++) {
        int i = ti * 6 + x;
        if (i < NI) {
            #pragma unroll
            for (int y = 0; y < 16; y++)
                g_sim[(size_t)b * (NI * NP) + (size_t)i * NP + tp * 16 + y] = acc[x][y];
        }
    }
}

// ================= kernel: softmax rows -> attn (written to d_out) =======
__global__ __launch_bounds__(256) void k_softmax(float* __restrict__ attn_out) {
    int b = blockIdx.x / NI, i = blockIdx.x - b * NI;
    int t = threadIdx.x;
    __shared__ float red[8];
    __shared__ float bc[1];
    float v = g_sim[(size_t)b * (NI * NP) + (size_t)i * NP + t];
    float m = v;
    #pragma unroll
    for (int off = 16; off; off >>= 1) m = fmaxf(m, __shfl_xor_sync(0xffffffffu, m, off));
    if ((t & 31) == 0) red[t >> 5] = m;
    __syncthreads();
    if (t == 0) {
        float mm = red[0];
        #pragma unroll
        for (int w = 1; w < 8; w++) mm = fmaxf(mm, red[w]);
        bc[0] = mm;
    }
    __syncthreads();
    float e = expf(v - bc[0]);
    float s = e;
    #pragma unroll
    for (int off = 16; off; off >>= 1) s += __shfl_xor_sync(0xffffffffu, s, off);
    if ((t & 31) == 0) red[t >> 5] = s;
    __syncthreads();
    if (t == 0) {
        float ss = 0.f;
        #pragma unroll
        for (int w = 0; w < 8; w++) ss += red[w];
        bc[0] = 1.f / ss;
    }
    __syncthreads();
    attn_out[(size_t)b * (NI * NP) + (size_t)i * NP + t] = e * bc[0];
}

// ================= kernel: xo = v_t @ attn^T (320x81, K=256) ==============
__global__ __launch_bounds__(256) void k_xo(const float* __restrict__ attn) {
    int b = blockIdx.x;
    int mbase = blockIdx.y * 64;
    __shared__ float sv[16][68];
    __shared__ float sa[16][96];
    int tid = threadIdx.x;
    int am = tid >> 2, ak = (tid & 3) * 4;
    int tm = tid >> 4, tn = tid & 15;
    float acc[4][6];
    #pragma unroll
    for (int x = 0; x < 4; x++)
        #pragma unroll
        for (int y = 0; y < 6; y++) acc[x][y] = 0.f;

    for (int p0 = 0; p0 < NP; p0 += 16) {
        float4 v4 = *(const float4*)(g_v + (size_t)b * (NC * NP)
                                     + (size_t)(mbase + am) * NP + p0 + ak);
        sv[ak + 0][am] = v4.x; sv[ak + 1][am] = v4.y;
        sv[ak + 2][am] = v4.z; sv[ak + 3][am] = v4.w;
        for (int idx = tid; idx < 16 * NI; idx += 256) {
            int ii = idx >> 4, pp = idx & 15;
            sa[pp][ii] = attn[(size_t)b * (NI * NP) + (size_t)ii * NP + p0 + pp];
        }
        __syncthreads();
        #pragma unroll
        for (int p = 0; p < 16; p++) {
            float4 a4 = *(const float4*)&sv[p][tm * 4];
            float a[4] = {a4.x, a4.y, a4.z, a4.w};
            float bb[6];
            #pragma unroll
            for (int y = 0; y < 6; y++) bb[y] = sa[p][tn * 6 + y];
            #pragma unroll
            for (int x = 0; x < 4; x++)
                #pragma unroll
                for (int y = 0; y < 6; y++)
                    acc[x][y] = fmaf(a[x], bb[y], acc[x][y]);
        }
        __syncthreads();
    }
    #pragma unroll
    for (int x = 0; x < 4; x++) {
        int o = mbase + tm * 4 + x;
        #pragma unroll
        for (int y = 0; y < 6; y++) {
            int i = tn * 6 + y;
            if (i < NI) g_xo[(size_t)b * (NC * NI) + (size_t)o * NI + i] = acc[x][y];
        }
    }
}

// ========== kernel: residual + masked scatter of xo back into image =======
__global__ __launch_bounds__(256) void k_out(const float* __restrict__ gx,
                                             const float* __restrict__ bbox,
                                             float* __restrict__ out) {
    int idx = blockIdx.x * 256 + threadIdx.x;
    int x = idx & 63;
    int y = (idx >> 6) & 63;
    int bc = idx >> 12;
    int b = bc / NC;
    int c = bc - b * NC;
    float val = gx[idx];
    int bx1 = (int)(bbox[b * 4 + 0] * 64.f);
    int by1 = (int)(bbox[b * 4 + 1] * 64.f);
    int bx2 = max((int)(bbox[b * 4 + 2] * 64.f), bx1 + 1);
    int by2 = max((int)(bbox[b * 4 + 3] * 64.f), by1 + 1);
    if (y >= by1 && y < by2 && x >= bx1 && x < bx2) {
        int sy = min(max((y - by1) * 9 / (by2 - by1), 0), 8);
        int sx = min(max((x - bx1) * 9 / (bx2 - bx1), 0), 8);
        val += g_xo[(size_t)b * (NC * NI) + (size_t)c * NI + sy * 9 + sx];
    }
    out[idx] = val;
}

// ============================ launch ======================================
extern "C" void kernel_launch(void* const* d_in, const int* in_sizes, int n_in,
                              void* d_out, int out_size) {
    const float* global_x  = (const float*)d_in[0];
    const float* context   = (const float*)d_in[1];
    const float* indicator = (const float*)d_in[2];
    const float* bbox      = (const float*)d_in[3];
    const float* ln_g      = (const float*)d_in[4];
    const float* ln_b      = (const float*)d_in[5];
    const float* cn_g      = (const float*)d_in[6];
    const float* cn_b      = (const float*)d_in[7];
    const float* w_in      = (const float*)d_in[8];
    const float* b_in      = (const float*)d_in[9];
    const float* w_ctx     = (const float*)d_in[10];
    const float* b_ctx     = (const float*)d_in[11];
    const float* w_out     = (const float*)d_in[12];
    const float* b_out     = (const float*)d_in[13];
    float* out  = (float*)d_out;
    float* attn = out + OUT_ATTN_OFF;

    k_ctx<<<NB * 32, 256>>>(context, cn_g, cn_b);
    k_roi<<<(NB * XNC * NI + 255) / 256, 256>>>(global_x, bbox, indicator);
    k_gn_roi<<<NB * 32, 256>>>(ln_g, ln_b);
    k_gemm<0><<<dim3(32, 5), 256>>>(w_in, b_in);
    k_gemm<1><<<dim3(64, 5), 256>>>(w_ctx, b_ctx);
    k_gemm<2><<<dim3(64, 5), 256>>>(w_out, b_out);
    k_sim<<<NB, 256>>>();
    k_softmax<<<NB * NI, 256>>>(attn);
    k_xo<<<dim3(NB, 5), 256>>>(attn);
    k_out<<<(NB * NC * HH * WW) / 256, 256>>>(global_x, bbox, out);
}

// round 5
// speedup vs baseline: 2.3946x; 2.3946x over previous
#include <cuda_runtime.h>
#include <cuda_bf16.h>
#include <math.h>
#include <stdint.h>

// ---------------- problem constants ----------------
#define NB   32
#define NC   320
#define HH   64
#define WW   64
#define CTX  1024
#define NP   256      // 16x16 ctx spatial
#define NI   81       // 9x9 roi points
#define XNC  322      // 320 + 2 indicator channels
#define KK   9216     // conv GEMM K = 1024*9
#define OUT_ATTN_OFF 41943040  // 32*320*64*64

// ---------------- device scratch (static, no allocation) ----------------
__device__ float g_kmap [NB * CTX * NP];    // groupnormed ctx [b][c][p]
__device__ float g_xn   [NB * XNC * NI];    // roi features [b][c][i]
__device__ float g_q    [NB * NC * NI];
__device__ float g_k    [NB * NC * NP];
__device__ float g_v    [NB * NC * NP];
__device__ float g_sim  [NB * NI * NP];
__device__ float g_xo   [NB * NC * NI];
// bf16 hi/lo split operands for tensor-core conv
__device__ __align__(16) __nv_bfloat16 g_cxh[NB * NP * CTX];  // context hi [b][p][c]
__device__ __align__(16) __nv_bfloat16 g_cxl[NB * NP * CTX];  // context lo
__device__ __align__(16) __nv_bfloat16 g_wh [NC * KK];        // w_out hi [o][tap*1024+c]
__device__ __align__(16) __nv_bfloat16 g_wl [NC * KK];        // w_out lo

// =================== helpers (baseline PTX only) ========================
__device__ __forceinline__ uint32_t smem_u32(const void* p) {
    uint32_t a;
    asm("{ .reg .u64 t; cvta.to.shared.u64 t, %1; cvt.u32.u64 %0, t; }" : "=r"(a) : "l"(p));
    return a;
}
#define CP16(dst, src, sz) \
    asm volatile("cp.async.ca.shared.global [%0], [%1], 16, %2;" \
                 :: "r"(dst), "l"(src), "r"(sz))
#define CP_COMMIT() asm volatile("cp.async.commit_group;" ::: "memory")
#define CP_WAIT(n)  asm volatile("cp.async.wait_group %0;" :: "n"(n) : "memory")

__device__ __forceinline__ void mma16816(float* c, const uint32_t* a, const uint32_t* b) {
    asm volatile("mma.sync.aligned.m16n8k16.row.col.f32.bf16.bf16.f32 "
        "{%0,%1,%2,%3}, {%4,%5,%6,%7}, {%8,%9}, {%0,%1,%2,%3};"
        : "+f"(c[0]), "+f"(c[1]), "+f"(c[2]), "+f"(c[3])
        : "r"(a[0]), "r"(a[1]), "r"(a[2]), "r"(a[3]), "r"(b[0]), "r"(b[1]));
}

// ================= prep: bf16 hi/lo splits ==============================
__global__ __launch_bounds__(256) void k_cvt_ctx(const float* __restrict__ context) {
    int idx = blockIdx.x * 256 + threadIdx.x;   // NB*NP*CTX
    float v = context[idx];
    __nv_bfloat16 h = __float2bfloat16(v);
    g_cxh[idx] = h;
    g_cxl[idx] = __float2bfloat16(v - __bfloat162float(h));
}
__global__ __launch_bounds__(256) void k_cvt_w(const float* __restrict__ w_out) {
    int idx = blockIdx.x * 256 + threadIdx.x;   // NC*KK
    int o = idx / KK, r = idx - o * KK;
    int tap = r >> 10, c = r & 1023;
    float v = w_out[o * KK + c * 9 + tap];
    __nv_bfloat16 h = __float2bfloat16(v);
    g_wh[idx] = h;
    g_wl[idx] = __float2bfloat16(v - __bfloat162float(h));
}

// ============== mma.sync conv: v = w_out (*) ctx + b_out =================
// 96 CTAs = 32 imgs x 3 M-tiles(128). Per CTA: M=128, N=256, K=9216,
// K-chunks of 64, cp.async double buffer, 3xBF16 split, fp32 accum in regs.
// SMEM rows padded to 72 bf16 (144B) -> conflict-free fragment loads.
#define SA_H 0
#define SA_L 18432
#define SB_H 36864
#define SB_L 73728
#define BUFSTRIDE 110592
#define CONV_SMEM (2 * BUFSTRIDE)
#define NCHUNK 144

__global__ void __launch_bounds__(512, 1) k_conv(const float* __restrict__ bias) {
    extern __shared__ char smem[];
    uint32_t sb = smem_u32(smem);
    int tid = threadIdx.x;
    int bimg = blockIdx.x / 3;
    int mt   = blockIdx.x - bimg * 3;
    int mbase = mt * 128;
    const __nv_bfloat16* cxh = g_cxh + (size_t)bimg * (NP * CTX);
    const __nv_bfloat16* cxl = g_cxl + (size_t)bimg * (NP * CTX);

    auto load_chunk = [&](int buf, int ch) {
        int tap = ch >> 4, c0 = (ch & 15) << 6;
        int t3 = tap / 3;
        int dy = t3 - 1, dx = tap - t3 * 3 - 1;
        uint32_t base = sb + buf * BUFSTRIDE;
        // A (weights hi/lo): 128 rows x 64 bf16
        #pragma unroll
        for (int r = 0; r < 2; r++) {
            int id = r * 512 + tid;
            int row = id >> 3, v = id & 7;
            int o = mbase + row;
            int ok = (o < NC) ? 16 : 0;
            size_t so = ok ? ((size_t)o * KK + tap * 1024 + c0 + v * 8) : 0;
            uint32_t dst = base + SA_H + (uint32_t)(row * 144 + v * 16);
            CP16(dst, g_wh + so, ok);
            CP16(dst + (SA_L - SA_H), g_wl + so, ok);
        }
        // B (im2col context hi/lo): 256 rows x 64 bf16
        #pragma unroll
        for (int r = 0; r < 4; r++) {
            int id = r * 512 + tid;
            int row = id >> 3, v = id & 7;
            int yy = (row >> 4) + dy, xx = (row & 15) + dx;
            int ok = ((unsigned)yy < 16u && (unsigned)xx < 16u) ? 16 : 0;
            size_t so = ok ? ((size_t)(yy * 16 + xx) * CTX + c0 + v * 8) : 0;
            uint32_t dst = base + SB_H + (uint32_t)(row * 144 + v * 16);
            CP16(dst, cxh + so, ok);
            CP16(dst + (SB_L - SB_H), cxl + so, ok);
        }
    };

    int w = tid >> 5, l = tid & 31;
    int wm = w >> 2;            // 0..3  (m: 32 each)
    int wn = (w & 3) * 64;      // 0,64,128,192 (n: 64 each)
    int g = l >> 2, tg = l & 3;

    float acc[2][8][4];
    #pragma unroll
    for (int i = 0; i < 2; i++)
        #pragma unroll
        for (int j = 0; j < 8; j++)
            #pragma unroll
            for (int q = 0; q < 4; q++) acc[i][j][q] = 0.f;

    auto compute = [&](int buf) {
        const uint32_t* pAh = (const uint32_t*)(smem + buf * BUFSTRIDE + SA_H);
        const uint32_t* pAl = (const uint32_t*)(smem + buf * BUFSTRIDE + SA_L);
        const uint32_t* pBh = (const uint32_t*)(smem + buf * BUFSTRIDE + SB_H);
        const uint32_t* pBl = (const uint32_t*)(smem + buf * BUFSTRIDE + SB_L);
        #pragma unroll
        for (int s = 0; s < 4; s++) {
            int kb = s * 8 + tg;          // u32 index within a 36-u32 row
            uint32_t ah[2][4], al[2][4];
            #pragma unroll
            for (int i = 0; i < 2; i++) {
                int r0 = (wm * 32 + i * 16 + g) * 36;
                int r8 = r0 + 8 * 36;
                ah[i][0] = pAh[r0 + kb];     ah[i][1] = pAh[r8 + kb];
                ah[i][2] = pAh[r0 + kb + 4]; ah[i][3] = pAh[r8 + kb + 4];
                al[i][0] = pAl[r0 + kb];     al[i][1] = pAl[r8 + kb];
                al[i][2] = pAl[r0 + kb + 4]; al[i][3] = pAl[r8 + kb + 4];
            }
            #pragma unroll
            for (int j = 0; j < 8; j++) {
                int n = (wn + j * 8 + g) * 36;
                uint32_t bh[2] = { pBh[n + kb], pBh[n + kb + 4] };
                uint32_t bl[2] = { pBl[n + kb], pBl[n + kb + 4] };
                #pragma unroll
                for (int i = 0; i < 2; i++) {
                    mma16816(acc[i][j], ah[i], bh);
                    mma16816(acc[i][j], ah[i], bl);
                    mma16816(acc[i][j], al[i], bh);
                }
            }
        }
    };

    load_chunk(0, 0);
    CP_COMMIT();
    for (int ch = 0; ch < NCHUNK; ch++) {
        if (ch + 1 < NCHUNK) {
            load_chunk((ch + 1) & 1, ch + 1);
            CP_COMMIT();
            CP_WAIT(1);
        } else {
            CP_WAIT(0);
        }
        __syncthreads();
        compute(ch & 1);
        __syncthreads();
    }

    // ---- epilogue: acc + bias -> g_v ----
    float* vbase = g_v + (size_t)bimg * (NC * NP);
    #pragma unroll
    for (int i = 0; i < 2; i++) {
        int o0 = mbase + wm * 32 + i * 16 + g;
        int o1 = o0 + 8;
        float b0 = (o0 < NC) ? bias[o0] : 0.f;
        float b1 = (o1 < NC) ? bias[o1] : 0.f;
        #pragma unroll
        for (int j = 0; j < 8; j++) {
            int p = wn + j * 8 + tg * 2;
            if (o0 < NC)
                *(float2*)(vbase + (size_t)o0 * NP + p)
                    = make_float2(acc[i][j][0] + b0, acc[i][j][1] + b0);
            if (o1 < NC)
                *(float2*)(vbase + (size_t)o1 * NP + p)
                    = make_float2(acc[i][j][2] + b1, acc[i][j][3] + b1);
        }
    }
}

// ================= kernel 1: ctx transpose + group norm ==================
__global__ __launch_bounds__(256) void k_ctx(const float* __restrict__ context,
                                             const float* __restrict__ cn_g,
                                             const float* __restrict__ cn_b) {
    int b = blockIdx.x >> 5, g = blockIdx.x & 31;
    __shared__ float s[32 * 257];
    __shared__ float redA[8], redB[8];
    __shared__ float stats[2];
    const float* src = context + (size_t)b * (NP * CTX) + g * 32;
    float sum = 0.f, sq = 0.f;
    for (int i = threadIdx.x; i < 8192; i += 256) {
        int cl = i & 31, p = i >> 5;
        float v = src[(size_t)p * CTX + cl];
        s[cl * 257 + p] = v;
        sum += v; sq += v * v;
    }
    #pragma unroll
    for (int off = 16; off; off >>= 1) {
        sum += __shfl_down_sync(0xffffffffu, sum, off);
        sq  += __shfl_down_sync(0xffffffffu, sq,  off);
    }
    if ((threadIdx.x & 31) == 0) { redA[threadIdx.x >> 5] = sum; redB[threadIdx.x >> 5] = sq; }
    __syncthreads();
    if (threadIdx.x == 0) {
        float a = 0.f, b2 = 0.f;
        #pragma unroll
        for (int w = 0; w < 8; w++) { a += redA[w]; b2 += redB[w]; }
        float mean = a * (1.f / 8192.f);
        float var  = b2 * (1.f / 8192.f) - mean * mean;
        stats[0] = mean; stats[1] = rsqrtf(var + 1e-6f);
    }
    __syncthreads();
    float mean = stats[0], rstd = stats[1];
    for (int i = threadIdx.x; i < 8192; i += 256) {
        int cl = i >> 8, p = i & 255;
        float v = s[cl * 257 + p];
        int c = g * 32 + cl;
        g_kmap[(size_t)b * (CTX * NP) + (size_t)c * NP + p]
            = (v - mean) * rstd * cn_g[c] + cn_b[c];
    }
}

// ================= kernel 2a: roi bilinear samples ======================
__global__ __launch_bounds__(256) void k_roi(const float* __restrict__ gx,
                                             const float* __restrict__ bbox,
                                             const float* __restrict__ indicator) {
    int idx = blockIdx.x * 256 + threadIdx.x;
    if (idx >= NB * XNC * NI) return;
    int b = idx / (XNC * NI);
    int r = idx - b * (XNC * NI);
    int c = r / NI;
    int i = r - c * NI;
    float out;
    if (c >= NC) {
        out = indicator[b * 2 + (c - NC)];
    } else {
        float x1 = bbox[b * 4 + 0], y1 = bbox[b * 4 + 1];
        float x2 = bbox[b * 4 + 2], y2 = bbox[b * 4 + 3];
        float rw = fmaxf(x2 - x1, 1.0f), rh = fmaxf(y2 - y1, 1.0f);
        int iy = i / 9, ix = i - iy * 9;
        float xs = x1 + ((float)ix + 0.5f) * (rw * (1.f / 9.f));
        float ys = y1 + ((float)iy + 0.5f) * (rh * (1.f / 9.f));
        float yv = fminf(fmaxf(ys, 0.f), 63.f);
        float xv = fminf(fmaxf(xs, 0.f), 63.f);
        int y0 = (int)floorf(yv), x0 = (int)floorf(xv);
        int y1i = min(y0 + 1, 63), x1i = min(x0 + 1, 63);
        float ly = yv - (float)y0, lx = xv - (float)x0;
        const float* im = gx + (size_t)b * (NC * HH * WW) + (size_t)c * (HH * WW);
        float g00 = im[y0 * WW + x0],  g01 = im[y0 * WW + x1i];
        float g10 = im[y1i * WW + x0], g11 = im[y1i * WW + x1i];
        out = g00 * (1.f - ly) * (1.f - lx) + g01 * (1.f - ly) * lx
            + g10 * ly * (1.f - lx)        + g11 * ly * lx;
    }
    g_xn[idx] = out;
}

// ============ kernel 2b: group norm over roi features ====================
__global__ __launch_bounds__(256) void k_gn_roi(const float* __restrict__ ln_g,
                                                const float* __restrict__ ln_b) {
    int b = blockIdx.x >> 5, g = blockIdx.x & 31;
    float* base = g_xn + (size_t)b * (XNC * NI) + g * 810;
    __shared__ float s[810];
    __shared__ float redA[8], redB[8];
    __shared__ float stats[2];
    float sum = 0.f, sq = 0.f;
    for (int i = threadIdx.x; i < 810; i += 256) {
        float v = base[i];
        s[i] = v; sum += v; sq += v * v;
    }
    #pragma unroll
    for (int off = 16; off; off >>= 1) {
        sum += __shfl_down_sync(0xffffffffu, sum, off);
        sq  += __shfl_down_sync(0xffffffffu, sq,  off);
    }
    if ((threadIdx.x & 31) == 0) { redA[threadIdx.x >> 5] = sum; redB[threadIdx.x >> 5] = sq; }
    __syncthreads();
    if (threadIdx.x == 0) {
        float a = 0.f, b2 = 0.f;
        #pragma unroll
        for (int w = 0; w < 8; w++) { a += redA[w]; b2 += redB[w]; }
        float mean = a * (1.f / 810.f);
        float var  = b2 * (1.f / 810.f) - mean * mean;
        stats[0] = mean; stats[1] = rsqrtf(var + 1e-6f);
    }
    __syncthreads();
    float mean = stats[0], rstd = stats[1];
    for (int i = threadIdx.x; i < 810; i += 256) {
        int c = g * 10 + i / 81;
        base[i] = (s[i] - mean) * rstd * ln_g[c] + ln_b[c];
    }
}

// ================= templated tiled SGEMM (BM=64, BN=128, Kc=16) ==========
// MODE 0: q = w_in  @ xn    K=322,  N=81  per image
// MODE 1: k = w_ctx @ kmap  K=1024, N=256 per image
template <int MODE>
__global__ __launch_bounds__(256) void k_gemm(const float* __restrict__ A,
                                              const float* __restrict__ bias) {
    constexpr int K = (MODE == 0) ? 322 : 1024;
    __shared__ float sA[16][68];
    __shared__ float sB[16][128];
    int tid = threadIdx.x;
    int b, pbase;
    if (MODE == 0) { b = blockIdx.x; pbase = 0; }
    else           { b = blockIdx.x >> 1; pbase = (blockIdx.x & 1) * 128; }
    int mbase = blockIdx.y * 64;

    float acc[4][8];
    #pragma unroll
    for (int x = 0; x < 4; x++)
        #pragma unroll
        for (int y = 0; y < 8; y++) acc[x][y] = 0.f;

    int am = tid >> 2;
    int ak = (tid & 3) * 4;
    int bk = tid >> 4;
    int bn = (tid & 15) * 8;
    int tm = tid >> 4, tn = tid & 15;

    const float* abase = A + (size_t)(mbase + am) * K + ak;

    for (int k0 = 0; k0 < K; k0 += 16) {
        if (MODE == 0) {
            #pragma unroll
            for (int j = 0; j < 4; j++) {
                float v = 0.f;
                if (k0 + ak + j < 322) v = abase[k0 + j];
                sA[ak + j][am] = v;
            }
        } else {
            float4 a4 = *(const float4*)(abase + k0);
            sA[ak + 0][am] = a4.x; sA[ak + 1][am] = a4.y;
            sA[ak + 2][am] = a4.z; sA[ak + 3][am] = a4.w;
        }
        int kk = k0 + bk;
        if (MODE == 0) {
            const float* bp = g_xn + (size_t)b * (XNC * NI) + (size_t)kk * NI;
            bool kok = kk < 322;
            #pragma unroll
            for (int j = 0; j < 8; j++) {
                int n = bn + j;
                sB[bk][bn + j] = (kok && n < NI) ? bp[n] : 0.f;
            }
        } else {
            const float4* bp = (const float4*)(g_kmap + (size_t)b * (CTX * NP)
                                               + (size_t)kk * NP + pbase + bn);
            *(float4*)&sB[bk][bn]     = bp[0];
            *(float4*)&sB[bk][bn + 4] = bp[1];
        }
        __syncthreads();
        #pragma unroll
        for (int k = 0; k < 16; k++) {
            float4 a4 = *(const float4*)&sA[k][tm * 4];
            float4 b0 = *(const float4*)&sB[k][tn * 8];
            float4 b1 = *(const float4*)&sB[k][tn * 8 + 4];
            float a[4]  = {a4.x, a4.y, a4.z, a4.w};
            float bb[8] = {b0.x, b0.y, b0.z, b0.w, b1.x, b1.y, b1.z, b1.w};
            #pragma unroll
            for (int x = 0; x < 4; x++)
                #pragma unroll
                for (int y = 0; y < 8; y++)
                    acc[x][y] = fmaf(a[x], bb[y], acc[x][y]);
        }
        __syncthreads();
    }
    #pragma unroll
    for (int x = 0; x < 4; x++) {
        int o = mbase + tm * 4 + x;
        float bs = bias[o];
        #pragma unroll
        for (int y = 0; y < 8; y++) {
            int n = tn * 8 + y;
            float v = acc[x][y] + bs;
            if (MODE == 0) {
                if (n < NI) g_q[(size_t)b * (NC * NI) + (size_t)o * NI + n] = v;
            } else {
                g_k[(size_t)b * (NC * NP) + (size_t)o * NP + pbase + n] = v;
            }
        }
    }
}

// ================= kernel: sim = q^T k (81x256, K=320) ===================
__global__ __launch_bounds__(256) void k_sim() {
    int b = blockIdx.x;
    __shared__ float sq[8][96];
    __shared__ float sk[8][256];
    int tid = threadIdx.x;
    int ti = tid >> 4;
    int tp = tid & 15;
    float acc[6][16];
    #pragma unroll
    for (int x = 0; x < 6; x++)
        #pragma unroll
        for (int y = 0; y < 16; y++) acc[x][y] = 0.f;

    for (int o0 = 0; o0 < NC; o0 += 8) {
        for (int idx = tid; idx < 8 * NI; idx += 256) {
            int ko = idx / NI, i = idx - ko * NI;
            sq[ko][i] = g_q[(size_t)b * (NC * NI) + (size_t)(o0 + ko) * NI + i];
        }
        {
            int ko = tid >> 5;
            int pp = (tid & 31) * 8;
            const float4* kp = (const float4*)(g_k + (size_t)b * (NC * NP)
                                               + (size_t)(o0 + ko) * NP + pp);
            *(float4*)&sk[ko][pp]     = kp[0];
            *(float4*)&sk[ko][pp + 4] = kp[1];
        }
        __syncthreads();
        #pragma unroll
        for (int ko = 0; ko < 8; ko++) {
            float a[6];
            #pragma unroll
            for (int x = 0; x < 6; x++) a[x] = sq[ko][ti * 6 + x];
            float4 b0 = *(const float4*)&sk[ko][tp * 16];
            float4 b1 = *(const float4*)&sk[ko][tp * 16 + 4];
            float4 b2 = *(const float4*)&sk[ko][tp * 16 + 8];
            float4 b3 = *(const float4*)&sk[ko][tp * 16 + 12];
            float bb[16] = {b0.x, b0.y, b0.z, b0.w, b1.x, b1.y, b1.z, b1.w,
                            b2.x, b2.y, b2.z, b2.w, b3.x, b3.y, b3.z, b3.w};
            #pragma unroll
            for (int x = 0; x < 6; x++)
                #pragma unroll
                for (int y = 0; y < 16; y++)
                    acc[x][y] = fmaf(a[x], bb[y], acc[x][y]);
        }
        __syncthreads();
    }
    #pragma unroll
    for (int x = 0; x < 6; x++) {
        int i = ti * 6 + x;
        if (i < NI) {
            #pragma unroll
            for (int y = 0; y < 16; y++)
                g_sim[(size_t)b * (NI * NP) + (size_t)i * NP + tp * 16 + y] = acc[x][y];
        }
    }
}

// ================= kernel: softmax rows -> attn ==========================
__global__ __launch_bounds__(256) void k_softmax(float* __restrict__ attn_out) {
    int b = blockIdx.x / NI, i = blockIdx.x - b * NI;
    int t = threadIdx.x;
    __shared__ float red[8];
    __shared__ float bc[1];
    float v = g_sim[(size_t)b * (NI * NP) + (size_t)i * NP + t];
    float m = v;
    #pragma unroll
    for (int off = 16; off; off >>= 1) m = fmaxf(m, __shfl_xor_sync(0xffffffffu, m, off));
    if ((t & 31) == 0) red[t >> 5] = m;
    __syncthreads();
    if (t == 0) {
        float mm = red[0];
        #pragma unroll
        for (int w = 1; w < 8; w++) mm = fmaxf(mm, red[w]);
        bc[0] = mm;
    }
    __syncthreads();
    float e = expf(v - bc[0]);
    float s = e;
    #pragma unroll
    for (int off = 16; off; off >>= 1) s += __shfl_xor_sync(0xffffffffu, s, off);
    if ((t & 31) == 0) red[t >> 5] = s;
    __syncthreads();
    if (t == 0) {
        float ss = 0.f;
        #pragma unroll
        for (int w = 0; w < 8; w++) ss += red[w];
        bc[0] = 1.f / ss;
    }
    __syncthreads();
    attn_out[(size_t)b * (NI * NP) + (size_t)i * NP + t] = e * bc[0];
}

// ================= kernel: xo = v_t @ attn^T (320x81, K=256) =============
__global__ __launch_bounds__(256) void k_xo(const float* __restrict__ attn) {
    int b = blockIdx.x;
    int mbase = blockIdx.y * 64;
    __shared__ float sv[16][68];
    __shared__ float sa[16][96];
    int tid = threadIdx.x;
    int am = tid >> 2, ak = (tid & 3) * 4;
    int tm = tid >> 4, tn = tid & 15;
    float acc[4][6];
    #pragma unroll
    for (int x = 0; x < 4; x++)
        #pragma unroll
        for (int y = 0; y < 6; y++) acc[x][y] = 0.f;

    for (int p0 = 0; p0 < NP; p0 += 16) {
        float4 v4 = *(const float4*)(g_v + (size_t)b * (NC * NP)
                                     + (size_t)(mbase + am) * NP + p0 + ak);
        sv[ak + 0][am] = v4.x; sv[ak + 1][am] = v4.y;
        sv[ak + 2][am] = v4.z; sv[ak + 3][am] = v4.w;
        for (int idx = tid; idx < 16 * NI; idx += 256) {
            int ii = idx >> 4, pp = idx & 15;
            sa[pp][ii] = attn[(size_t)b * (NI * NP) + (size_t)ii * NP + p0 + pp];
        }
        __syncthreads();
        #pragma unroll
        for (int p = 0; p < 16; p++) {
            float4 a4 = *(const float4*)&sv[p][tm * 4];
            float a[4] = {a4.x, a4.y, a4.z, a4.w};
            float bb[6];
            #pragma unroll
            for (int y = 0; y < 6; y++) bb[y] = sa[p][tn * 6 + y];
            #pragma unroll
            for (int x = 0; x < 4; x++)
                #pragma unroll
                for (int y = 0; y < 6; y++)
                    acc[x][y] = fmaf(a[x], bb[y], acc[x][y]);
        }
        __syncthreads();
    }
    #pragma unroll
    for (int x = 0; x < 4; x++) {
        int o = mbase + tm * 4 + x;
        #pragma unroll
        for (int y = 0; y < 6; y++) {
            int i = tn * 6 + y;
            if (i < NI) g_xo[(size_t)b * (NC * NI) + (size_t)o * NI + i] = acc[x][y];
        }
    }
}

// ========== kernel: residual + masked scatter ============================
__global__ __launch_bounds__(256) void k_out(const float* __restrict__ gx,
                                             const float* __restrict__ bbox,
                                             float* __restrict__ out) {
    int idx = blockIdx.x * 256 + threadIdx.x;
    int x = idx & 63;
    int y = (idx >> 6) & 63;
    int bc = idx >> 12;
    int b = bc / NC;
    int c = bc - b * NC;
    float val = gx[idx];
    int bx1 = (int)(bbox[b * 4 + 0] * 64.f);
    int by1 = (int)(bbox[b * 4 + 1] * 64.f);
    int bx2 = max((int)(bbox[b * 4 + 2] * 64.f), bx1 + 1);
    int by2 = max((int)(bbox[b * 4 + 3] * 64.f), by1 + 1);
    if (y >= by1 && y < by2 && x >= bx1 && x < bx2) {
        int sy = min(max((y - by1) * 9 / (by2 - by1), 0), 8);
        int sx = min(max((x - bx1) * 9 / (bx2 - bx1), 0), 8);
        val += g_xo[(size_t)b * (NC * NI) + (size_t)c * NI + sy * 9 + sx];
    }
    out[idx] = val;
}

// ============================ launch ======================================
extern "C" void kernel_launch(void* const* d_in, const int* in_sizes, int n_in,
                              void* d_out, int out_size) {
    const float* global_x  = (const float*)d_in[0];
    const float* context   = (const float*)d_in[1];
    const float* indicator = (const float*)d_in[2];
    const float* bbox      = (const float*)d_in[3];
    const float* ln_g      = (const float*)d_in[4];
    const float* ln_b      = (const float*)d_in[5];
    const float* cn_g      = (const float*)d_in[6];
    const float* cn_b      = (const float*)d_in[7];
    const float* w_in      = (const float*)d_in[8];
    const float* b_in      = (const float*)d_in[9];
    const float* w_ctx     = (const float*)d_in[10];
    const float* b_ctx     = (const float*)d_in[11];
    const float* w_out     = (const float*)d_in[12];
    const float* b_out     = (const float*)d_in[13];
    float* out  = (float*)d_out;
    float* attn = out + OUT_ATTN_OFF;

    static bool attr_done = false;
    if (!attr_done) {
        cudaFuncSetAttribute(k_conv, cudaFuncAttributeMaxDynamicSharedMemorySize,
                             CONV_SMEM);
        attr_done = true;
    }

    k_cvt_ctx<<<(NB * NP * CTX) / 256, 256>>>(context);
    k_cvt_w<<<(NC * KK) / 256, 256>>>(w_out);
    k_ctx<<<NB * 32, 256>>>(context, cn_g, cn_b);
    k_roi<<<(NB * XNC * NI + 255) / 256, 256>>>(global_x, bbox, indicator);
    k_gn_roi<<<NB * 32, 256>>>(ln_g, ln_b);
    k_gemm<0><<<dim3(32, 5), 256>>>(w_in, b_in);
    k_gemm<1><<<dim3(64, 5), 256>>>(w_ctx, b_ctx);
    k_conv<<<96, 512, CONV_SMEM>>>(b_out);
    k_sim<<<NB, 256>>>();
    k_softmax<<<NB * NI, 256>>>(attn);
    k_xo<<<dim3(NB, 5), 256>>>(attn);
    k_out<<<(NB * NC * HH * WW) / 256, 256>>>(global_x, bbox, out);
}

// round 6
// speedup vs baseline: 3.9022x; 1.6296x over previous
#include <cuda_runtime.h>
#include <cuda_bf16.h>
#include <math.h>
#include <stdint.h>

// ---------------- problem constants ----------------
#define NB   32
#define NC   320
#define HH   64
#define WW   64
#define CTX  1024
#define NP   256      // 16x16 ctx spatial
#define NI   81       // 9x9 roi points
#define XNC  322      // 320 + 2 indicator channels
#define KK   9216     // conv GEMM K = 1024*9
#define OUT_ATTN_OFF 41943040  // 32*320*64*64

// ---------------- device scratch (static, no allocation) ----------------
__device__ float g_xn   [NB * XNC * NI];    // roi features [b][c][i]
__device__ float g_q    [NB * NC * NI];
__device__ float g_k    [NB * NC * NP];
__device__ float g_v    [NB * NC * NP];
__device__ float g_sim  [NB * NI * NP];
__device__ float g_xo   [NB * NC * NI];
// bf16 hi/lo split operands for tensor-core GEMMs
__device__ __align__(16) __nv_bfloat16 g_cxh[NB * NP * CTX];  // raw context hi [b][p][c]
__device__ __align__(16) __nv_bfloat16 g_cxl[NB * NP * CTX];  // raw context lo
__device__ __align__(16) __nv_bfloat16 g_kmh[NB * NP * CTX];  // normed ctx hi [b][p][c]
__device__ __align__(16) __nv_bfloat16 g_kml[NB * NP * CTX];  // normed ctx lo
__device__ __align__(16) __nv_bfloat16 g_wh [NC * KK];        // w_out hi [o][tap*1024+c]
__device__ __align__(16) __nv_bfloat16 g_wl [NC * KK];        // w_out lo
__device__ __align__(16) __nv_bfloat16 g_wch[NC * CTX];       // w_ctx hi [o][c]
__device__ __align__(16) __nv_bfloat16 g_wcl[NC * CTX];       // w_ctx lo

// =================== helpers (baseline PTX only) ========================
__device__ __forceinline__ uint32_t smem_u32(const void* p) {
    uint32_t a;
    asm("{ .reg .u64 t; cvta.to.shared.u64 t, %1; cvt.u32.u64 %0, t; }" : "=r"(a) : "l"(p));
    return a;
}
#define CP16(dst, src, sz) \
    asm volatile("cp.async.ca.shared.global [%0], [%1], 16, %2;" \
                 :: "r"(dst), "l"(src), "r"(sz))
#define CP_COMMIT() asm volatile("cp.async.commit_group;" ::: "memory")
#define CP_WAIT(n)  asm volatile("cp.async.wait_group %0;" :: "n"(n) : "memory")

__device__ __forceinline__ void mma16816(float* c, const uint32_t* a, const uint32_t* b) {
    asm volatile("mma.sync.aligned.m16n8k16.row.col.f32.bf16.bf16.f32 "
        "{%0,%1,%2,%3}, {%4,%5,%6,%7}, {%8,%9}, {%0,%1,%2,%3};"
        : "+f"(c[0]), "+f"(c[1]), "+f"(c[2]), "+f"(c[3])
        : "r"(a[0]), "r"(a[1]), "r"(a[2]), "r"(a[3]), "r"(b[0]), "r"(b[1]));
}

// ================= prep: bf16 hi/lo weight splits ========================
__global__ __launch_bounds__(256) void k_cvt_w(const float* __restrict__ w_out) {
    int idx = blockIdx.x * 256 + threadIdx.x;   // NC*KK
    int o = idx / KK, r = idx - o * KK;
    int tap = r >> 10, c = r & 1023;
    float v = w_out[o * KK + c * 9 + tap];
    __nv_bfloat16 h = __float2bfloat16(v);
    g_wh[idx] = h;
    g_wl[idx] = __float2bfloat16(v - __bfloat162float(h));
}
__global__ __launch_bounds__(256) void k_cvt_wctx(const float* __restrict__ w_ctx) {
    int idx = blockIdx.x * 256 + threadIdx.x;   // NC*CTX, row-major identical layout
    float v = w_ctx[idx];
    __nv_bfloat16 h = __float2bfloat16(v);
    g_wch[idx] = h;
    g_wcl[idx] = __float2bfloat16(v - __bfloat162float(h));
}

// ===== unified mma.sync GEMM: MODE 0 conv (K=9216, im2col), MODE 1 kproj =
// grid 128 = 32 imgs x (2 M-tiles of 160) x (2 N-tiles of 128). 512 thr.
// 16 warps as 2(m) x 8(n); warp tile 80x16 (5 m-frags x 2 n-frags).
// 3xBF16 split: D += Ah*Bh + Ah*Bl + Al*Bh, fp32 reg accumulators.
// SMEM rows padded to 72 bf16 (144B / 36 u32): bank = (4*row + kb) % 32.
#define SA_LD 23040                 // hi->lo distance for A (160*144)
#define SB_LD 18432                 // hi->lo distance for B (128*144)
#define SB_OFF 46080
#define BUFSTRIDE 82944
#define MMA_SMEM (2 * BUFSTRIDE)

template <int MODE>
__global__ void __launch_bounds__(512, 1) k_mma(const float* __restrict__ bias) {
    constexpr int NCH = (MODE == 0) ? 144 : 16;
    extern __shared__ char smem[];
    uint32_t sb = smem_u32(smem);
    int tid = threadIdx.x;
    int bimg = blockIdx.x >> 2;
    int tt = blockIdx.x & 3;
    int mbase = (tt >> 1) * 160;
    int pbase = (tt & 1) * 128;

    const __nv_bfloat16* Ah = (MODE == 0) ? g_wh : g_wch;
    const __nv_bfloat16* Al = (MODE == 0) ? g_wl : g_wcl;
    const __nv_bfloat16* Bh = ((MODE == 0) ? g_cxh : g_kmh) + (size_t)bimg * (NP * CTX);
    const __nv_bfloat16* Bl = ((MODE == 0) ? g_cxl : g_kml) + (size_t)bimg * (NP * CTX);

    auto load_chunk = [&](int buf, int ch) {
        uint32_t base = sb + buf * BUFSTRIDE;
        if (MODE == 0) {
            int tap = ch >> 4, c0 = (ch & 15) << 6;
            for (int id = tid; id < 1280; id += 512) {
                int row = id >> 3, v = id & 7;
                size_t so = (size_t)(mbase + row) * KK + tap * 1024 + c0 + v * 8;
                uint32_t dst = base + (uint32_t)(row * 144 + v * 16);
                CP16(dst, Ah + so, 16);
                CP16(dst + SA_LD, Al + so, 16);
            }
            int t3 = tap / 3;
            int dy = t3 - 1, dx = tap - t3 * 3 - 1;
            for (int id = tid; id < 1024; id += 512) {
                int row = id >> 3, v = id & 7;
                int p = pbase + row;
                int yy = (p >> 4) + dy, xx = (p & 15) + dx;
                int ok = ((unsigned)yy < 16u && (unsigned)xx < 16u) ? 16 : 0;
                size_t so = ok ? ((size_t)(yy * 16 + xx) * CTX + c0 + v * 8) : 0;
                uint32_t dst = base + SB_OFF + (uint32_t)(row * 144 + v * 16);
                CP16(dst, Bh + so, ok);
                CP16(dst + SB_LD, Bl + so, ok);
            }
        } else {
            int c0 = ch << 6;
            for (int id = tid; id < 1280; id += 512) {
                int row = id >> 3, v = id & 7;
                size_t so = (size_t)(mbase + row) * CTX + c0 + v * 8;
                uint32_t dst = base + (uint32_t)(row * 144 + v * 16);
                CP16(dst, Ah + so, 16);
                CP16(dst + SA_LD, Al + so, 16);
            }
            for (int id = tid; id < 1024; id += 512) {
                int row = id >> 3, v = id & 7;
                size_t so = (size_t)(pbase + row) * CTX + c0 + v * 8;
                uint32_t dst = base + SB_OFF + (uint32_t)(row * 144 + v * 16);
                CP16(dst, Bh + so, 16);
                CP16(dst + SB_LD, Bl + so, 16);
            }
        }
    };

    int w = tid >> 5, l = tid & 31;
    int wm = w >> 3;        // 0..1: m offset 80 each
    int wn = w & 7;         // 0..7: n offset 16 each
    int g = l >> 2, tg = l & 3;

    float acc[5][2][4];
    #pragma unroll
    for (int f = 0; f < 5; f++)
        #pragma unroll
        for (int j = 0; j < 2; j++)
            #pragma unroll
            for (int q = 0; q < 4; q++) acc[f][j][q] = 0.f;

    auto compute = [&](int buf) {
        const uint32_t* pAh = (const uint32_t*)(smem + buf * BUFSTRIDE);
        const uint32_t* pAl = (const uint32_t*)(smem + buf * BUFSTRIDE + SA_LD);
        const uint32_t* pBh = (const uint32_t*)(smem + buf * BUFSTRIDE + SB_OFF);
        const uint32_t* pBl = (const uint32_t*)(smem + buf * BUFSTRIDE + SB_OFF + SB_LD);
        #pragma unroll
        for (int s = 0; s < 4; s++) {
            int kb = s * 8 + tg;
            uint32_t ah[5][4], al[5][4];
            #pragma unroll
            for (int f = 0; f < 5; f++) {
                int r0 = (wm * 80 + f * 16 + g) * 36;
                int r8 = r0 + 8 * 36;
                ah[f][0] = pAh[r0 + kb];     ah[f][1] = pAh[r8 + kb];
                ah[f][2] = pAh[r0 + kb + 4]; ah[f][3] = pAh[r8 + kb + 4];
                al[f][0] = pAl[r0 + kb];     al[f][1] = pAl[r8 + kb];
                al[f][2] = pAl[r0 + kb + 4]; al[f][3] = pAl[r8 + kb + 4];
            }
            #pragma unroll
            for (int j = 0; j < 2; j++) {
                int n = (wn * 16 + j * 8 + g) * 36;
                uint32_t bh[2] = { pBh[n + kb], pBh[n + kb + 4] };
                uint32_t bl[2] = { pBl[n + kb], pBl[n + kb + 4] };
                #pragma unroll
                for (int f = 0; f < 5; f++) {
                    mma16816(acc[f][j], ah[f], bh);
                    mma16816(acc[f][j], ah[f], bl);
                    mma16816(acc[f][j], al[f], bh);
                }
            }
        }
    };

    load_chunk(0, 0);
    CP_COMMIT();
    for (int ch = 0; ch < NCH; ch++) {
        if (ch + 1 < NCH) {
            load_chunk((ch + 1) & 1, ch + 1);
            CP_COMMIT();
            CP_WAIT(1);
        } else {
            CP_WAIT(0);
        }
        __syncthreads();
        compute(ch & 1);
        __syncthreads();
    }

    // ---- epilogue: acc + bias (M=320 exact, no guards) ----
    float* dst = ((MODE == 0) ? g_v : g_k) + (size_t)bimg * (NC * NP);
    #pragma unroll
    for (int f = 0; f < 5; f++) {
        int o0 = mbase + wm * 80 + f * 16 + g;
        int o1 = o0 + 8;
        float b0 = bias[o0], b1 = bias[o1];
        #pragma unroll
        for (int j = 0; j < 2; j++) {
            int p = pbase + wn * 16 + j * 8 + tg * 2;
            *(float2*)(dst + (size_t)o0 * NP + p)
                = make_float2(acc[f][j][0] + b0, acc[f][j][1] + b0);
            *(float2*)(dst + (size_t)o1 * NP + p)
                = make_float2(acc[f][j][2] + b1, acc[f][j][3] + b1);
        }
    }
}

// ====== kernel 1: ctx group norm + bf16 hi/lo splits (raw & normed) ======
// grid 32*32 (b,g), 256 threads. group = 32 channels x 256 p.
__global__ __launch_bounds__(256) void k_ctx(const float* __restrict__ context,
                                             const float* __restrict__ cn_g,
                                             const float* __restrict__ cn_b) {
    int b = blockIdx.x >> 5, g = blockIdx.x & 31;
    __shared__ float s[32 * 257];
    __shared__ float redA[8], redB[8];
    __shared__ float stats[2];
    const float* src = context + (size_t)b * (NP * CTX) + g * 32;
    float sum = 0.f, sq = 0.f;
    for (int i = threadIdx.x; i < 8192; i += 256) {
        int cl = i & 31, p = i >> 5;
        float v = src[(size_t)p * CTX + cl];
        s[cl * 257 + p] = v;
        sum += v; sq += v * v;
    }
    #pragma unroll
    for (int off = 16; off; off >>= 1) {
        sum += __shfl_down_sync(0xffffffffu, sum, off);
        sq  += __shfl_down_sync(0xffffffffu, sq,  off);
    }
    if ((threadIdx.x & 31) == 0) { redA[threadIdx.x >> 5] = sum; redB[threadIdx.x >> 5] = sq; }
    __syncthreads();
    if (threadIdx.x == 0) {
        float a = 0.f, b2 = 0.f;
        #pragma unroll
        for (int w = 0; w < 8; w++) { a += redA[w]; b2 += redB[w]; }
        float mean = a * (1.f / 8192.f);
        float var  = b2 * (1.f / 8192.f) - mean * mean;
        stats[0] = mean; stats[1] = rsqrtf(var + 1e-6f);
    }
    __syncthreads();
    float mean = stats[0], rstd = stats[1];
    int cl = threadIdx.x & 31;
    int c = g * 32 + cl;
    float gam = cn_g[c] * rstd, bet = cn_b[c];
    for (int i = threadIdx.x; i < 8192; i += 256) {
        int p = i >> 5;
        float v = s[cl * 257 + p];
        size_t o = ((size_t)b * NP + p) * CTX + c;
        __nv_bfloat16 h = __float2bfloat16(v);
        g_cxh[o] = h;
        g_cxl[o] = __float2bfloat16(v - __bfloat162float(h));
        float nv = (v - mean) * gam + bet;
        __nv_bfloat16 nh = __float2bfloat16(nv);
        g_kmh[o] = nh;
        g_kml[o] = __float2bfloat16(nv - __bfloat162float(nh));
    }
}

// ================= kernel 2a: roi bilinear samples ======================
__global__ __launch_bounds__(256) void k_roi(const float* __restrict__ gx,
                                             const float* __restrict__ bbox,
                                             const float* __restrict__ indicator) {
    int idx = blockIdx.x * 256 + threadIdx.x;
    if (idx >= NB * XNC * NI) return;
    int b = idx / (XNC * NI);
    int r = idx - b * (XNC * NI);
    int c = r / NI;
    int i = r - c * NI;
    float out;
    if (c >= NC) {
        out = indicator[b * 2 + (c - NC)];
    } else {
        float x1 = bbox[b * 4 + 0], y1 = bbox[b * 4 + 1];
        float x2 = bbox[b * 4 + 2], y2 = bbox[b * 4 + 3];
        float rw = fmaxf(x2 - x1, 1.0f), rh = fmaxf(y2 - y1, 1.0f);
        int iy = i / 9, ix = i - iy * 9;
        float xs = x1 + ((float)ix + 0.5f) * (rw * (1.f / 9.f));
        float ys = y1 + ((float)iy + 0.5f) * (rh * (1.f / 9.f));
        float yv = fminf(fmaxf(ys, 0.f), 63.f);
        float xv = fminf(fmaxf(xs, 0.f), 63.f);
        int y0 = (int)floorf(yv), x0 = (int)floorf(xv);
        int y1i = min(y0 + 1, 63), x1i = min(x0 + 1, 63);
        float ly = yv - (float)y0, lx = xv - (float)x0;
        const float* im = gx + (size_t)b * (NC * HH * WW) + (size_t)c * (HH * WW);
        float g00 = im[y0 * WW + x0],  g01 = im[y0 * WW + x1i];
        float g10 = im[y1i * WW + x0], g11 = im[y1i * WW + x1i];
        out = g00 * (1.f - ly) * (1.f - lx) + g01 * (1.f - ly) * lx
            + g10 * ly * (1.f - lx)        + g11 * ly * lx;
    }
    g_xn[idx] = out;
}

// ============ kernel 2b: group norm over roi features ====================
__global__ __launch_bounds__(256) void k_gn_roi(const float* __restrict__ ln_g,
                                                const float* __restrict__ ln_b) {
    int b = blockIdx.x >> 5, g = blockIdx.x & 31;
    float* base = g_xn + (size_t)b * (XNC * NI) + g * 810;
    __shared__ float s[810];
    __shared__ float redA[8], redB[8];
    __shared__ float stats[2];
    float sum = 0.f, sq = 0.f;
    for (int i = threadIdx.x; i < 810; i += 256) {
        float v = base[i];
        s[i] = v; sum += v; sq += v * v;
    }
    #pragma unroll
    for (int off = 16; off; off >>= 1) {
        sum += __shfl_down_sync(0xffffffffu, sum, off);
        sq  += __shfl_down_sync(0xffffffffu, sq,  off);
    }
    if ((threadIdx.x & 31) == 0) { redA[threadIdx.x >> 5] = sum; redB[threadIdx.x >> 5] = sq; }
    __syncthreads();
    if (threadIdx.x == 0) {
        float a = 0.f, b2 = 0.f;
        #pragma unroll
        for (int w = 0; w < 8; w++) { a += redA[w]; b2 += redB[w]; }
        float mean = a * (1.f / 810.f);
        float var  = b2 * (1.f / 810.f) - mean * mean;
        stats[0] = mean; stats[1] = rsqrtf(var + 1e-6f);
    }
    __syncthreads();
    float mean = stats[0], rstd = stats[1];
    for (int i = threadIdx.x; i < 810; i += 256) {
        int c = g * 10 + i / 81;
        base[i] = (s[i] - mean) * rstd * ln_g[c] + ln_b[c];
    }
}

// ================= q projection SGEMM (FFMA, small) ======================
// q = w_in @ xn    K=322, N=81 per image, grid (32, 5)
__global__ __launch_bounds__(256) void k_gemm_q(const float* __restrict__ A,
                                                const float* __restrict__ bias) {
    const int K = 322;
    __shared__ float sA[16][68];
    __shared__ float sB[16][128];
    int tid = threadIdx.x;
    int b = blockIdx.x;
    int mbase = blockIdx.y * 64;

    float acc[4][8];
    #pragma unroll
    for (int x = 0; x < 4; x++)
        #pragma unroll
        for (int y = 0; y < 8; y++) acc[x][y] = 0.f;

    int am = tid >> 2;
    int ak = (tid & 3) * 4;
    int bk = tid >> 4;
    int bn = (tid & 15) * 8;
    int tm = tid >> 4, tn = tid & 15;

    const float* abase = A + (size_t)(mbase + am) * K + ak;

    for (int k0 = 0; k0 < K; k0 += 16) {
        #pragma unroll
        for (int j = 0; j < 4; j++) {
            float v = 0.f;
            if (k0 + ak + j < 322) v = abase[k0 + j];
            sA[ak + j][am] = v;
        }
        int kk = k0 + bk;
        const float* bp = g_xn + (size_t)b * (XNC * NI) + (size_t)kk * NI;
        bool kok = kk < 322;
        #pragma unroll
        for (int j = 0; j < 8; j++) {
            int n = bn + j;
            sB[bk][bn + j] = (kok && n < NI) ? bp[n] : 0.f;
        }
        __syncthreads();
        #pragma unroll
        for (int k = 0; k < 16; k++) {
            float4 a4 = *(const float4*)&sA[k][tm * 4];
            float4 b0 = *(const float4*)&sB[k][tn * 8];
            float4 b1 = *(const float4*)&sB[k][tn * 8 + 4];
            float a[4]  = {a4.x, a4.y, a4.z, a4.w};
            float bb[8] = {b0.x, b0.y, b0.z, b0.w, b1.x, b1.y, b1.z, b1.w};
            #pragma unroll
            for (int x = 0; x < 4; x++)
                #pragma unroll
                for (int y = 0; y < 8; y++)
                    acc[x][y] = fmaf(a[x], bb[y], acc[x][y]);
        }
        __syncthreads();
    }
    #pragma unroll
    for (int x = 0; x < 4; x++) {
        int o = mbase + tm * 4 + x;
        float bs = bias[o];
        #pragma unroll
        for (int y = 0; y < 8; y++) {
            int n = tn * 8 + y;
            if (n < NI) g_q[(size_t)b * (NC * NI) + (size_t)o * NI + n] = acc[x][y] + bs;
        }
    }
}

// ======== kernel: sim = q^T k (81x128 per block, K=320), grid (32,2) =====
__global__ __launch_bounds__(256) void k_sim() {
    int b = blockIdx.x;
    int pb = blockIdx.y * 128;
    __shared__ float sq[8][96];
    __shared__ float sk[8][128];
    int tid = threadIdx.x;
    int ti = tid >> 4;
    int tp = tid & 15;
    float acc[6][8];
    #pragma unroll
    for (int x = 0; x < 6; x++)
        #pragma unroll
        for (int y = 0; y < 8; y++) acc[x][y] = 0.f;

    for (int o0 = 0; o0 < NC; o0 += 8) {
        for (int idx = tid; idx < 8 * NI; idx += 256) {
            int ko = idx / NI, i = idx - ko * NI;
            sq[ko][i] = g_q[(size_t)b * (NC * NI) + (size_t)(o0 + ko) * NI + i];
        }
        {
            int ko = tid >> 5;
            int pp = (tid & 31) * 4;
            *(float4*)&sk[ko][pp] = *(const float4*)(g_k + (size_t)b * (NC * NP)
                                       + (size_t)(o0 + ko) * NP + pb + pp);
        }
        __syncthreads();
        #pragma unroll
        for (int ko = 0; ko < 8; ko++) {
            float a[6];
            #pragma unroll
            for (int x = 0; x < 6; x++) a[x] = sq[ko][ti * 6 + x];
            float4 b0 = *(const float4*)&sk[ko][tp * 8];
            float4 b1 = *(const float4*)&sk[ko][tp * 8 + 4];
            float bb[8] = {b0.x, b0.y, b0.z, b0.w, b1.x, b1.y, b1.z, b1.w};
            #pragma unroll
            for (int x = 0; x < 6; x++)
                #pragma unroll
                for (int y = 0; y < 8; y++)
                    acc[x][y] = fmaf(a[x], bb[y], acc[x][y]);
        }
        __syncthreads();
    }
    #pragma unroll
    for (int x = 0; x < 6; x++) {
        int i = ti * 6 + x;
        if (i < NI) {
            #pragma unroll
            for (int y = 0; y < 8; y++)
                g_sim[(size_t)b * (NI * NP) + (size_t)i * NP + pb + tp * 8 + y] = acc[x][y];
        }
    }
}

// ================= kernel: softmax rows -> attn ==========================
__global__ __launch_bounds__(256) void k_softmax(float* __restrict__ attn_out) {
    int b = blockIdx.x / NI, i = blockIdx.x - b * NI;
    int t = threadIdx.x;
    __shared__ float red[8];
    __shared__ float bc[1];
    float v = g_sim[(size_t)b * (NI * NP) + (size_t)i * NP + t];
    float m = v;
    #pragma unroll
    for (int off = 16; off; off >>= 1) m = fmaxf(m, __shfl_xor_sync(0xffffffffu, m, off));
    if ((t & 31) == 0) red[t >> 5] = m;
    __syncthreads();
    if (t == 0) {
        float mm = red[0];
        #pragma unroll
        for (int w = 1; w < 8; w++) mm = fmaxf(mm, red[w]);
        bc[0] = mm;
    }
    __syncthreads();
    float e = expf(v - bc[0]);
    float s = e;
    #pragma unroll
    for (int off = 16; off; off >>= 1) s += __shfl_xor_sync(0xffffffffu, s, off);
    if ((t & 31) == 0) red[t >> 5] = s;
    __syncthreads();
    if (t == 0) {
        float ss = 0.f;
        #pragma unroll
        for (int w = 0; w < 8; w++) ss += red[w];
        bc[0] = 1.f / ss;
    }
    __syncthreads();
    attn_out[(size_t)b * (NI * NP) + (size_t)i * NP + t] = e * bc[0];
}

// ================= kernel: xo = v_t @ attn^T (320x81, K=256) =============
__global__ __launch_bounds__(256) void k_xo(const float* __restrict__ attn) {
    int b = blockIdx.x;
    int mbase = blockIdx.y * 64;
    __shared__ float sv[16][68];
    __shared__ float sa[16][96];
    int tid = threadIdx.x;
    int am = tid >> 2, ak = (tid & 3) * 4;
    int tm = tid >> 4, tn = tid & 15;
    float acc[4][6];
    #pragma unroll
    for (int x = 0; x < 4; x++)
        #pragma unroll
        for (int y = 0; y < 6; y++) acc[x][y] = 0.f;

    for (int p0 = 0; p0 < NP; p0 += 16) {
        float4 v4 = *(const float4*)(g_v + (size_t)b * (NC * NP)
                                     + (size_t)(mbase + am) * NP + p0 + ak);
        sv[ak + 0][am] = v4.x; sv[ak + 1][am] = v4.y;
        sv[ak + 2][am] = v4.z; sv[ak + 3][am] = v4.w;
        for (int idx = tid; idx < 16 * NI; idx += 256) {
            int ii = idx >> 4, pp = idx & 15;
            sa[pp][ii] = attn[(size_t)b * (NI * NP) + (size_t)ii * NP + p0 + pp];
        }
        __syncthreads();
        #pragma unroll
        for (int p = 0; p < 16; p++) {
            float4 a4 = *(const float4*)&sv[p][tm * 4];
            float a[4] = {a4.x, a4.y, a4.z, a4.w};
            float bb[6];
            #pragma unroll
            for (int y = 0; y < 6; y++) bb[y] = sa[p][tn * 6 + y];
            #pragma unroll
            for (int x = 0; x < 4; x++)
                #pragma unroll
                for (int y = 0; y < 6; y++)
                    acc[x][y] = fmaf(a[x], bb[y], acc[x][y]);
        }
        __syncthreads();
    }
    #pragma unroll
    for (int x = 0; x < 4; x++) {
        int o = mbase + tm * 4 + x;
        #pragma unroll
        for (int y = 0; y < 6; y++) {
            int i = tn * 6 + y;
            if (i < NI) g_xo[(size_t)b * (NC * NI) + (size_t)o * NI + i] = acc[x][y];
        }
    }
}

// ========== kernel: residual + masked scatter ============================
__global__ __launch_bounds__(256) void k_out(const float* __restrict__ gx,
                                             const float* __restrict__ bbox,
                                             float* __restrict__ out) {
    int idx = blockIdx.x * 256 + threadIdx.x;
    int x = idx & 63;
    int y = (idx >> 6) & 63;
    int bc = idx >> 12;
    int b = bc / NC;
    int c = bc - b * NC;
    float val = gx[idx];
    int bx1 = (int)(bbox[b * 4 + 0] * 64.f);
    int by1 = (int)(bbox[b * 4 + 1] * 64.f);
    int bx2 = max((int)(bbox[b * 4 + 2] * 64.f), bx1 + 1);
    int by2 = max((int)(bbox[b * 4 + 3] * 64.f), by1 + 1);
    if (y >= by1 && y < by2 && x >= bx1 && x < bx2) {
        int sy = min(max((y - by1) * 9 / (by2 - by1), 0), 8);
        int sx = min(max((x - bx1) * 9 / (bx2 - bx1), 0), 8);
        val += g_xo[(size_t)b * (NC * NI) + (size_t)c * NI + sy * 9 + sx];
    }
    out[idx] = val;
}

// ============================ launch ======================================
extern "C" void kernel_launch(void* const* d_in, const int* in_sizes, int n_in,
                              void* d_out, int out_size) {
    const float* global_x  = (const float*)d_in[0];
    const float* context   = (const float*)d_in[1];
    const float* indicator = (const float*)d_in[2];
    const float* bbox      = (const float*)d_in[3];
    const float* ln_g      = (const float*)d_in[4];
    const float* ln_b      = (const float*)d_in[5];
    const float* cn_g      = (const float*)d_in[6];
    const float* cn_b      = (const float*)d_in[7];
    const float* w_in      = (const float*)d_in[8];
    const float* b_in      = (const float*)d_in[9];
    const float* w_ctx     = (const float*)d_in[10];
    const float* b_ctx     = (const float*)d_in[11];
    const float* w_out     = (const float*)d_in[12];
    const float* b_out     = (const float*)d_in[13];
    float* out  = (float*)d_out;
    float* attn = out + OUT_ATTN_OFF;

    static bool attr_done = false;
    if (!attr_done) {
        cudaFuncSetAttribute(k_mma<0>, cudaFuncAttributeMaxDynamicSharedMemorySize,
                             MMA_SMEM);
        cudaFuncSetAttribute(k_mma<1>, cudaFuncAttributeMaxDynamicSharedMemorySize,
                             MMA_SMEM);
        attr_done = true;
    }

    k_ctx<<<NB * 32, 256>>>(context, cn_g, cn_b);
    k_cvt_w<<<(NC * KK) / 256, 256>>>(w_out);
    k_cvt_wctx<<<(NC * CTX) / 256, 256>>>(w_ctx);
    k_roi<<<(NB * XNC * NI + 255) / 256, 256>>>(global_x, bbox, indicator);
    k_gn_roi<<<NB * 32, 256>>>(ln_g, ln_b);
    k_gemm_q<<<dim3(32, 5), 256>>>(w_in, b_in);
    k_mma<1><<<128, 512, MMA_SMEM>>>(b_ctx);
    k_mma<0><<<128, 512, MMA_SMEM>>>(b_out);
    k_sim<<<dim3(NB, 2), 256>>>();
    k_softmax<<<NB * NI, 256>>>(attn);
    k_xo<<<dim3(NB, 5), 256>>>(attn);
    k_out<<<(NB * NC * HH * WW) / 256, 256>>>(global_x, bbox, out);
}

// round 7
// speedup vs baseline: 5.9402x; 1.5223x over previous
#include <cuda_runtime.h>
#include <cuda_bf16.h>
#include <cuda_fp16.h>
#include <math.h>
#include <stdint.h>

// ---------------- problem constants ----------------
#define NB   32
#define NC   320
#define HH   64
#define WW   64
#define CTX  1024
#define NP   256      // 16x16 ctx spatial
#define NI   81       // 9x9 roi points
#define XNC  322      // 320 + 2 indicator channels
#define KK   9216     // conv GEMM K = 1024*9
#define OUT_ATTN_OFF 41943040  // 32*320*64*64

// ---------------- device scratch (static, no allocation) ----------------
__device__ float g_xn   [NB * XNC * NI];    // roi features [b][c][i]
__device__ float g_q    [NB * NC * NI];
__device__ float g_k    [NB * NC * NP];
__device__ float g_v    [NB * NC * NP];
__device__ float g_sim  [NB * NI * NP];
__device__ float g_xo   [NB * NC * NI];
// fp16 operands for conv (single MMA, fp32 accumulate)
__device__ __align__(16) __half g_cxf[NB * NP * CTX];         // raw context fp16 [b][p][c]
__device__ __align__(16) __half g_wf [NC * KK];               // w_out fp16 [o][tap*1024+c]
// bf16 hi/lo split operands for k projection (3x split, high accuracy)
__device__ __align__(16) __nv_bfloat16 g_kmh[NB * NP * CTX];  // normed ctx hi [b][p][c]
__device__ __align__(16) __nv_bfloat16 g_kml[NB * NP * CTX];  // normed ctx lo
__device__ __align__(16) __nv_bfloat16 g_wch[NC * CTX];       // w_ctx hi [o][c]
__device__ __align__(16) __nv_bfloat16 g_wcl[NC * CTX];       // w_ctx lo

// =================== helpers (baseline PTX only) ========================
__device__ __forceinline__ uint32_t smem_u32(const void* p) {
    uint32_t a;
    asm("{ .reg .u64 t; cvta.to.shared.u64 t, %1; cvt.u32.u64 %0, t; }" : "=r"(a) : "l"(p));
    return a;
}
#define CP16(dst, src, sz) \
    asm volatile("cp.async.ca.shared.global [%0], [%1], 16, %2;" \
                 :: "r"(dst), "l"(src), "r"(sz))
#define CP_COMMIT() asm volatile("cp.async.commit_group;" ::: "memory")
#define CP_WAIT(n)  asm volatile("cp.async.wait_group %0;" :: "n"(n) : "memory")

__device__ __forceinline__ void mma_bf16(float* c, const uint32_t* a, const uint32_t* b) {
    asm volatile("mma.sync.aligned.m16n8k16.row.col.f32.bf16.bf16.f32 "
        "{%0,%1,%2,%3}, {%4,%5,%6,%7}, {%8,%9}, {%0,%1,%2,%3};"
        : "+f"(c[0]), "+f"(c[1]), "+f"(c[2]), "+f"(c[3])
        : "r"(a[0]), "r"(a[1]), "r"(a[2]), "r"(a[3]), "r"(b[0]), "r"(b[1]));
}
__device__ __forceinline__ void mma_f16(float* c, const uint32_t* a, const uint32_t* b) {
    asm volatile("mma.sync.aligned.m16n8k16.row.col.f32.f16.f16.f32 "
        "{%0,%1,%2,%3}, {%4,%5,%6,%7}, {%8,%9}, {%0,%1,%2,%3};"
        : "+f"(c[0]), "+f"(c[1]), "+f"(c[2]), "+f"(c[3])
        : "r"(a[0]), "r"(a[1]), "r"(a[2]), "r"(a[3]), "r"(b[0]), "r"(b[1]));
}

// ================= prep: weight conversions ==============================
__global__ __launch_bounds__(256) void k_cvt_w(const float* __restrict__ w_out) {
    int idx = blockIdx.x * 256 + threadIdx.x;   // NC*KK
    int o = idx / KK, r = idx - o * KK;
    int tap = r >> 10, c = r & 1023;
    g_wf[idx] = __float2half(w_out[o * KK + c * 9 + tap]);
}
__global__ __launch_bounds__(256) void k_cvt_wctx(const float* __restrict__ w_ctx) {
    int idx = blockIdx.x * 256 + threadIdx.x;   // NC*CTX
    float v = w_ctx[idx];
    __nv_bfloat16 h = __float2bfloat16(v);
    g_wch[idx] = h;
    g_wcl[idx] = __float2bfloat16(v - __bfloat162float(h));
}

// ============ fp16 conv: v = w_out (*) ctx + b_out =======================
// grid 128 = 32 imgs x (2 M-tiles of 160) x (2 N-tiles of 128). 512 thr.
// 16 warps as 2(m) x 8(n); warp tile 80x16 (5 m-frags x 2 n-frags).
// fp16 operands, fp32 accum. K-chunks of 128 (72 chunks), double buffer.
// Rows padded to 136 fp16 = 272B = 68 u32: bank = (4*row + kb) % 32.
#define CV_B_OFF 43520               // A = 160*272
#define CV_BUF   78336               // + B = 128*272
#define CV_SMEM  (2 * CV_BUF)
#define CV_NCH   72

__global__ void __launch_bounds__(512, 1) k_conv(const float* __restrict__ bias) {
    extern __shared__ char smem[];
    uint32_t sb = smem_u32(smem);
    int tid = threadIdx.x;
    int bimg = blockIdx.x >> 2;
    int tt = blockIdx.x & 3;
    int mbase = (tt >> 1) * 160;
    int pbase = (tt & 1) * 128;
    const __half* Bsrc = g_cxf + (size_t)bimg * (NP * CTX);

    auto load_chunk = [&](int buf, int ch) {
        uint32_t base = sb + buf * CV_BUF;
        int tap = ch >> 3, c0 = (ch & 7) << 7;
        int t3 = tap / 3;
        int dy = t3 - 1, dx = tap - t3 * 3 - 1;
        // A: 160 rows x 128 fp16 = 2560 x 16B
        #pragma unroll
        for (int r = 0; r < 5; r++) {
            int id = r * 512 + tid;
            int row = id >> 4, v = id & 15;
            size_t so = (size_t)(mbase + row) * KK + tap * 1024 + c0 + v * 8;
            CP16(base + (uint32_t)(row * 272 + v * 16), g_wf + so, 16);
        }
        // B: 128 rows x 128 fp16 = 2048 x 16B (im2col halo zero-fill)
        #pragma unroll
        for (int r = 0; r < 4; r++) {
            int id = r * 512 + tid;
            int row = id >> 4, v = id & 15;
            int p = pbase + row;
            int yy = (p >> 4) + dy, xx = (p & 15) + dx;
            int ok = ((unsigned)yy < 16u && (unsigned)xx < 16u) ? 16 : 0;
            size_t so = ok ? ((size_t)(yy * 16 + xx) * CTX + c0 + v * 8) : 0;
            CP16(base + CV_B_OFF + (uint32_t)(row * 272 + v * 16), Bsrc + so, ok);
        }
    };

    int w = tid >> 5, l = tid & 31;
    int wm = w >> 3;        // 0..1: m offset 80
    int wn = w & 7;         // 0..7: n offset 16
    int g = l >> 2, tg = l & 3;

    float acc[5][2][4];
    #pragma unroll
    for (int f = 0; f < 5; f++)
        #pragma unroll
        for (int j = 0; j < 2; j++)
            #pragma unroll
            for (int q = 0; q < 4; q++) acc[f][j][q] = 0.f;

    auto compute = [&](int buf) {
        const uint32_t* pA = (const uint32_t*)(smem + buf * CV_BUF);
        const uint32_t* pB = (const uint32_t*)(smem + buf * CV_BUF + CV_B_OFF);
        #pragma unroll
        for (int s = 0; s < 8; s++) {
            int kb = s * 8 + tg;
            uint32_t ah[5][4];
            #pragma unroll
            for (int f = 0; f < 5; f++) {
                int r0 = (wm * 80 + f * 16 + g) * 68;
                int r8 = r0 + 8 * 68;
                ah[f][0] = pA[r0 + kb];     ah[f][1] = pA[r8 + kb];
                ah[f][2] = pA[r0 + kb + 4]; ah[f][3] = pA[r8 + kb + 4];
            }
            #pragma unroll
            for (int j = 0; j < 2; j++) {
                int n = (wn * 16 + j * 8 + g) * 68;
                uint32_t bh[2] = { pB[n + kb], pB[n + kb + 4] };
                #pragma unroll
                for (int f = 0; f < 5; f++)
                    mma_f16(acc[f][j], ah[f], bh);
            }
        }
    };

    load_chunk(0, 0);
    CP_COMMIT();
    for (int ch = 0; ch < CV_NCH; ch++) {
        if (ch + 1 < CV_NCH) {
            load_chunk((ch + 1) & 1, ch + 1);
            CP_COMMIT();
            CP_WAIT(1);
        } else {
            CP_WAIT(0);
        }
        __syncthreads();
        compute(ch & 1);
        __syncthreads();
    }

    float* dst = g_v + (size_t)bimg * (NC * NP);
    #pragma unroll
    for (int f = 0; f < 5; f++) {
        int o0 = mbase + wm * 80 + f * 16 + g;
        int o1 = o0 + 8;
        float b0 = bias[o0], b1 = bias[o1];
        #pragma unroll
        for (int j = 0; j < 2; j++) {
            int p = pbase + wn * 16 + j * 8 + tg * 2;
            *(float2*)(dst + (size_t)o0 * NP + p)
                = make_float2(acc[f][j][0] + b0, acc[f][j][1] + b0);
            *(float2*)(dst + (size_t)o1 * NP + p)
                = make_float2(acc[f][j][2] + b1, acc[f][j][3] + b1);
        }
    }
}

// ===== k projection (3xBF16 split, high accuracy): k = w_ctx @ kmap ======
// grid 128 = 32 imgs x 2 M x 2 N. K=1024, 16 chunks of 64.
#define SA_LD 23040                 // hi->lo distance for A (160*144)
#define SB_LD 18432                 // hi->lo distance for B (128*144)
#define SB_OFF 46080
#define BUFSTRIDE 82944
#define KP_SMEM (2 * BUFSTRIDE)

__global__ void __launch_bounds__(512, 1) k_kproj(const float* __restrict__ bias) {
    const int NCH = 16;
    extern __shared__ char smem[];
    uint32_t sb = smem_u32(smem);
    int tid = threadIdx.x;
    int bimg = blockIdx.x >> 2;
    int tt = blockIdx.x & 3;
    int mbase = (tt >> 1) * 160;
    int pbase = (tt & 1) * 128;

    const __nv_bfloat16* Bh = g_kmh + (size_t)bimg * (NP * CTX);
    const __nv_bfloat16* Bl = g_kml + (size_t)bimg * (NP * CTX);

    auto load_chunk = [&](int buf, int ch) {
        uint32_t base = sb + buf * BUFSTRIDE;
        int c0 = ch << 6;
        for (int id = tid; id < 1280; id += 512) {
            int row = id >> 3, v = id & 7;
            size_t so = (size_t)(mbase + row) * CTX + c0 + v * 8;
            uint32_t dst = base + (uint32_t)(row * 144 + v * 16);
            CP16(dst, g_wch + so, 16);
            CP16(dst + SA_LD, g_wcl + so, 16);
        }
        for (int id = tid; id < 1024; id += 512) {
            int row = id >> 3, v = id & 7;
            size_t so = (size_t)(pbase + row) * CTX + c0 + v * 8;
            uint32_t dst = base + SB_OFF + (uint32_t)(row * 144 + v * 16);
            CP16(dst, Bh + so, 16);
            CP16(dst + SB_LD, Bl + so, 16);
        }
    };

    int w = tid >> 5, l = tid & 31;
    int wm = w >> 3;
    int wn = w & 7;
    int g = l >> 2, tg = l & 3;

    float acc[5][2][4];
    #pragma unroll
    for (int f = 0; f < 5; f++)
        #pragma unroll
        for (int j = 0; j < 2; j++)
            #pragma unroll
            for (int q = 0; q < 4; q++) acc[f][j][q] = 0.f;

    auto compute = [&](int buf) {
        const uint32_t* pAh = (const uint32_t*)(smem + buf * BUFSTRIDE);
        const uint32_t* pAl = (const uint32_t*)(smem + buf * BUFSTRIDE + SA_LD);
        const uint32_t* pBh = (const uint32_t*)(smem + buf * BUFSTRIDE + SB_OFF);
        const uint32_t* pBl = (const uint32_t*)(smem + buf * BUFSTRIDE + SB_OFF + SB_LD);
        #pragma unroll
        for (int s = 0; s < 4; s++) {
            int kb = s * 8 + tg;
            uint32_t ah[5][4], al[5][4];
            #pragma unroll
            for (int f = 0; f < 5; f++) {
                int r0 = (wm * 80 + f * 16 + g) * 36;
                int r8 = r0 + 8 * 36;
                ah[f][0] = pAh[r0 + kb];     ah[f][1] = pAh[r8 + kb];
                ah[f][2] = pAh[r0 + kb + 4]; ah[f][3] = pAh[r8 + kb + 4];
                al[f][0] = pAl[r0 + kb];     al[f][1] = pAl[r8 + kb];
                al[f][2] = pAl[r0 + kb + 4]; al[f][3] = pAl[r8 + kb + 4];
            }
            #pragma unroll
            for (int j = 0; j < 2; j++) {
                int n = (wn * 16 + j * 8 + g) * 36;
                uint32_t bh[2] = { pBh[n + kb], pBh[n + kb + 4] };
                uint32_t bl[2] = { pBl[n + kb], pBl[n + kb + 4] };
                #pragma unroll
                for (int f = 0; f < 5; f++) {
                    mma_bf16(acc[f][j], ah[f], bh);
                    mma_bf16(acc[f][j], ah[f], bl);
                    mma_bf16(acc[f][j], al[f], bh);
                }
            }
        }
    };

    load_chunk(0, 0);
    CP_COMMIT();
    for (int ch = 0; ch < NCH; ch++) {
        if (ch + 1 < NCH) {
            load_chunk((ch + 1) & 1, ch + 1);
            CP_COMMIT();
            CP_WAIT(1);
        } else {
            CP_WAIT(0);
        }
        __syncthreads();
        compute(ch & 1);
        __syncthreads();
    }

    float* dst = g_k + (size_t)bimg * (NC * NP);
    #pragma unroll
    for (int f = 0; f < 5; f++) {
        int o0 = mbase + wm * 80 + f * 16 + g;
        int o1 = o0 + 8;
        float b0 = bias[o0], b1 = bias[o1];
        #pragma unroll
        for (int j = 0; j < 2; j++) {
            int p = pbase + wn * 16 + j * 8 + tg * 2;
            *(float2*)(dst + (size_t)o0 * NP + p)
                = make_float2(acc[f][j][0] + b0, acc[f][j][1] + b0);
            *(float2*)(dst + (size_t)o1 * NP + p)
                = make_float2(acc[f][j][2] + b1, acc[f][j][3] + b1);
        }
    }
}

// ====== kernel 1: ctx group norm + fp16 raw + bf16 hi/lo normed =========
__global__ __launch_bounds__(256) void k_ctx(const float* __restrict__ context,
                                             const float* __restrict__ cn_g,
                                             const float* __restrict__ cn_b) {
    int b = blockIdx.x >> 5, g = blockIdx.x & 31;
    __shared__ float s[32 * 257];
    __shared__ float redA[8], redB[8];
    __shared__ float stats[2];
    const float* src = context + (size_t)b * (NP * CTX) + g * 32;
    float sum = 0.f, sq = 0.f;
    for (int i = threadIdx.x; i < 8192; i += 256) {
        int cl = i & 31, p = i >> 5;
        float v = src[(size_t)p * CTX + cl];
        s[cl * 257 + p] = v;
        sum += v; sq += v * v;
    }
    #pragma unroll
    for (int off = 16; off; off >>= 1) {
        sum += __shfl_down_sync(0xffffffffu, sum, off);
        sq  += __shfl_down_sync(0xffffffffu, sq,  off);
    }
    if ((threadIdx.x & 31) == 0) { redA[threadIdx.x >> 5] = sum; redB[threadIdx.x >> 5] = sq; }
    __syncthreads();
    if (threadIdx.x == 0) {
        float a = 0.f, b2 = 0.f;
        #pragma unroll
        for (int w = 0; w < 8; w++) { a += redA[w]; b2 += redB[w]; }
        float mean = a * (1.f / 8192.f);
        float var  = b2 * (1.f / 8192.f) - mean * mean;
        stats[0] = mean; stats[1] = rsqrtf(var + 1e-6f);
    }
    __syncthreads();
    float mean = stats[0], rstd = stats[1];
    int cl = threadIdx.x & 31;
    int c = g * 32 + cl;
    float gam = cn_g[c] * rstd, bet = cn_b[c];
    for (int i = threadIdx.x; i < 8192; i += 256) {
        int p = i >> 5;
        float v = s[cl * 257 + p];
        size_t o = ((size_t)b * NP + p) * CTX + c;
        g_cxf[o] = __float2half(v);
        float nv = (v - mean) * gam + bet;
        __nv_bfloat16 nh = __float2bfloat16(nv);
        g_kmh[o] = nh;
        g_kml[o] = __float2bfloat16(nv - __bfloat162float(nh));
    }
}

// ================= kernel 2a: roi bilinear samples ======================
__global__ __launch_bounds__(256) void k_roi(const float* __restrict__ gx,
                                             const float* __restrict__ bbox,
                                             const float* __restrict__ indicator) {
    int idx = blockIdx.x * 256 + threadIdx.x;
    if (idx >= NB * XNC * NI) return;
    int b = idx / (XNC * NI);
    int r = idx - b * (XNC * NI);
    int c = r / NI;
    int i = r - c * NI;
    float out;
    if (c >= NC) {
        out = indicator[b * 2 + (c - NC)];
    } else {
        float x1 = bbox[b * 4 + 0], y1 = bbox[b * 4 + 1];
        float x2 = bbox[b * 4 + 2], y2 = bbox[b * 4 + 3];
        float rw = fmaxf(x2 - x1, 1.0f), rh = fmaxf(y2 - y1, 1.0f);
        int iy = i / 9, ix = i - iy * 9;
        float xs = x1 + ((float)ix + 0.5f) * (rw * (1.f / 9.f));
        float ys = y1 + ((float)iy + 0.5f) * (rh * (1.f / 9.f));
        float yv = fminf(fmaxf(ys, 0.f), 63.f);
        float xv = fminf(fmaxf(xs, 0.f), 63.f);
        int y0 = (int)floorf(yv), x0 = (int)floorf(xv);
        int y1i = min(y0 + 1, 63), x1i = min(x0 + 1, 63);
        float ly = yv - (float)y0, lx = xv - (float)x0;
        const float* im = gx + (size_t)b * (NC * HH * WW) + (size_t)c * (HH * WW);
        float g00 = im[y0 * WW + x0],  g01 = im[y0 * WW + x1i];
        float g10 = im[y1i * WW + x0], g11 = im[y1i * WW + x1i];
        out = g00 * (1.f - ly) * (1.f - lx) + g01 * (1.f - ly) * lx
            + g10 * ly * (1.f - lx)        + g11 * ly * lx;
    }
    g_xn[idx] = out;
}

// ============ kernel 2b: group norm over roi features ====================
__global__ __launch_bounds__(256) void k_gn_roi(const float* __restrict__ ln_g,
                                                const float* __restrict__ ln_b) {
    int b = blockIdx.x >> 5, g = blockIdx.x & 31;
    float* base = g_xn + (size_t)b * (XNC * NI) + g * 810;
    __shared__ float s[810];
    __shared__ float redA[8], redB[8];
    __shared__ float stats[2];
    float sum = 0.f, sq = 0.f;
    for (int i = threadIdx.x; i < 810; i += 256) {
        float v = base[i];
        s[i] = v; sum += v; sq += v * v;
    }
    #pragma unroll
    for (int off = 16; off; off >>= 1) {
        sum += __shfl_down_sync(0xffffffffu, sum, off);
        sq  += __shfl_down_sync(0xffffffffu, sq,  off);
    }
    if ((threadIdx.x & 31) == 0) { redA[threadIdx.x >> 5] = sum; redB[threadIdx.x >> 5] = sq; }
    __syncthreads();
    if (threadIdx.x == 0) {
        float a = 0.f, b2 = 0.f;
        #pragma unroll
        for (int w = 0; w < 8; w++) { a += redA[w]; b2 += redB[w]; }
        float mean = a * (1.f / 810.f);
        float var  = b2 * (1.f / 810.f) - mean * mean;
        stats[0] = mean; stats[1] = rsqrtf(var + 1e-6f);
    }
    __syncthreads();
    float mean = stats[0], rstd = stats[1];
    for (int i = threadIdx.x; i < 810; i += 256) {
        int c = g * 10 + i / 81;
        base[i] = (s[i] - mean) * rstd * ln_g[c] + ln_b[c];
    }
}

// ================= q projection SGEMM (FFMA, fp32-exact path) ===========
__global__ __launch_bounds__(256) void k_gemm_q(const float* __restrict__ A,
                                                const float* __restrict__ bias) {
    const int K = 322;
    __shared__ float sA[16][68];
    __shared__ float sB[16][128];
    int tid = threadIdx.x;
    int b = blockIdx.x;
    int mbase = blockIdx.y * 64;

    float acc[4][8];
    #pragma unroll
    for (int x = 0; x < 4; x++)
        #pragma unroll
        for (int y = 0; y < 8; y++) acc[x][y] = 0.f;

    int am = tid >> 2;
    int ak = (tid & 3) * 4;
    int bk = tid >> 4;
    int bn = (tid & 15) * 8;
    int tm = tid >> 4, tn = tid & 15;

    const float* abase = A + (size_t)(mbase + am) * K + ak;

    for (int k0 = 0; k0 < K; k0 += 16) {
        #pragma unroll
        for (int j = 0; j < 4; j++) {
            float v = 0.f;
            if (k0 + ak + j < 322) v = abase[k0 + j];
            sA[ak + j][am] = v;
        }
        int kk = k0 + bk;
        const float* bp = g_xn + (size_t)b * (XNC * NI) + (size_t)kk * NI;
        bool kok = kk < 322;
        #pragma unroll
        for (int j = 0; j < 8; j++) {
            int n = bn + j;
            sB[bk][bn + j] = (kok && n < NI) ? bp[n] : 0.f;
        }
        __syncthreads();
        #pragma unroll
        for (int k = 0; k < 16; k++) {
            float4 a4 = *(const float4*)&sA[k][tm * 4];
            float4 b0 = *(const float4*)&sB[k][tn * 8];
            float4 b1 = *(const float4*)&sB[k][tn * 8 + 4];
            float a[4]  = {a4.x, a4.y, a4.z, a4.w};
            float bb[8] = {b0.x, b0.y, b0.z, b0.w, b1.x, b1.y, b1.z, b1.w};
            #pragma unroll
            for (int x = 0; x < 4; x++)
                #pragma unroll
                for (int y = 0; y < 8; y++)
                    acc[x][y] = fmaf(a[x], bb[y], acc[x][y]);
        }
        __syncthreads();
    }
    #pragma unroll
    for (int x = 0; x < 4; x++) {
        int o = mbase + tm * 4 + x;
        float bs = bias[o];
        #pragma unroll
        for (int y = 0; y < 8; y++) {
            int n = tn * 8 + y;
            if (n < NI) g_q[(size_t)b * (NC * NI) + (size_t)o * NI + n] = acc[x][y] + bs;
        }
    }
}

// ======== kernel: sim = q^T k (81x128 per block, K=320), grid (32,2) =====
__global__ __launch_bounds__(256) void k_sim() {
    int b = blockIdx.x;
    int pb = blockIdx.y * 128;
    __shared__ float sq[8][96];
    __shared__ float sk[8][128];
    int tid = threadIdx.x;
    int ti = tid >> 4;
    int tp = tid & 15;
    float acc[6][8];
    #pragma unroll
    for (int x = 0; x < 6; x++)
        #pragma unroll
        for (int y = 0; y < 8; y++) acc[x][y] = 0.f;

    for (int o0 = 0; o0 < NC; o0 += 8) {
        for (int idx = tid; idx < 8 * NI; idx += 256) {
            int ko = idx / NI, i = idx - ko * NI;
            sq[ko][i] = g_q[(size_t)b * (NC * NI) + (size_t)(o0 + ko) * NI + i];
        }
        {
            int ko = tid >> 5;
            int pp = (tid & 31) * 4;
            *(float4*)&sk[ko][pp] = *(const float4*)(g_k + (size_t)b * (NC * NP)
                                       + (size_t)(o0 + ko) * NP + pb + pp);
        }
        __syncthreads();
        #pragma unroll
        for (int ko = 0; ko < 8; ko++) {
            float a[6];
            #pragma unroll
            for (int x = 0; x < 6; x++) a[x] = sq[ko][ti * 6 + x];
            float4 b0 = *(const float4*)&sk[ko][tp * 8];
            float4 b1 = *(const float4*)&sk[ko][tp * 8 + 4];
            float bb[8] = {b0.x, b0.y, b0.z, b0.w, b1.x, b1.y, b1.z, b1.w};
            #pragma unroll
            for (int x = 0; x < 6; x++)
                #pragma unroll
                for (int y = 0; y < 8; y++)
                    acc[x][y] = fmaf(a[x], bb[y], acc[x][y]);
        }
        __syncthreads();
    }
    #pragma unroll
    for (int x = 0; x < 6; x++) {
        int i = ti * 6 + x;
        if (i < NI) {
            #pragma unroll
            for (int y = 0; y < 8; y++)
                g_sim[(size_t)b * (NI * NP) + (size_t)i * NP + pb + tp * 8 + y] = acc[x][y];
        }
    }
}

// ================= kernel: softmax rows -> attn ==========================
__global__ __launch_bounds__(256) void k_softmax(float* __restrict__ attn_out) {
    int b = blockIdx.x / NI, i = blockIdx.x - b * NI;
    int t = threadIdx.x;
    __shared__ float red[8];
    __shared__ float bc[1];
    float v = g_sim[(size_t)b * (NI * NP) + (size_t)i * NP + t];
    float m = v;
    #pragma unroll
    for (int off = 16; off; off >>= 1) m = fmaxf(m, __shfl_xor_sync(0xffffffffu, m, off));
    if ((t & 31) == 0) red[t >> 5] = m;
    __syncthreads();
    if (t == 0) {
        float mm = red[0];
        #pragma unroll
        for (int w = 1; w < 8; w++) mm = fmaxf(mm, red[w]);
        bc[0] = mm;
    }
    __syncthreads();
    float e = expf(v - bc[0]);
    float s = e;
    #pragma unroll
    for (int off = 16; off; off >>= 1) s += __shfl_xor_sync(0xffffffffu, s, off);
    if ((t & 31) == 0) red[t >> 5] = s;
    __syncthreads();
    if (t == 0) {
        float ss = 0.f;
        #pragma unroll
        for (int w = 0; w < 8; w++) ss += red[w];
        bc[0] = 1.f / ss;
    }
    __syncthreads();
    attn_out[(size_t)b * (NI * NP) + (size_t)i * NP + t] = e * bc[0];
}

// ================= kernel: xo = v_t @ attn^T (320x81, K=256) =============
__global__ __launch_bounds__(256) void k_xo(const float* __restrict__ attn) {
    int b = blockIdx.x;
    int mbase = blockIdx.y * 64;
    __shared__ float sv[16][68];
    __shared__ float sa[16][96];
    int tid = threadIdx.x;
    int am = tid >> 2, ak = (tid & 3) * 4;
    int tm = tid >> 4, tn = tid & 15;
    float acc[4][6];
    #pragma unroll
    for (int x = 0; x < 4; x++)
        #pragma unroll
        for (int y = 0; y < 6; y++) acc[x][y] = 0.f;

    for (int p0 = 0; p0 < NP; p0 += 16) {
        float4 v4 = *(const float4*)(g_v + (size_t)b * (NC * NP)
                                     + (size_t)(mbase + am) * NP + p0 + ak);
        sv[ak + 0][am] = v4.x; sv[ak + 1][am] = v4.y;
        sv[ak + 2][am] = v4.z; sv[ak + 3][am] = v4.w;
        for (int idx = tid; idx < 16 * NI; idx += 256) {
            int ii = idx >> 4, pp = idx & 15;
            sa[pp][ii] = attn[(size_t)b * (NI * NP) + (size_t)ii * NP + p0 + pp];
        }
        __syncthreads();
        #pragma unroll
        for (int p = 0; p < 16; p++) {
            float4 a4 = *(const float4*)&sv[p][tm * 4];
            float a[4] = {a4.x, a4.y, a4.z, a4.w};
            float bb[6];
            #pragma unroll
            for (int y = 0; y < 6; y++) bb[y] = sa[p][tn * 6 + y];
            #pragma unroll
            for (int x = 0; x < 4; x++)
                #pragma unroll
                for (int y = 0; y < 6; y++)
                    acc[x][y] = fmaf(a[x], bb[y], acc[x][y]);
        }
        __syncthreads();
    }
    #pragma unroll
    for (int x = 0; x < 4; x++) {
        int o = mbase + tm * 4 + x;
        #pragma unroll
        for (int y = 0; y < 6; y++) {
            int i = tn * 6 + y;
            if (i < NI) g_xo[(size_t)b * (NC * NI) + (size_t)o * NI + i] = acc[x][y];
        }
    }
}

// ========== kernel: residual + masked scatter ============================
__global__ __launch_bounds__(256) void k_out(const float* __restrict__ gx,
                                             const float* __restrict__ bbox,
                                             float* __restrict__ out) {
    int idx = blockIdx.x * 256 + threadIdx.x;
    int x = idx & 63;
    int y = (idx >> 6) & 63;
    int bc = idx >> 12;
    int b = bc / NC;
    int c = bc - b * NC;
    float val = gx[idx];
    int bx1 = (int)(bbox[b * 4 + 0] * 64.f);
    int by1 = (int)(bbox[b * 4 + 1] * 64.f);
    int bx2 = max((int)(bbox[b * 4 + 2] * 64.f), bx1 + 1);
    int by2 = max((int)(bbox[b * 4 + 3] * 64.f), by1 + 1);
    if (y >= by1 && y < by2 && x >= bx1 && x < bx2) {
        int sy = min(max((y - by1) * 9 / (by2 - by1), 0), 8);
        int sx = min(max((x - bx1) * 9 / (bx2 - bx1), 0), 8);
        val += g_xo[(size_t)b * (NC * NI) + (size_t)c * NI + sy * 9 + sx];
    }
    out[idx] = val;
}

// ============================ launch ======================================
extern "C" void kernel_launch(void* const* d_in, const int* in_sizes, int n_in,
                              void* d_out, int out_size) {
    const float* global_x  = (const float*)d_in[0];
    const float* context   = (const float*)d_in[1];
    const float* indicator = (const float*)d_in[2];
    const float* bbox      = (const float*)d_in[3];
    const float* ln_g      = (const float*)d_in[4];
    const float* ln_b      = (const float*)d_in[5];
    const float* cn_g      = (const float*)d_in[6];
    const float* cn_b      = (const float*)d_in[7];
    const float* w_in      = (const float*)d_in[8];
    const float* b_in      = (const float*)d_in[9];
    const float* w_ctx     = (const float*)d_in[10];
    const float* b_ctx     = (const float*)d_in[11];
    const float* w_out     = (const float*)d_in[12];
    const float* b_out     = (const float*)d_in[13];
    float* out  = (float*)d_out;
    float* attn = out + OUT_ATTN_OFF;

    static cudaStream_t s2 = nullptr;
    static cudaEvent_t ev_fork = nullptr, ev_join = nullptr;
    static bool init_done = false;
    if (!init_done) {
        cudaFuncSetAttribute(k_conv, cudaFuncAttributeMaxDynamicSharedMemorySize,
                             CV_SMEM);
        cudaFuncSetAttribute(k_kproj, cudaFuncAttributeMaxDynamicSharedMemorySize,
                             KP_SMEM);
        cudaStreamCreateWithFlags(&s2, cudaStreamNonBlocking);
        cudaEventCreateWithFlags(&ev_fork, cudaEventDisableTiming);
        cudaEventCreateWithFlags(&ev_join, cudaEventDisableTiming);
        init_done = true;
    }

    // fork: independent roi -> groupnorm -> q chain on s2
    cudaEventRecord(ev_fork, 0);
    cudaStreamWaitEvent(s2, ev_fork, 0);
    k_roi<<<(NB * XNC * NI + 255) / 256, 256, 0, s2>>>(global_x, bbox, indicator);
    k_gn_roi<<<NB * 32, 256, 0, s2>>>(ln_g, ln_b);
    k_gemm_q<<<dim3(32, 5), 256, 0, s2>>>(w_in, b_in);
    cudaEventRecord(ev_join, s2);

    // main chain: ctx prep -> k projection -> conv
    k_ctx<<<NB * 32, 256>>>(context, cn_g, cn_b);
    k_cvt_w<<<(NC * KK) / 256, 256>>>(w_out);
    k_cvt_wctx<<<(NC * CTX) / 256, 256>>>(w_ctx);
    k_kproj<<<128, 512, KP_SMEM>>>(b_ctx);
    k_conv<<<128, 512, CV_SMEM>>>(b_out);

    // join, then attention tail
    cudaStreamWaitEvent(0, ev_join, 0);
    k_sim<<<dim3(NB, 2), 256>>>();
    k_softmax<<<NB * NI, 256>>>(attn);
    k_xo<<<dim3(NB, 5), 256>>>(attn);
    k_out<<<(NB * NC * HH * WW) / 256, 256>>>(global_x, bbox, out);
}

// round 9
// speedup vs baseline: 8.1203x; 1.3670x over previous
#include <cuda_runtime.h>
#include <cuda_bf16.h>
#include <cuda_fp16.h>
#include <math.h>
#include <stdint.h>

// ---------------- problem constants ----------------
#define NB   32
#define NC   320
#define HH   64
#define WW   64
#define CTX  1024
#define NP   256      // 16x16 ctx spatial
#define NI   81       // 9x9 roi points
#define XNC  322      // 320 + 2 indicator channels
#define KK   9216     // conv GEMM K = 1024*9
#define OUT_ATTN_OFF 41943040  // 32*320*64*64

// ---------------- device scratch (static, no allocation) ----------------
__device__ float g_xn   [NB * XNC * NI];    // roi features [b][c][i]
__device__ float g_q    [NB * NC * NI];
__device__ float g_k    [NB * NC * NP];
__device__ float g_v    [NB * NC * NP];
__device__ float g_sim  [NB * NI * NP];
__device__ float g_xo   [NB * NC * NI];
// fp16 operands for conv (single MMA, fp32 accumulate)
__device__ __align__(16) __half g_cxf[NB * NP * CTX];         // raw context fp16 [b][p][c]
__device__ __align__(16) __half g_wf [NC * KK];               // w_out fp16 [o][tap*1024+c]
// bf16 hi/lo split operands for k projection (3x split, high accuracy)
__device__ __align__(16) __nv_bfloat16 g_kmh[NB * NP * CTX];  // normed ctx hi [b][p][c]
__device__ __align__(16) __nv_bfloat16 g_kml[NB * NP * CTX];  // normed ctx lo
__device__ __align__(16) __nv_bfloat16 g_wch[NC * CTX];       // w_ctx hi [o][c]
__device__ __align__(16) __nv_bfloat16 g_wcl[NC * CTX];       // w_ctx lo

// =================== helpers (baseline PTX only) ========================
__device__ __forceinline__ uint32_t smem_u32(const void* p) {
    uint32_t a;
    asm("{ .reg .u64 t; cvta.to.shared.u64 t, %1; cvt.u32.u64 %0, t; }" : "=r"(a) : "l"(p));
    return a;
}
#define CP16(dst, src, sz) \
    asm volatile("cp.async.ca.shared.global [%0], [%1], 16, %2;" \
                 :: "r"(dst), "l"(src), "r"(sz))
#define CP_COMMIT() asm volatile("cp.async.commit_group;" ::: "memory")
#define CP_WAIT(n)  asm volatile("cp.async.wait_group %0;" :: "n"(n) : "memory")

__device__ __forceinline__ void mma_bf16(float* c, const uint32_t* a, const uint32_t* b) {
    asm volatile("mma.sync.aligned.m16n8k16.row.col.f32.bf16.bf16.f32 "
        "{%0,%1,%2,%3}, {%4,%5,%6,%7}, {%8,%9}, {%0,%1,%2,%3};"
        : "+f"(c[0]), "+f"(c[1]), "+f"(c[2]), "+f"(c[3])
        : "r"(a[0]), "r"(a[1]), "r"(a[2]), "r"(a[3]), "r"(b[0]), "r"(b[1]));
}
__device__ __forceinline__ void mma_f16(float* c, const uint32_t* a, const uint32_t* b) {
    asm volatile("mma.sync.aligned.m16n8k16.row.col.f32.f16.f16.f32 "
        "{%0,%1,%2,%3}, {%4,%5,%6,%7}, {%8,%9}, {%0,%1,%2,%3};"
        : "+f"(c[0]), "+f"(c[1]), "+f"(c[2]), "+f"(c[3])
        : "r"(a[0]), "r"(a[1]), "r"(a[2]), "r"(a[3]), "r"(b[0]), "r"(b[1]));
}

// ================= prep: weight conversions ==============================
__global__ __launch_bounds__(256) void k_cvt_w(const float* __restrict__ w_out) {
    int idx = blockIdx.x * 256 + threadIdx.x;   // NC*KK
    int o = idx / KK, r = idx - o * KK;
    int tap = r >> 10, c = r & 1023;
    g_wf[idx] = __float2half(w_out[o * KK + c * 9 + tap]);
}
__global__ __launch_bounds__(256) void k_cvt_wctx(const float* __restrict__ w_ctx) {
    int idx = blockIdx.x * 256 + threadIdx.x;   // NC*CTX
    float v = w_ctx[idx];
    __nv_bfloat16 h = __float2bfloat16(v);
    g_wch[idx] = h;
    g_wcl[idx] = __float2bfloat16(v - __bfloat162float(h));
}

// ============ fp16 conv: v = w_out (*) ctx + b_out =======================
// grid 128 = 32 imgs x (2 M-tiles of 160) x (2 N-tiles of 128). 512 thr.
// fp16 operands, fp32 accum. K-chunks of 128 (72 chunks), double buffer.
// Rows padded to 136 fp16 = 272B = 68 u32: bank = (4*row + kb) % 32.
#define CV_B_OFF 43520               // A = 160*272
#define CV_BUF   78336               // + B = 128*272
#define CV_SMEM  (2 * CV_BUF)
#define CV_NCH   72

__global__ void __launch_bounds__(512, 1) k_conv(const float* __restrict__ bias) {
    extern __shared__ char smem[];
    uint32_t sb = smem_u32(smem);
    int tid = threadIdx.x;
    int bimg = blockIdx.x >> 2;
    int tt = blockIdx.x & 3;
    int mbase = (tt >> 1) * 160;
    int pbase = (tt & 1) * 128;
    const __half* Bsrc = g_cxf + (size_t)bimg * (NP * CTX);

    auto load_chunk = [&](int buf, int ch) {
        uint32_t base = sb + buf * CV_BUF;
        int tap = ch >> 3, c0 = (ch & 7) << 7;
        int t3 = tap / 3;
        int dy = t3 - 1, dx = tap - t3 * 3 - 1;
        #pragma unroll
        for (int r = 0; r < 5; r++) {
            int id = r * 512 + tid;
            int row = id >> 4, v = id & 15;
            size_t so = (size_t)(mbase + row) * KK + tap * 1024 + c0 + v * 8;
            CP16(base + (uint32_t)(row * 272 + v * 16), g_wf + so, 16);
        }
        #pragma unroll
        for (int r = 0; r < 4; r++) {
            int id = r * 512 + tid;
            int row = id >> 4, v = id & 15;
            int p = pbase + row;
            int yy = (p >> 4) + dy, xx = (p & 15) + dx;
            int ok = ((unsigned)yy < 16u && (unsigned)xx < 16u) ? 16 : 0;
            size_t so = ok ? ((size_t)(yy * 16 + xx) * CTX + c0 + v * 8) : 0;
            CP16(base + CV_B_OFF + (uint32_t)(row * 272 + v * 16), Bsrc + so, ok);
        }
    };

    int w = tid >> 5, l = tid & 31;
    int wm = w >> 3;        // 0..1: m offset 80
    int wn = w & 7;         // 0..7: n offset 16
    int g = l >> 2, tg = l & 3;

    float acc[5][2][4];
    #pragma unroll
    for (int f = 0; f < 5; f++)
        #pragma unroll
        for (int j = 0; j < 2; j++)
            #pragma unroll
            for (int q = 0; q < 4; q++) acc[f][j][q] = 0.f;

    auto compute = [&](int buf) {
        const uint32_t* pA = (const uint32_t*)(smem + buf * CV_BUF);
        const uint32_t* pB = (const uint32_t*)(smem + buf * CV_BUF + CV_B_OFF);
        #pragma unroll
        for (int s = 0; s < 8; s++) {
            int kb = s * 8 + tg;
            uint32_t ah[5][4];
            #pragma unroll
            for (int f = 0; f < 5; f++) {
                int r0 = (wm * 80 + f * 16 + g) * 68;
                int r8 = r0 + 8 * 68;
                ah[f][0] = pA[r0 + kb];     ah[f][1] = pA[r8 + kb];
                ah[f][2] = pA[r0 + kb + 4]; ah[f][3] = pA[r8 + kb + 4];
            }
            #pragma unroll
            for (int j = 0; j < 2; j++) {
                int n = (wn * 16 + j * 8 + g) * 68;
                uint32_t bh[2] = { pB[n + kb], pB[n + kb + 4] };
                #pragma unroll
                for (int f = 0; f < 5; f++)
                    mma_f16(acc[f][j], ah[f], bh);
            }
        }
    };

    load_chunk(0, 0);
    CP_COMMIT();
    for (int ch = 0; ch < CV_NCH; ch++) {
        if (ch + 1 < CV_NCH) {
            load_chunk((ch + 1) & 1, ch + 1);
            CP_COMMIT();
            CP_WAIT(1);
        } else {
            CP_WAIT(0);
        }
        __syncthreads();
        compute(ch & 1);
        __syncthreads();
    }

    float* dst = g_v + (size_t)bimg * (NC * NP);
    #pragma unroll
    for (int f = 0; f < 5; f++) {
        int o0 = mbase + wm * 80 + f * 16 + g;
        int o1 = o0 + 8;
        float b0 = bias[o0], b1 = bias[o1];
        #pragma unroll
        for (int j = 0; j < 2; j++) {
            int p = pbase + wn * 16 + j * 8 + tg * 2;
            *(float2*)(dst + (size_t)o0 * NP + p)
                = make_float2(acc[f][j][0] + b0, acc[f][j][1] + b0);
            *(float2*)(dst + (size_t)o1 * NP + p)
                = make_float2(acc[f][j][2] + b1, acc[f][j][3] + b1);
        }
    }
}

// ===== k projection (3xBF16 split, high accuracy): k = w_ctx @ kmap ======
#define SA_LD 23040
#define SB_LD 18432
#define SB_OFF 46080
#define BUFSTRIDE 82944
#define KP_SMEM (2 * BUFSTRIDE)

__global__ void __launch_bounds__(512, 1) k_kproj(const float* __restrict__ bias) {
    const int NCH = 16;
    extern __shared__ char smem[];
    uint32_t sb = smem_u32(smem);
    int tid = threadIdx.x;
    int bimg = blockIdx.x >> 2;
    int tt = blockIdx.x & 3;
    int mbase = (tt >> 1) * 160;
    int pbase = (tt & 1) * 128;

    const __nv_bfloat16* Bh = g_kmh + (size_t)bimg * (NP * CTX);
    const __nv_bfloat16* Bl = g_kml + (size_t)bimg * (NP * CTX);

    auto load_chunk = [&](int buf, int ch) {
        uint32_t base = sb + buf * BUFSTRIDE;
        int c0 = ch << 6;
        for (int id = tid; id < 1280; id += 512) {
            int row = id >> 3, v = id & 7;
            size_t so = (size_t)(mbase + row) * CTX + c0 + v * 8;
            uint32_t dst = base + (uint32_t)(row * 144 + v * 16);
            CP16(dst, g_wch + so, 16);
            CP16(dst + SA_LD, g_wcl + so, 16);
        }
        for (int id = tid; id < 1024; id += 512) {
            int row = id >> 3, v = id & 7;
            size_t so = (size_t)(pbase + row) * CTX + c0 + v * 8;
            uint32_t dst = base + SB_OFF + (uint32_t)(row * 144 + v * 16);
            CP16(dst, Bh + so, 16);
            CP16(dst + SB_LD, Bl + so, 16);
        }
    };

    int w = tid >> 5, l = tid & 31;
    int wm = w >> 3;
    int wn = w & 7;
    int g = l >> 2, tg = l & 3;

    float acc[5][2][4];
    #pragma unroll
    for (int f = 0; f < 5; f++)
        #pragma unroll
        for (int j = 0; j < 2; j++)
            #pragma unroll
            for (int q = 0; q < 4; q++) acc[f][j][q] = 0.f;

    auto compute = [&](int buf) {
        const uint32_t* pAh = (const uint32_t*)(smem + buf * BUFSTRIDE);
        const uint32_t* pAl = (const uint32_t*)(smem + buf * BUFSTRIDE + SA_LD);
        const uint32_t* pBh = (const uint32_t*)(smem + buf * BUFSTRIDE + SB_OFF);
        const uint32_t* pBl = (const uint32_t*)(smem + buf * BUFSTRIDE + SB_OFF + SB_LD);
        #pragma unroll
        for (int s = 0; s < 4; s++) {
            int kb = s * 8 + tg;
            uint32_t ah[5][4], al[5][4];
            #pragma unroll
            for (int f = 0; f < 5; f++) {
                int r0 = (wm * 80 + f * 16 + g) * 36;
                int r8 = r0 + 8 * 36;
                ah[f][0] = pAh[r0 + kb];     ah[f][1] = pAh[r8 + kb];
                ah[f][2] = pAh[r0 + kb + 4]; ah[f][3] = pAh[r8 + kb + 4];
                al[f][0] = pAl[r0 + kb];     al[f][1] = pAl[r8 + kb];
                al[f][2] = pAl[r0 + kb + 4]; al[f][3] = pAl[r8 + kb + 4];
            }
            #pragma unroll
            for (int j = 0; j < 2; j++) {
                int n = (wn * 16 + j * 8 + g) * 36;
                uint32_t bh[2] = { pBh[n + kb], pBh[n + kb + 4] };
                uint32_t bl[2] = { pBl[n + kb], pBl[n + kb + 4] };
                #pragma unroll
                for (int f = 0; f < 5; f++) {
                    mma_bf16(acc[f][j], ah[f], bh);
                    mma_bf16(acc[f][j], ah[f], bl);
                    mma_bf16(acc[f][j], al[f], bh);
                }
            }
        }
    };

    load_chunk(0, 0);
    CP_COMMIT();
    for (int ch = 0; ch < NCH; ch++) {
        if (ch + 1 < NCH) {
            load_chunk((ch + 1) & 1, ch + 1);
            CP_COMMIT();
            CP_WAIT(1);
        } else {
            CP_WAIT(0);
        }
        __syncthreads();
        compute(ch & 1);
        __syncthreads();
    }

    float* dst = g_k + (size_t)bimg * (NC * NP);
    #pragma unroll
    for (int f = 0; f < 5; f++) {
        int o0 = mbase + wm * 80 + f * 16 + g;
        int o1 = o0 + 8;
        float b0 = bias[o0], b1 = bias[o1];
        #pragma unroll
        for (int j = 0; j < 2; j++) {
            int p = pbase + wn * 16 + j * 8 + tg * 2;
            *(float2*)(dst + (size_t)o0 * NP + p)
                = make_float2(acc[f][j][0] + b0, acc[f][j][1] + b0);
            *(float2*)(dst + (size_t)o1 * NP + p)
                = make_float2(acc[f][j][2] + b1, acc[f][j][3] + b1);
        }
    }
}

// ====== kernel 1: ctx group norm + fp16 raw + bf16 hi/lo normed =========
__global__ __launch_bounds__(256) void k_ctx(const float* __restrict__ context,
                                             const float* __restrict__ cn_g,
                                             const float* __restrict__ cn_b) {
    int b = blockIdx.x >> 5, g = blockIdx.x & 31;
    __shared__ float s[32 * 257];
    __shared__ float redA[8], redB[8];
    __shared__ float stats[2];
    const float* src = context + (size_t)b * (NP * CTX) + g * 32;
    float sum = 0.f, sq = 0.f;
    for (int i = threadIdx.x; i < 8192; i += 256) {
        int cl = i & 31, p = i >> 5;
        float v = src[(size_t)p * CTX + cl];
        s[cl * 257 + p] = v;
        sum += v; sq += v * v;
    }
    #pragma unroll
    for (int off = 16; off; off >>= 1) {
        sum += __shfl_down_sync(0xffffffffu, sum, off);
        sq  += __shfl_down_sync(0xffffffffu, sq,  off);
    }
    if ((threadIdx.x & 31) == 0) { redA[threadIdx.x >> 5] = sum; redB[threadIdx.x >> 5] = sq; }
    __syncthreads();
    if (threadIdx.x == 0) {
        float a = 0.f, b2 = 0.f;
        #pragma unroll
        for (int w = 0; w < 8; w++) { a += redA[w]; b2 += redB[w]; }
        float mean = a * (1.f / 8192.f);
        float var  = b2 * (1.f / 8192.f) - mean * mean;
        stats[0] = mean; stats[1] = rsqrtf(var + 1e-6f);
    }
    __syncthreads();
    float mean = stats[0], rstd = stats[1];
    int cl = threadIdx.x & 31;
    int c = g * 32 + cl;
    float gam = cn_g[c] * rstd, bet = cn_b[c];
    for (int i = threadIdx.x; i < 8192; i += 256) {
        int p = i >> 5;
        float v = s[cl * 257 + p];
        size_t o = ((size_t)b * NP + p) * CTX + c;
        g_cxf[o] = __float2half(v);
        float nv = (v - mean) * gam + bet;
        __nv_bfloat16 nh = __float2bfloat16(nv);
        g_kmh[o] = nh;
        g_kml[o] = __float2bfloat16(nv - __bfloat162float(nh));
    }
}

// ================= kernel 2a: roi bilinear samples ======================
__global__ __launch_bounds__(256) void k_roi(const float* __restrict__ gx,
                                             const float* __restrict__ bbox,
                                             const float* __restrict__ indicator) {
    int idx = blockIdx.x * 256 + threadIdx.x;
    if (idx >= NB * XNC * NI) return;
    int b = idx / (XNC * NI);
    int r = idx - b * (XNC * NI);
    int c = r / NI;
    int i = r - c * NI;
    float out;
    if (c >= NC) {
        out = indicator[b * 2 + (c - NC)];
    } else {
        float x1 = bbox[b * 4 + 0], y1 = bbox[b * 4 + 1];
        float x2 = bbox[b * 4 + 2], y2 = bbox[b * 4 + 3];
        float rw = fmaxf(x2 - x1, 1.0f), rh = fmaxf(y2 - y1, 1.0f);
        int iy = i / 9, ix = i - iy * 9;
        float xs = x1 + ((float)ix + 0.5f) * (rw * (1.f / 9.f));
        float ys = y1 + ((float)iy + 0.5f) * (rh * (1.f / 9.f));
        float yv = fminf(fmaxf(ys, 0.f), 63.f);
        float xv = fminf(fmaxf(xs, 0.f), 63.f);
        int y0 = (int)floorf(yv), x0 = (int)floorf(xv);
        int y1i = min(y0 + 1, 63), x1i = min(x0 + 1, 63);
        float ly = yv - (float)y0, lx = xv - (float)x0;
        const float* im = gx + (size_t)b * (NC * HH * WW) + (size_t)c * (HH * WW);
        float g00 = im[y0 * WW + x0],  g01 = im[y0 * WW + x1i];
        float g10 = im[y1i * WW + x0], g11 = im[y1i * WW + x1i];
        out = g00 * (1.f - ly) * (1.f - lx) + g01 * (1.f - ly) * lx
            + g10 * ly * (1.f - lx)        + g11 * ly * lx;
    }
    g_xn[idx] = out;
}

// ============ kernel 2b: group norm over roi features ====================
__global__ __launch_bounds__(256) void k_gn_roi(const float* __restrict__ ln_g,
                                                const float* __restrict__ ln_b) {
    int b = blockIdx.x >> 5, g = blockIdx.x & 31;
    float* base = g_xn + (size_t)b * (XNC * NI) + g * 810;
    __shared__ float s[810];
    __shared__ float redA[8], redB[8];
    __shared__ float stats[2];
    float sum = 0.f, sq = 0.f;
    for (int i = threadIdx.x; i < 810; i += 256) {
        float v = base[i];
        s[i] = v; sum += v; sq += v * v;
    }
    #pragma unroll
    for (int off = 16; off; off >>= 1) {
        sum += __shfl_down_sync(0xffffffffu, sum, off);
        sq  += __shfl_down_sync(0xffffffffu, sq,  off);
    }
    if ((threadIdx.x & 31) == 0) { redA[threadIdx.x >> 5] = sum; redB[threadIdx.x >> 5] = sq; }
    __syncthreads();
    if (threadIdx.x == 0) {
        float a = 0.f, b2 = 0.f;
        #pragma unroll
        for (int w = 0; w < 8; w++) { a += redA[w]; b2 += redB[w]; }
        float mean = a * (1.f / 810.f);
        float var  = b2 * (1.f / 810.f) - mean * mean;
        stats[0] = mean; stats[1] = rsqrtf(var + 1e-6f);
    }
    __syncthreads();
    float mean = stats[0], rstd = stats[1];
    for (int i = threadIdx.x; i < 810; i += 256) {
        int c = g * 10 + i / 81;
        base[i] = (s[i] - mean) * rstd * ln_g[c] + ln_b[c];
    }
}

// ================= q projection SGEMM (FFMA, fp32-exact path) ===========
__global__ __launch_bounds__(256) void k_gemm_q(const float* __restrict__ A,
                                                const float* __restrict__ bias) {
    const int K = 322;
    __shared__ float sA[16][68];
    __shared__ float sB[16][128];
    int tid = threadIdx.x;
    int b = blockIdx.x;
    int mbase = blockIdx.y * 64;

    float acc[4][8];
    #pragma unroll
    for (int x = 0; x < 4; x++)
        #pragma unroll
        for (int y = 0; y < 8; y++) acc[x][y] = 0.f;

    int am = tid >> 2;
    int ak = (tid & 3) * 4;
    int bk = tid >> 4;
    int bn = (tid & 15) * 8;
    int tm = tid >> 4, tn = tid & 15;

    const float* abase = A + (size_t)(mbase + am) * K + ak;

    for (int k0 = 0; k0 < K; k0 += 16) {
        #pragma unroll
        for (int j = 0; j < 4; j++) {
            float v = 0.f;
            if (k0 + ak + j < 322) v = abase[k0 + j];
            sA[ak + j][am] = v;
        }
        int kk = k0 + bk;
        const float* bp = g_xn + (size_t)b * (XNC * NI) + (size_t)kk * NI;
        bool kok = kk < 322;
        #pragma unroll
        for (int j = 0; j < 8; j++) {
            int n = bn + j;
            sB[bk][bn + j] = (kok && n < NI) ? bp[n] : 0.f;
        }
        __syncthreads();
        #pragma unroll
        for (int k = 0; k < 16; k++) {
            float4 a4 = *(const float4*)&sA[k][tm * 4];
            float4 b0 = *(const float4*)&sB[k][tn * 8];
            float4 b1 = *(const float4*)&sB[k][tn * 8 + 4];
            float a[4]  = {a4.x, a4.y, a4.z, a4.w};
            float bb[8] = {b0.x, b0.y, b0.z, b0.w, b1.x, b1.y, b1.z, b1.w};
            #pragma unroll
            for (int x = 0; x < 4; x++)
                #pragma unroll
                for (int y = 0; y < 8; y++)
                    acc[x][y] = fmaf(a[x], bb[y], acc[x][y]);
        }
        __syncthreads();
    }
    #pragma unroll
    for (int x = 0; x < 4; x++) {
        int o = mbase + tm * 4 + x;
        float bs = bias[o];
        #pragma unroll
        for (int y = 0; y < 8; y++) {
            int n = tn * 8 + y;
            if (n < NI) g_q[(size_t)b * (NC * NI) + (size_t)o * NI + n] = acc[x][y] + bs;
        }
    }
}

// ======== kernel: sim = q^T k (81x128 per block, K=320), grid (32,2) =====
__global__ __launch_bounds__(256) void k_sim() {
    int b = blockIdx.x;
    int pb = blockIdx.y * 128;
    __shared__ float sq[8][96];
    __shared__ float sk[8][128];
    int tid = threadIdx.x;
    int ti = tid >> 4;
    int tp = tid & 15;
    float acc[6][8];
    #pragma unroll
    for (int x = 0; x < 6; x++)
        #pragma unroll
        for (int y = 0; y < 8; y++) acc[x][y] = 0.f;

    for (int o0 = 0; o0 < NC; o0 += 8) {
        for (int idx = tid; idx < 8 * NI; idx += 256) {
            int ko = idx / NI, i = idx - ko * NI;
            sq[ko][i] = g_q[(size_t)b * (NC * NI) + (size_t)(o0 + ko) * NI + i];
        }
        {
            int ko = tid >> 5;
            int pp = (tid & 31) * 4;
            *(float4*)&sk[ko][pp] = *(const float4*)(g_k + (size_t)b * (NC * NP)
                                       + (size_t)(o0 + ko) * NP + pb + pp);
        }
        __syncthreads();
        #pragma unroll
        for (int ko = 0; ko < 8; ko++) {
            float a[6];
            #pragma unroll
            for (int x = 0; x < 6; x++) a[x] = sq[ko][ti * 6 + x];
            float4 b0 = *(const float4*)&sk[ko][tp * 8];
            float4 b1 = *(const float4*)&sk[ko][tp * 8 + 4];
            float bb[8] = {b0.x, b0.y, b0.z, b0.w, b1.x, b1.y, b1.z, b1.w};
            #pragma unroll
            for (int x = 0; x < 6; x++)
                #pragma unroll
                for (int y = 0; y < 8; y++)
                    acc[x][y] = fmaf(a[x], bb[y], acc[x][y]);
        }
        __syncthreads();
    }
    #pragma unroll
    for (int x = 0; x < 6; x++) {
        int i = ti * 6 + x;
        if (i < NI) {
            #pragma unroll
            for (int y = 0; y < 8; y++)
                g_sim[(size_t)b * (NI * NP) + (size_t)i * NP + pb + tp * 8 + y] = acc[x][y];
        }
    }
}

// ================= kernel: softmax rows -> attn ==========================
__global__ __launch_bounds__(256) void k_softmax(float* __restrict__ attn_out) {
    int b = blockIdx.x / NI, i = blockIdx.x - b * NI;
    int t = threadIdx.x;
    __shared__ float red[8];
    __shared__ float bc[1];
    float v = g_sim[(size_t)b * (NI * NP) + (size_t)i * NP + t];
    float m = v;
    #pragma unroll
    for (int off = 16; off; off >>= 1) m = fmaxf(m, __shfl_xor_sync(0xffffffffu, m, off));
    if ((t & 31) == 0) red[t >> 5] = m;
    __syncthreads();
    if (t == 0) {
        float mm = red[0];
        #pragma unroll
        for (int w = 1; w < 8; w++) mm = fmaxf(mm, red[w]);
        bc[0] = mm;
    }
    __syncthreads();
    float e = expf(v - bc[0]);
    float s = e;
    #pragma unroll
    for (int off = 16; off; off >>= 1) s += __shfl_xor_sync(0xffffffffu, s, off);
    if ((t & 31) == 0) red[t >> 5] = s;
    __syncthreads();
    if (t == 0) {
        float ss = 0.f;
        #pragma unroll
        for (int w = 0; w < 8; w++) ss += red[w];
        bc[0] = 1.f / ss;
    }
    __syncthreads();
    attn_out[(size_t)b * (NI * NP) + (size_t)i * NP + t] = e * bc[0];
}

// ================= kernel: xo = v_t @ attn^T (320x81, K=256) =============
__global__ __launch_bounds__(256) void k_xo(const float* __restrict__ attn) {
    int b = blockIdx.x;
    int mbase = blockIdx.y * 64;
    __shared__ float sv[16][68];
    __shared__ float sa[16][96];
    int tid = threadIdx.x;
    int am = tid >> 2, ak = (tid & 3) * 4;
    int tm = tid >> 4, tn = tid & 15;
    float acc[4][6];
    #pragma unroll
    for (int x = 0; x < 4; x++)
        #pragma unroll
        for (int y = 0; y < 6; y++) acc[x][y] = 0.f;

    for (int p0 = 0; p0 < NP; p0 += 16) {
        float4 v4 = *(const float4*)(g_v + (size_t)b * (NC * NP)
                                     + (size_t)(mbase + am) * NP + p0 + ak);
        sv[ak + 0][am] = v4.x; sv[ak + 1][am] = v4.y;
        sv[ak + 2][am] = v4.z; sv[ak + 3][am] = v4.w;
        for (int idx = tid; idx < 16 * NI; idx += 256) {
            int ii = idx >> 4, pp = idx & 15;
            sa[pp][ii] = attn[(size_t)b * (NI * NP) + (size_t)ii * NP + p0 + pp];
        }
        __syncthreads();
        #pragma unroll
        for (int p = 0; p < 16; p++) {
            float4 a4 = *(const float4*)&sv[p][tm * 4];
            float a[4] = {a4.x, a4.y, a4.z, a4.w};
            float bb[6];
            #pragma unroll
            for (int y = 0; y < 6; y++) bb[y] = sa[p][tn * 6 + y];
            #pragma unroll
            for (int x = 0; x < 4; x++)
                #pragma unroll
                for (int y = 0; y < 6; y++)
                    acc[x][y] = fmaf(a[x], bb[y], acc[x][y]);
        }
        __syncthreads();
    }
    #pragma unroll
    for (int x = 0; x < 4; x++) {
        int o = mbase + tm * 4 + x;
        #pragma unroll
        for (int y = 0; y < 6; y++) {
            int i = tn * 6 + y;
            if (i < NI) g_xo[(size_t)b * (NC * NI) + (size_t)o * NI + i] = acc[x][y];
        }
    }
}

// ========== kernel: residual + masked scatter (float4) ===================
__global__ __launch_bounds__(256) void k_out(const float* __restrict__ gx,
                                             const float* __restrict__ bbox,
                                             float* __restrict__ out) {
    int t = blockIdx.x * 256 + threadIdx.x;   // handles 4 consecutive x
    int base = t * 4;
    int x0 = base & 63;
    int y = (base >> 6) & 63;
    int bc = base >> 12;
    int b = bc / NC;
    int c = bc - b * NC;
    float4 val = *(const float4*)(gx + base);
    int bx1 = (int)(bbox[b * 4 + 0] * 64.f);
    int by1 = (int)(bbox[b * 4 + 1] * 64.f);
    int bx2 = max((int)(bbox[b * 4 + 2] * 64.f), bx1 + 1);
    int by2 = max((int)(bbox[b * 4 + 3] * 64.f), by1 + 1);
    if (y >= by1 && y < by2) {
        int sy = min(max((y - by1) * 9 / (by2 - by1), 0), 8);
        const float* xrow = g_xo + (size_t)b * (NC * NI) + (size_t)c * NI + sy * 9;
        float* vp = &val.x;
        #pragma unroll
        for (int j = 0; j < 4; j++) {
            int x = x0 + j;
            if (x >= bx1 && x < bx2) {
                int sx = min(max((x - bx1) * 9 / (bx2 - bx1), 0), 8);
                vp[j] += xrow[sx];
            }
        }
    }
    *(float4*)(out + base) = val;
}

// ============================ launch ======================================
extern "C" void kernel_launch(void* const* d_in, const int* in_sizes, int n_in,
                              void* d_out, int out_size) {
    const float* global_x  = (const float*)d_in[0];
    const float* context   = (const float*)d_in[1];
    const float* indicator = (const float*)d_in[2];
    const float* bbox      = (const float*)d_in[3];
    const float* ln_g      = (const float*)d_in[4];
    const float* ln_b      = (const float*)d_in[5];
    const float* cn_g      = (const float*)d_in[6];
    const float* cn_b      = (const float*)d_in[7];
    const float* w_in      = (const float*)d_in[8];
    const float* b_in      = (const float*)d_in[9];
    const float* w_ctx     = (const float*)d_in[10];
    const float* b_ctx     = (const float*)d_in[11];
    const float* w_out     = (const float*)d_in[12];
    const float* b_out     = (const float*)d_in[13];
    float* out  = (float*)d_out;
    float* attn = out + OUT_ATTN_OFF;

    static cudaStream_t s2 = nullptr, s3 = nullptr;
    static cudaEvent_t ev_fork = nullptr, ev_q = nullptr;
    static cudaEvent_t ev_ctx = nullptr, ev_wctx = nullptr, ev_conv = nullptr;
    static bool init_done = false;
    if (!init_done) {
        cudaFuncSetAttribute(k_conv, cudaFuncAttributeMaxDynamicSharedMemorySize,
                             CV_SMEM);
        cudaFuncSetAttribute(k_kproj, cudaFuncAttributeMaxDynamicSharedMemorySize,
                             KP_SMEM);
        cudaStreamCreateWithFlags(&s2, cudaStreamNonBlocking);
        cudaStreamCreateWithFlags(&s3, cudaStreamNonBlocking);
        cudaEventCreateWithFlags(&ev_fork, cudaEventDisableTiming);
        cudaEventCreateWithFlags(&ev_q,    cudaEventDisableTiming);
        cudaEventCreateWithFlags(&ev_ctx,  cudaEventDisableTiming);
        cudaEventCreateWithFlags(&ev_wctx, cudaEventDisableTiming);
        cudaEventCreateWithFlags(&ev_conv, cudaEventDisableTiming);
        init_done = true;
    }

    cudaEventRecord(ev_fork, 0);
    cudaStreamWaitEvent(s2, ev_fork, 0);
    cudaStreamWaitEvent(s3, ev_fork, 0);

    // s2: independent roi -> groupnorm -> q chain
    k_roi<<<(NB * XNC * NI + 255) / 256, 256, 0, s2>>>(global_x, bbox, indicator);
    k_gn_roi<<<NB * 32, 256, 0, s2>>>(ln_g, ln_b);
    k_gemm_q<<<dim3(32, 5), 256, 0, s2>>>(w_in, b_in);
    cudaEventRecord(ev_q, s2);

    // s3: weight conversions (overlap with k_ctx), then conv after ctx ready
    k_cvt_wctx<<<(NC * CTX) / 256, 256, 0, s3>>>(w_ctx);
    cudaEventRecord(ev_wctx, s3);
    k_cvt_w<<<(NC * KK) / 256, 256, 0, s3>>>(w_out);

    // default: context groupnorm + splits
    k_ctx<<<NB * 32, 256>>>(context, cn_g, cn_b);
    cudaEventRecord(ev_ctx, 0);

    // s3: conv (needs g_cxf from k_ctx + g_wf from cvt_w)
    cudaStreamWaitEvent(s3, ev_ctx, 0);
    k_conv<<<128, 512, CV_SMEM, s3>>>(b_out);
    cudaEventRecord(ev_conv, s3);

    // default: k projection (needs kmap from k_ctx + wch/wcl from cvt_wctx)
    cudaStreamWaitEvent(0, ev_wctx, 0);
    k_kproj<<<128, 512, KP_SMEM>>>(b_ctx);

    // attention tail on default
    cudaStreamWaitEvent(0, ev_q, 0);
    k_sim<<<dim3(NB, 2), 256>>>();
    k_softmax<<<NB * NI, 256>>>(attn);
    cudaStreamWaitEvent(0, ev_conv, 0);
    k_xo<<<dim3(NB, 5), 256>>>(attn);
    k_out<<<(NB * NC * HH * WW) / 1024, 256>>>(global_x, bbox, out);
}

// round 11
// speedup vs baseline: 8.5276x; 1.0502x over previous
#include <cuda_runtime.h>
#include <cuda_bf16.h>
#include <cuda_fp16.h>
#include <math.h>
#include <stdint.h>

// ---------------- problem constants ----------------
#define NB   32
#define NC   320
#define HH   64
#define WW   64
#define CTX  1024
#define NP   256      // 16x16 ctx spatial
#define NI   81       // 9x9 roi points
#define XNC  322      // 320 + 2 indicator channels
#define KK   9216     // conv GEMM K = 1024*9
#define OUT_ATTN_OFF 41943040  // 32*320*64*64

// ---------------- device scratch (static, no allocation) ----------------
__device__ float g_xn   [NB * XNC * NI];    // roi features [b][c][i]
__device__ float g_q    [NB * NC * NI];
__device__ float g_k    [NB * NC * NP];
__device__ float g_v    [NB * NC * NP];
__device__ float g_sim  [NB * NI * NP];
__device__ float g_xo   [NB * NC * NI];
// fp16 operands for conv (single MMA, fp32 accumulate)
__device__ __align__(16) __half g_cxf[NB * NP * CTX];         // raw context fp16 [b][p][c]
__device__ __align__(16) __half g_wf [NC * KK];               // w_out fp16 [o][tap*1024+c]
// bf16 hi/lo split operands for k projection (3x split, high accuracy)
__device__ __align__(16) __nv_bfloat16 g_kmh[NB * NP * CTX];  // normed ctx hi [b][p][c]
__device__ __align__(16) __nv_bfloat16 g_kml[NB * NP * CTX];  // normed ctx lo
__device__ __align__(16) __nv_bfloat16 g_wch[NC * CTX];       // w_ctx hi [o][c]
__device__ __align__(16) __nv_bfloat16 g_wcl[NC * CTX];       // w_ctx lo

// =================== helpers (baseline PTX only) ========================
__device__ __forceinline__ uint32_t smem_u32(const void* p) {
    uint32_t a;
    asm("{ .reg .u64 t; cvta.to.shared.u64 t, %1; cvt.u32.u64 %0, t; }" : "=r"(a) : "l"(p));
    return a;
}
#define CP16(dst, src, sz) \
    asm volatile("cp.async.ca.shared.global [%0], [%1], 16, %2;" \
                 :: "r"(dst), "l"(src), "r"(sz))
#define CP_COMMIT() asm volatile("cp.async.commit_group;" ::: "memory")
#define CP_WAIT(n)  asm volatile("cp.async.wait_group %0;" :: "n"(n) : "memory")

__device__ __forceinline__ void mma_bf16(float* c, const uint32_t* a, const uint32_t* b) {
    asm volatile("mma.sync.aligned.m16n8k16.row.col.f32.bf16.bf16.f32 "
        "{%0,%1,%2,%3}, {%4,%5,%6,%7}, {%8,%9}, {%0,%1,%2,%3};"
        : "+f"(c[0]), "+f"(c[1]), "+f"(c[2]), "+f"(c[3])
        : "r"(a[0]), "r"(a[1]), "r"(a[2]), "r"(a[3]), "r"(b[0]), "r"(b[1]));
}
__device__ __forceinline__ void mma_f16(float* c, const uint32_t* a, const uint32_t* b) {
    asm volatile("mma.sync.aligned.m16n8k16.row.col.f32.f16.f16.f32 "
        "{%0,%1,%2,%3}, {%4,%5,%6,%7}, {%8,%9}, {%0,%1,%2,%3};"
        : "+f"(c[0]), "+f"(c[1]), "+f"(c[2]), "+f"(c[3])
        : "r"(a[0]), "r"(a[1]), "r"(a[2]), "r"(a[3]), "r"(b[0]), "r"(b[1]));
}

// ================= prep: weight conversions ==============================
__global__ __launch_bounds__(256) void k_cvt_w(const float* __restrict__ w_out) {
    int idx = blockIdx.x * 256 + threadIdx.x;   // NC*KK
    int o = idx / KK, r = idx - o * KK;
    int tap = r >> 10, c = r & 1023;
    g_wf[idx] = __float2half(w_out[o * KK + c * 9 + tap]);
}
__global__ __launch_bounds__(256) void k_cvt_wctx(const float* __restrict__ w_ctx) {
    int idx = blockIdx.x * 256 + threadIdx.x;   // NC*CTX
    float v = w_ctx[idx];
    __nv_bfloat16 h = __float2bfloat16(v);
    g_wch[idx] = h;
    g_wcl[idx] = __float2bfloat16(v - __bfloat162float(h));
}

// ============ fp16 conv: v = w_out (*) ctx + b_out =======================
// grid 128 = 32 imgs x (2 M-tiles of 160) x (2 N-tiles of 128). 256 thr.
// 8 warps as 2(m) x 4(n); warp tile 80x32 (5 m-frags x 4 n-frags).
// fp16 operands, fp32 accum. K-chunks of 128 (72 chunks), double buffer.
// Rows padded to 136 fp16 = 272B = 68 u32: bank = (4*row + kb) % 32.
#define CV_B_OFF 43520               // A = 160*272
#define CV_BUF   78336               // + B = 128*272
#define CV_SMEM  (2 * CV_BUF)
#define CV_NCH   72

__global__ void __launch_bounds__(256, 1) k_conv(const float* __restrict__ bias) {
    extern __shared__ char smem[];
    uint32_t sb = smem_u32(smem);
    int tid = threadIdx.x;
    int bimg = blockIdx.x >> 2;
    int tt = blockIdx.x & 3;
    int mbase = (tt >> 1) * 160;
    int pbase = (tt & 1) * 128;
    const __half* Bsrc = g_cxf + (size_t)bimg * (NP * CTX);

    auto load_chunk = [&](int buf, int ch) {
        uint32_t base = sb + buf * CV_BUF;
        int tap = ch >> 3, c0 = (ch & 7) << 7;
        int t3 = tap / 3;
        int dy = t3 - 1, dx = tap - t3 * 3 - 1;
        #pragma unroll
        for (int r = 0; r < 10; r++) {
            int id = r * 256 + tid;
            int row = id >> 4, v = id & 15;
            size_t so = (size_t)(mbase + row) * KK + tap * 1024 + c0 + v * 8;
            CP16(base + (uint32_t)(row * 272 + v * 16), g_wf + so, 16);
        }
        #pragma unroll
        for (int r = 0; r < 8; r++) {
            int id = r * 256 + tid;
            int row = id >> 4, v = id & 15;
            int p = pbase + row;
            int yy = (p >> 4) + dy, xx = (p & 15) + dx;
            int ok = ((unsigned)yy < 16u && (unsigned)xx < 16u) ? 16 : 0;
            size_t so = ok ? ((size_t)(yy * 16 + xx) * CTX + c0 + v * 8) : 0;
            CP16(base + CV_B_OFF + (uint32_t)(row * 272 + v * 16), Bsrc + so, ok);
        }
    };

    int w = tid >> 5, l = tid & 31;
    int wm = w >> 2;        // 0..1: m offset 80
    int wn = w & 3;         // 0..3: n offset 32
    int g = l >> 2, tg = l & 3;

    float acc[5][4][4];
    #pragma unroll
    for (int f = 0; f < 5; f++)
        #pragma unroll
        for (int j = 0; j < 4; j++)
            #pragma unroll
            for (int q = 0; q < 4; q++) acc[f][j][q] = 0.f;

    auto compute = [&](int buf) {
        const uint32_t* pA = (const uint32_t*)(smem + buf * CV_BUF);
        const uint32_t* pB = (const uint32_t*)(smem + buf * CV_BUF + CV_B_OFF);
        #pragma unroll
        for (int s = 0; s < 8; s++) {
            int kb = s * 8 + tg;
            uint32_t ah[5][4];
            #pragma unroll
            for (int f = 0; f < 5; f++) {
                int r0 = (wm * 80 + f * 16 + g) * 68;
                int r8 = r0 + 8 * 68;
                ah[f][0] = pA[r0 + kb];     ah[f][1] = pA[r8 + kb];
                ah[f][2] = pA[r0 + kb + 4]; ah[f][3] = pA[r8 + kb + 4];
            }
            #pragma unroll
            for (int j = 0; j < 4; j++) {
                int n = (wn * 32 + j * 8 + g) * 68;
                uint32_t bh[2] = { pB[n + kb], pB[n + kb + 4] };
                #pragma unroll
                for (int f = 0; f < 5; f++)
                    mma_f16(acc[f][j], ah[f], bh);
            }
        }
    };

    load_chunk(0, 0);
    CP_COMMIT();
    for (int ch = 0; ch < CV_NCH; ch++) {
        if (ch + 1 < CV_NCH) {
            load_chunk((ch + 1) & 1, ch + 1);
            CP_COMMIT();
            CP_WAIT(1);
        } else {
            CP_WAIT(0);
        }
        __syncthreads();
        compute(ch & 1);
        __syncthreads();
    }

    float* dst = g_v + (size_t)bimg * (NC * NP);
    #pragma unroll
    for (int f = 0; f < 5; f++) {
        int o0 = mbase + wm * 80 + f * 16 + g;
        int o1 = o0 + 8;
        float b0 = bias[o0], b1 = bias[o1];
        #pragma unroll
        for (int j = 0; j < 4; j++) {
            int p = pbase + wn * 32 + j * 8 + tg * 2;
            *(float2*)(dst + (size_t)o0 * NP + p)
                = make_float2(acc[f][j][0] + b0, acc[f][j][1] + b0);
            *(float2*)(dst + (size_t)o1 * NP + p)
                = make_float2(acc[f][j][2] + b1, acc[f][j][3] + b1);
        }
    }
}

// ===== k projection (3xBF16 split, high accuracy): k = w_ctx @ kmap ======
// 8 warps as 2(m) x 4(n); warp tile 80x32.
#define SA_LD 23040
#define SB_LD 18432
#define SB_OFF 46080
#define BUFSTRIDE 82944
#define KP_SMEM (2 * BUFSTRIDE)

__global__ void __launch_bounds__(256, 1) k_kproj(const float* __restrict__ bias) {
    const int NCH = 16;
    extern __shared__ char smem[];
    uint32_t sb = smem_u32(smem);
    int tid = threadIdx.x;
    int bimg = blockIdx.x >> 2;
    int tt = blockIdx.x & 3;
    int mbase = (tt >> 1) * 160;
    int pbase = (tt & 1) * 128;

    const __nv_bfloat16* Bh = g_kmh + (size_t)bimg * (NP * CTX);
    const __nv_bfloat16* Bl = g_kml + (size_t)bimg * (NP * CTX);

    auto load_chunk = [&](int buf, int ch) {
        uint32_t base = sb + buf * BUFSTRIDE;
        int c0 = ch << 6;
        #pragma unroll
        for (int r = 0; r < 5; r++) {
            int id = r * 256 + tid;
            int row = id >> 3, v = id & 7;
            size_t so = (size_t)(mbase + row) * CTX + c0 + v * 8;
            uint32_t dst = base + (uint32_t)(row * 144 + v * 16);
            CP16(dst, g_wch + so, 16);
            CP16(dst + SA_LD, g_wcl + so, 16);
        }
        #pragma unroll
        for (int r = 0; r < 4; r++) {
            int id = r * 256 + tid;
            int row = id >> 3, v = id & 7;
            size_t so = (size_t)(pbase + row) * CTX + c0 + v * 8;
            uint32_t dst = base + SB_OFF + (uint32_t)(row * 144 + v * 16);
            CP16(dst, Bh + so, 16);
            CP16(dst + SB_LD, Bl + so, 16);
        }
    };

    int w = tid >> 5, l = tid & 31;
    int wm = w >> 2;
    int wn = w & 3;
    int g = l >> 2, tg = l & 3;

    float acc[5][4][4];
    #pragma unroll
    for (int f = 0; f < 5; f++)
        #pragma unroll
        for (int j = 0; j < 4; j++)
            #pragma unroll
            for (int q = 0; q < 4; q++) acc[f][j][q] = 0.f;

    auto compute = [&](int buf) {
        const uint32_t* pAh = (const uint32_t*)(smem + buf * BUFSTRIDE);
        const uint32_t* pAl = (const uint32_t*)(smem + buf * BUFSTRIDE + SA_LD);
        const uint32_t* pBh = (const uint32_t*)(smem + buf * BUFSTRIDE + SB_OFF);
        const uint32_t* pBl = (const uint32_t*)(smem + buf * BUFSTRIDE + SB_OFF + SB_LD);
        #pragma unroll
        for (int s = 0; s < 4; s++) {
            int kb = s * 8 + tg;
            uint32_t ah[5][4], al[5][4];
            #pragma unroll
            for (int f = 0; f < 5; f++) {
                int r0 = (wm * 80 + f * 16 + g) * 36;
                int r8 = r0 + 8 * 36;
                ah[f][0] = pAh[r0 + kb];     ah[f][1] = pAh[r8 + kb];
                ah[f][2] = pAh[r0 + kb + 4]; ah[f][3] = pAh[r8 + kb + 4];
                al[f][0] = pAl[r0 + kb];     al[f][1] = pAl[r8 + kb];
                al[f][2] = pAl[r0 + kb + 4]; al[f][3] = pAl[r8 + kb + 4];
            }
            #pragma unroll
            for (int j = 0; j < 4; j++) {
                int n = (wn * 32 + j * 8 + g) * 36;
                uint32_t bh[2] = { pBh[n + kb], pBh[n + kb + 4] };
                uint32_t bl[2] = { pBl[n + kb], pBl[n + kb + 4] };
                #pragma unroll
                for (int f = 0; f < 5; f++) {
                    mma_bf16(acc[f][j], ah[f], bh);
                    mma_bf16(acc[f][j], ah[f], bl);
                    mma_bf16(acc[f][j], al[f], bh);
                }
            }
        }
    };

    load_chunk(0, 0);
    CP_COMMIT();
    for (int ch = 0; ch < NCH; ch++) {
        if (ch + 1 < NCH) {
            load_chunk((ch + 1) & 1, ch + 1);
            CP_COMMIT();
            CP_WAIT(1);
        } else {
            CP_WAIT(0);
        }
        __syncthreads();
        compute(ch & 1);
        __syncthreads();
    }

    float* dst = g_k + (size_t)bimg * (NC * NP);
    #pragma unroll
    for (int f = 0; f < 5; f++) {
        int o0 = mbase + wm * 80 + f * 16 + g;
        int o1 = o0 + 8;
        float b0 = bias[o0], b1 = bias[o1];
        #pragma unroll
        for (int j = 0; j < 4; j++) {
            int p = pbase + wn * 32 + j * 8 + tg * 2;
            *(float2*)(dst + (size_t)o0 * NP + p)
                = make_float2(acc[f][j][0] + b0, acc[f][j][1] + b0);
            *(float2*)(dst + (size_t)o1 * NP + p)
                = make_float2(acc[f][j][2] + b1, acc[f][j][3] + b1);
        }
    }
}

// ====== kernel 1: ctx group norm + fp16 raw + bf16 hi/lo normed =========
__global__ __launch_bounds__(256) void k_ctx(const float* __restrict__ context,
                                             const float* __restrict__ cn_g,
                                             const float* __restrict__ cn_b) {
    int b = blockIdx.x >> 5, g = blockIdx.x & 31;
    __shared__ float s[32 * 257];
    __shared__ float redA[8], redB[8];
    __shared__ float stats[2];
    const float* src = context + (size_t)b * (NP * CTX) + g * 32;
    float sum = 0.f, sq = 0.f;
    for (int i = threadIdx.x; i < 8192; i += 256) {
        int cl = i & 31, p = i >> 5;
        float v = src[(size_t)p * CTX + cl];
        s[cl * 257 + p] = v;
        sum += v; sq += v * v;
    }
    #pragma unroll
    for (int off = 16; off; off >>= 1) {
        sum += __shfl_down_sync(0xffffffffu, sum, off);
        sq  += __shfl_down_sync(0xffffffffu, sq,  off);
    }
    if ((threadIdx.x & 31) == 0) { redA[threadIdx.x >> 5] = sum; redB[threadIdx.x >> 5] = sq; }
    __syncthreads();
    if (threadIdx.x == 0) {
        float a = 0.f, b2 = 0.f;
        #pragma unroll
        for (int w = 0; w < 8; w++) { a += redA[w]; b2 += redB[w]; }
        float mean = a * (1.f / 8192.f);
        float var  = b2 * (1.f / 8192.f) - mean * mean;
        stats[0] = mean; stats[1] = rsqrtf(var + 1e-6f);
    }
    __syncthreads();
    float mean = stats[0], rstd = stats[1];
    int cl = threadIdx.x & 31;
    int c = g * 32 + cl;
    float gam = cn_g[c] * rstd, bet = cn_b[c];
    for (int i = threadIdx.x; i < 8192; i += 256) {
        int p = i >> 5;
        float v = s[cl * 257 + p];
        size_t o = ((size_t)b * NP + p) * CTX + c;
        g_cxf[o] = __float2half(v);
        float nv = (v - mean) * gam + bet;
        __nv_bfloat16 nh = __float2bfloat16(nv);
        g_kmh[o] = nh;
        g_kml[o] = __float2bfloat16(nv - __bfloat162float(nh));
    }
}

// ================= kernel 2a: roi bilinear samples ======================
__global__ __launch_bounds__(256) void k_roi(const float* __restrict__ gx,
                                             const float* __restrict__ bbox,
                                             const float* __restrict__ indicator) {
    int idx = blockIdx.x * 256 + threadIdx.x;
    if (idx >= NB * XNC * NI) return;
    int b = idx / (XNC * NI);
    int r = idx - b * (XNC * NI);
    int c = r / NI;
    int i = r - c * NI;
    float out;
    if (c >= NC) {
        out = indicator[b * 2 + (c - NC)];
    } else {
        float x1 = bbox[b * 4 + 0], y1 = bbox[b * 4 + 1];
        float x2 = bbox[b * 4 + 2], y2 = bbox[b * 4 + 3];
        float rw = fmaxf(x2 - x1, 1.0f), rh = fmaxf(y2 - y1, 1.0f);
        int iy = i / 9, ix = i - iy * 9;
        float xs = x1 + ((float)ix + 0.5f) * (rw * (1.f / 9.f));
        float ys = y1 + ((float)iy + 0.5f) * (rh * (1.f / 9.f));
        float yv = fminf(fmaxf(ys, 0.f), 63.f);
        float xv = fminf(fmaxf(xs, 0.f), 63.f);
        int y0 = (int)floorf(yv), x0 = (int)floorf(xv);
        int y1i = min(y0 + 1, 63), x1i = min(x0 + 1, 63);
        float ly = yv - (float)y0, lx = xv - (float)x0;
        const float* im = gx + (size_t)b * (NC * HH * WW) + (size_t)c * (HH * WW);
        float g00 = im[y0 * WW + x0],  g01 = im[y0 * WW + x1i];
        float g10 = im[y1i * WW + x0], g11 = im[y1i * WW + x1i];
        out = g00 * (1.f - ly) * (1.f - lx) + g01 * (1.f - ly) * lx
            + g10 * ly * (1.f - lx)        + g11 * ly * lx;
    }
    g_xn[idx] = out;
}

// ============ kernel 2b: group norm over roi features ====================
__global__ __launch_bounds__(256) void k_gn_roi(const float* __restrict__ ln_g,
                                                const float* __restrict__ ln_b) {
    int b = blockIdx.x >> 5, g = blockIdx.x & 31;
    float* base = g_xn + (size_t)b * (XNC * NI) + g * 810;
    __shared__ float s[810];
    __shared__ float redA[8], redB[8];
    __shared__ float stats[2];
    float sum = 0.f, sq = 0.f;
    for (int i = threadIdx.x; i < 810; i += 256) {
        float v = base[i];
        s[i] = v; sum += v; sq += v * v;
    }
    #pragma unroll
    for (int off = 16; off; off >>= 1) {
        sum += __shfl_down_sync(0xffffffffu, sum, off);
        sq  += __shfl_down_sync(0xffffffffu, sq,  off);
    }
    if ((threadIdx.x & 31) == 0) { redA[threadIdx.x >> 5] = sum; redB[threadIdx.x >> 5] = sq; }
    __syncthreads();
    if (threadIdx.x == 0) {
        float a = 0.f, b2 = 0.f;
        #pragma unroll
        for (int w = 0; w < 8; w++) { a += redA[w]; b2 += redB[w]; }
        float mean = a * (1.f / 810.f);
        float var  = b2 * (1.f / 810.f) - mean * mean;
        stats[0] = mean; stats[1] = rsqrtf(var + 1e-6f);
    }
    __syncthreads();
    float mean = stats[0], rstd = stats[1];
    for (int i = threadIdx.x; i < 810; i += 256) {
        int c = g * 10 + i / 81;
        base[i] = (s[i] - mean) * rstd * ln_g[c] + ln_b[c];
    }
}

// ================= q projection SGEMM (FFMA, fp32-exact path) ===========
__global__ __launch_bounds__(256) void k_gemm_q(const float* __restrict__ A,
                                                const float* __restrict__ bias) {
    const int K = 322;
    __shared__ float sA[16][68];
    __shared__ float sB[16][128];
    int tid = threadIdx.x;
    int b = blockIdx.x;
    int mbase = blockIdx.y * 64;

    float acc[4][8];
    #pragma unroll
    for (int x = 0; x < 4; x++)
        #pragma unroll
        for (int y = 0; y < 8; y++) acc[x][y] = 0.f;

    int am = tid >> 2;
    int ak = (tid & 3) * 4;
    int bk = tid >> 4;
    int bn = (tid & 15) * 8;
    int tm = tid >> 4, tn = tid & 15;

    const float* abase = A + (size_t)(mbase + am) * K + ak;

    for (int k0 = 0; k0 < K; k0 += 16) {
        #pragma unroll
        for (int j = 0; j < 4; j++) {
            float v = 0.f;
            if (k0 + ak + j < 322) v = abase[k0 + j];
            sA[ak + j][am] = v;
        }
        int kk = k0 + bk;
        const float* bp = g_xn + (size_t)b * (XNC * NI) + (size_t)kk * NI;
        bool kok = kk < 322;
        #pragma unroll
        for (int j = 0; j < 8; j++) {
            int n = bn + j;
            sB[bk][bn + j] = (kok && n < NI) ? bp[n] : 0.f;
        }
        __syncthreads();
        #pragma unroll
        for (int k = 0; k < 16; k++) {
            float4 a4 = *(const float4*)&sA[k][tm * 4];
            float4 b0 = *(const float4*)&sB[k][tn * 8];
            float4 b1 = *(const float4*)&sB[k][tn * 8 + 4];
            float a[4]  = {a4.x, a4.y, a4.z, a4.w};
            float bb[8] = {b0.x, b0.y, b0.z, b0.w, b1.x, b1.y, b1.z, b1.w};
            #pragma unroll
            for (int x = 0; x < 4; x++)
                #pragma unroll
                for (int y = 0; y < 8; y++)
                    acc[x][y] = fmaf(a[x], bb[y], acc[x][y]);
        }
        __syncthreads();
    }
    #pragma unroll
    for (int x = 0; x < 4; x++) {
        int o = mbase + tm * 4 + x;
        float bs = bias[o];
        #pragma unroll
        for (int y = 0; y < 8; y++) {
            int n = tn * 8 + y;
            if (n < NI) g_q[(size_t)b * (NC * NI) + (size_t)o * NI + n] = acc[x][y] + bs;
        }
    }
}

// ======== kernel: sim = q^T k (81x64 per block, K=320), grid (32,4) ======
__global__ __launch_bounds__(256) void k_sim() {
    int b = blockIdx.x;
    int pb = blockIdx.y * 64;
    __shared__ float sq[8][96];
    __shared__ float sk[8][64];
    int tid = threadIdx.x;
    int ti = tid >> 4;
    int tp = tid & 15;
    float acc[6][4];
    #pragma unroll
    for (int x = 0; x < 6; x++)
        #pragma unroll
        for (int y = 0; y < 4; y++) acc[x][y] = 0.f;

    for (int o0 = 0; o0 < NC; o0 += 8) {
        for (int idx = tid; idx < 8 * NI; idx += 256) {
            int ko = idx / NI, i = idx - ko * NI;
            sq[ko][i] = g_q[(size_t)b * (NC * NI) + (size_t)(o0 + ko) * NI + i];
        }
        {
            int ko = tid >> 5;
            int pp = (tid & 31) * 2;
            *(float2*)&sk[ko][pp] = *(const float2*)(g_k + (size_t)b * (NC * NP)
                                       + (size_t)(o0 + ko) * NP + pb + pp);
        }
        __syncthreads();
        #pragma unroll
        for (int ko = 0; ko < 8; ko++) {
            float a[6];
            #pragma unroll
            for (int x = 0; x < 6; x++) a[x] = sq[ko][ti * 6 + x];
            float4 b0 = *(const float4*)&sk[ko][tp * 4];
            float bb[4] = {b0.x, b0.y, b0.z, b0.w};
            #pragma unroll
            for (int x = 0; x < 6; x++)
                #pragma unroll
                for (int y = 0; y < 4; y++)
                    acc[x][y] = fmaf(a[x], bb[y], acc[x][y]);
        }
        __syncthreads();
    }
    #pragma unroll
    for (int x = 0; x < 6; x++) {
        int i = ti * 6 + x;
        if (i < NI) {
            #pragma unroll
            for (int y = 0; y < 4; y++)
                g_sim[(size_t)b * (NI * NP) + (size_t)i * NP + pb + tp * 4 + y] = acc[x][y];
        }
    }
}

// ================= kernel: softmax rows -> attn ==========================
__global__ __launch_bounds__(256) void k_softmax(float* __restrict__ attn_out) {
    int b = blockIdx.x / NI, i = blockIdx.x - b * NI;
    int t = threadIdx.x;
    __shared__ float red[8];
    __shared__ float bc[1];
    float v = g_sim[(size_t)b * (NI * NP) + (size_t)i * NP + t];
    float m = v;
    #pragma unroll
    for (int off = 16; off; off >>= 1) m = fmaxf(m, __shfl_xor_sync(0xffffffffu, m, off));
    if ((t & 31) == 0) red[t >> 5] = m;
    __syncthreads();
    if (t == 0) {
        float mm = red[0];
        #pragma unroll
        for (int w = 1; w < 8; w++) mm = fmaxf(mm, red[w]);
        bc[0] = mm;
    }
    __syncthreads();
    float e = expf(v - bc[0]);
    float s = e;
    #pragma unroll
    for (int off = 16; off; off >>= 1) s += __shfl_xor_sync(0xffffffffu, s, off);
    if ((t & 31) == 0) red[t >> 5] = s;
    __syncthreads();
    if (t == 0) {
        float ss = 0.f;
        #pragma unroll
        for (int w = 0; w < 8; w++) ss += red[w];
        bc[0] = 1.f / ss;
    }
    __syncthreads();
    attn_out[(size_t)b * (NI * NP) + (size_t)i * NP + t] = e * bc[0];
}

// ================= kernel: xo = v_t @ attn^T (320x81, K=256) =============
__global__ __launch_bounds__(256) void k_xo(const float* __restrict__ attn) {
    int b = blockIdx.x;
    int mbase = blockIdx.y * 64;
    __shared__ float sv[16][68];
    __shared__ float sa[16][96];
    int tid = threadIdx.x;
    int am = tid >> 2, ak = (tid & 3) * 4;
    int tm = tid >> 4, tn = tid & 15;
    float acc[4][6];
    #pragma unroll
    for (int x = 0; x < 4; x++)
        #pragma unroll
        for (int y = 0; y < 6; y++) acc[x][y] = 0.f;

    for (int p0 = 0; p0 < NP; p0 += 16) {
        float4 v4 = *(const float4*)(g_v + (size_t)b * (NC * NP)
                                     + (size_t)(mbase + am) * NP + p0 + ak);
        sv[ak + 0][am] = v4.x; sv[ak + 1][am] = v4.y;
        sv[ak + 2][am] = v4.z; sv[ak + 3][am] = v4.w;
        for (int idx = tid; idx < 16 * NI; idx += 256) {
            int ii = idx >> 4, pp = idx & 15;
            sa[pp][ii] = attn[(size_t)b * (NI * NP) + (size_t)ii * NP + p0 + pp];
        }
        __syncthreads();
        #pragma unroll
        for (int p = 0; p < 16; p++) {
            float4 a4 = *(const float4*)&sv[p][tm * 4];
            float a[4] = {a4.x, a4.y, a4.z, a4.w};
            float bb[6];
            #pragma unroll
            for (int y = 0; y < 6; y++) bb[y] = sa[p][tn * 6 + y];
            #pragma unroll
            for (int x = 0; x < 4; x++)
                #pragma unroll
                for (int y = 0; y < 6; y++)
                    acc[x][y] = fmaf(a[x], bb[y], acc[x][y]);
        }
        __syncthreads();
    }
    #pragma unroll
    for (int x = 0; x < 4; x++) {
        int o = mbase + tm * 4 + x;
        #pragma unroll
        for (int y = 0; y < 6; y++) {
            int i = tn * 6 + y;
            if (i < NI) g_xo[(size_t)b * (NC * NI) + (size_t)o * NI + i] = acc[x][y];
        }
    }
}

// ========== kernel: residual + masked scatter (float4) ===================
__global__ __launch_bounds__(256) void k_out(const float* __restrict__ gx,
                                             const float* __restrict__ bbox,
                                             float* __restrict__ out) {
    int t = blockIdx.x * 256 + threadIdx.x;   // handles 4 consecutive x
    int base = t * 4;
    int x0 = base & 63;
    int y = (base >> 6) & 63;
    int bc = base >> 12;
    int b = bc / NC;
    int c = bc - b * NC;
    float4 val = *(const float4*)(gx + base);
    int bx1 = (int)(bbox[b * 4 + 0] * 64.f);
    int by1 = (int)(bbox[b * 4 + 1] * 64.f);
    int bx2 = max((int)(bbox[b * 4 + 2] * 64.f), bx1 + 1);
    int by2 = max((int)(bbox[b * 4 + 3] * 64.f), by1 + 1);
    if (y >= by1 && y < by2) {
        int sy = min(max((y - by1) * 9 / (by2 - by1), 0), 8);
        const float* xrow = g_xo + (size_t)b * (NC * NI) + (size_t)c * NI + sy * 9;
        float* vp = &val.x;
        #pragma unroll
        for (int j = 0; j < 4; j++) {
            int x = x0 + j;
            if (x >= bx1 && x < bx2) {
                int sx = min(max((x - bx1) * 9 / (bx2 - bx1), 0), 8);
                vp[j] += xrow[sx];
            }
        }
    }
    *(float4*)(out + base) = val;
}

// ============================ launch ======================================
extern "C" void kernel_launch(void* const* d_in, const int* in_sizes, int n_in,
                              void* d_out, int out_size) {
    const float* global_x  = (const float*)d_in[0];
    const float* context   = (const float*)d_in[1];
    const float* indicator = (const float*)d_in[2];
    const float* bbox      = (const float*)d_in[3];
    const float* ln_g      = (const float*)d_in[4];
    const float* ln_b      = (const float*)d_in[5];
    const float* cn_g      = (const float*)d_in[6];
    const float* cn_b      = (const float*)d_in[7];
    const float* w_in      = (const float*)d_in[8];
    const float* b_in      = (const float*)d_in[9];
    const float* w_ctx     = (const float*)d_in[10];
    const float* b_ctx     = (const float*)d_in[11];
    const float* w_out     = (const float*)d_in[12];
    const float* b_out     = (const float*)d_in[13];
    float* out  = (float*)d_out;
    float* attn = out + OUT_ATTN_OFF;

    static cudaStream_t s2 = nullptr, s3 = nullptr;
    static cudaEvent_t ev_fork = nullptr, ev_q = nullptr;
    static cudaEvent_t ev_ctx = nullptr, ev_wctx = nullptr, ev_conv = nullptr;
    static bool init_done = false;
    if (!init_done) {
        cudaFuncSetAttribute(k_conv, cudaFuncAttributeMaxDynamicSharedMemorySize,
                             CV_SMEM);
        cudaFuncSetAttribute(k_kproj, cudaFuncAttributeMaxDynamicSharedMemorySize,
                             KP_SMEM);
        cudaStreamCreateWithFlags(&s2, cudaStreamNonBlocking);
        cudaStreamCreateWithFlags(&s3, cudaStreamNonBlocking);
        cudaEventCreateWithFlags(&ev_fork, cudaEventDisableTiming);
        cudaEventCreateWithFlags(&ev_q,    cudaEventDisableTiming);
        cudaEventCreateWithFlags(&ev_ctx,  cudaEventDisableTiming);
        cudaEventCreateWithFlags(&ev_wctx, cudaEventDisableTiming);
        cudaEventCreateWithFlags(&ev_conv, cudaEventDisableTiming);
        init_done = true;
    }

    cudaEventRecord(ev_fork, 0);
    cudaStreamWaitEvent(s2, ev_fork, 0);
    cudaStreamWaitEvent(s3, ev_fork, 0);

    // s2: independent roi -> groupnorm -> q chain
    k_roi<<<(NB * XNC * NI + 255) / 256, 256, 0, s2>>>(global_x, bbox, indicator);
    k_gn_roi<<<NB * 32, 256, 0, s2>>>(ln_g, ln_b);
    k_gemm_q<<<dim3(32, 5), 256, 0, s2>>>(w_in, b_in);
    cudaEventRecord(ev_q, s2);

    // s3: weight conversions (overlap with k_ctx), then conv after ctx ready
    k_cvt_wctx<<<(NC * CTX) / 256, 256, 0, s3>>>(w_ctx);
    cudaEventRecord(ev_wctx, s3);
    k_cvt_w<<<(NC * KK) / 256, 256, 0, s3>>>(w_out);

    // default: context groupnorm + splits
    k_ctx<<<NB * 32, 256>>>(context, cn_g, cn_b);
    cudaEventRecord(ev_ctx, 0);

    // s3: conv (needs g_cxf from k_ctx + g_wf from cvt_w)
    cudaStreamWaitEvent(s3, ev_ctx, 0);
    k_conv<<<128, 256, CV_SMEM, s3>>>(b_out);
    cudaEventRecord(ev_conv, s3);

    // default: k projection (needs kmap from k_ctx + wch/wcl from cvt_wctx)
    cudaStreamWaitEvent(0, ev_wctx, 0);
    k_kproj<<<128, 256, KP_SMEM>>>(b_ctx);

    // attention tail on default
    cudaStreamWaitEvent(0, ev_q, 0);
    k_sim<<<dim3(NB, 4), 256>>>();
    k_softmax<<<NB * NI, 256>>>(attn);
    cudaStreamWaitEvent(0, ev_conv, 0);
    k_xo<<<dim3(NB, 5), 256>>>(attn);
    k_out<<<(NB * NC * HH * WW) / 1024, 256>>>(global_x, bbox, out);
}

// round 13
// speedup vs baseline: 8.6155x; 1.0103x over previous
#include <cuda_runtime.h>
#include <cuda_bf16.h>
#include <cuda_fp16.h>
#include <math.h>
#include <stdint.h>

// ---------------- problem constants ----------------
#define NB   32
#define NC   320
#define HH   64
#define WW   64
#define CTX  1024
#define NP   256      // 16x16 ctx spatial
#define NI   81       // 9x9 roi points
#define XNC  322      // 320 + 2 indicator channels
#define KK   9216     // conv GEMM K = 1024*9
#define OUT_ATTN_OFF 41943040  // 32*320*64*64

// ---------------- device scratch (static, no allocation) ----------------
__device__ float g_xn   [NB * XNC * NI];    // roi features [b][c][i]
__device__ float g_q    [NB * NC * NI];
__device__ float g_k    [NB * NC * NP];
__device__ float g_v    [NB * NC * NP];
__device__ float g_sim  [NB * NI * NP];
__device__ float g_xo   [NB * NC * NI];
// fp16 operands for conv (single MMA, fp32 accumulate)
__device__ __align__(16) __half g_cxf[NB * NP * CTX];         // raw context fp16 [b][p][c]
__device__ __align__(16) __half g_wf [NC * KK];               // w_out fp16 [o][tap*1024+c]
// bf16 hi/lo split operands for k projection (3x split, high accuracy)
__device__ __align__(16) __nv_bfloat16 g_kmh[NB * NP * CTX];  // normed ctx hi [b][p][c]
__device__ __align__(16) __nv_bfloat16 g_kml[NB * NP * CTX];  // normed ctx lo
__device__ __align__(16) __nv_bfloat16 g_wch[NC * CTX];       // w_ctx hi [o][c]
__device__ __align__(16) __nv_bfloat16 g_wcl[NC * CTX];       // w_ctx lo

// =================== helpers (baseline PTX only) ========================
__device__ __forceinline__ uint32_t smem_u32(const void* p) {
    uint32_t a;
    asm("{ .reg .u64 t; cvta.to.shared.u64 t, %1; cvt.u32.u64 %0, t; }" : "=r"(a) : "l"(p));
    return a;
}
#define CP16(dst, src, sz) \
    asm volatile("cp.async.ca.shared.global [%0], [%1], 16, %2;" \
                 :: "r"(dst), "l"(src), "r"(sz))
#define CP_COMMIT() asm volatile("cp.async.commit_group;" ::: "memory")
#define CP_WAIT(n)  asm volatile("cp.async.wait_group %0;" :: "n"(n) : "memory")

__device__ __forceinline__ void ldm_x4(uint32_t* r, uint32_t addr) {
    asm volatile("ldmatrix.sync.aligned.m8n8.x4.shared.b16 {%0,%1,%2,%3}, [%4];"
        : "=r"(r[0]), "=r"(r[1]), "=r"(r[2]), "=r"(r[3]) : "r"(addr));
}
__device__ __forceinline__ void mma_bf16(float* c, const uint32_t* a, const uint32_t* b) {
    asm volatile("mma.sync.aligned.m16n8k16.row.col.f32.bf16.bf16.f32 "
        "{%0,%1,%2,%3}, {%4,%5,%6,%7}, {%8,%9}, {%0,%1,%2,%3};"
        : "+f"(c[0]), "+f"(c[1]), "+f"(c[2]), "+f"(c[3])
        : "r"(a[0]), "r"(a[1]), "r"(a[2]), "r"(a[3]), "r"(b[0]), "r"(b[1]));
}
__device__ __forceinline__ void mma_f16(float* c, const uint32_t* a, const uint32_t* b) {
    asm volatile("mma.sync.aligned.m16n8k16.row.col.f32.f16.f16.f32 "
        "{%0,%1,%2,%3}, {%4,%5,%6,%7}, {%8,%9}, {%0,%1,%2,%3};"
        : "+f"(c[0]), "+f"(c[1]), "+f"(c[2]), "+f"(c[3])
        : "r"(a[0]), "r"(a[1]), "r"(a[2]), "r"(a[3]), "r"(b[0]), "r"(b[1]));
}

// ================= prep: weight conversions ==============================
__global__ __launch_bounds__(256) void k_cvt_w(const float* __restrict__ w_out) {
    int idx = blockIdx.x * 256 + threadIdx.x;   // NC*KK
    int o = idx / KK, r = idx - o * KK;
    int tap = r >> 10, c = r & 1023;
    g_wf[idx] = __float2half(w_out[o * KK + c * 9 + tap]);
}
__global__ __launch_bounds__(256) void k_cvt_wctx(const float* __restrict__ w_ctx) {
    int idx = blockIdx.x * 256 + threadIdx.x;   // NC*CTX
    float v = w_ctx[idx];
    __nv_bfloat16 h = __float2bfloat16(v);
    g_wch[idx] = h;
    g_wcl[idx] = __float2bfloat16(v - __bfloat162float(h));
}

// ============ fp16 conv: v = w_out (*) ctx + b_out =======================
// grid 128 = 32 imgs x (2 M-tiles of 160) x (2 N-tiles of 128). 256 thr.
// 8 warps as 2(m) x 4(n); warp tile 80x32. ldmatrix fragment loads.
// Rows padded to 136 fp16 = 272B = 68 u32: conflict-free (stride ≡4 mod 32).
#define CV_B_OFF 43520               // A = 160*272
#define CV_BUF   78336               // + B = 128*272
#define CV_SMEM  (2 * CV_BUF)
#define CV_NCH   72

__global__ void __launch_bounds__(256, 1) k_conv(const float* __restrict__ bias) {
    extern __shared__ char smem[];
    uint32_t sb = smem_u32(smem);
    int tid = threadIdx.x;
    int bimg = blockIdx.x >> 2;
    int tt = blockIdx.x & 3;
    int mbase = (tt >> 1) * 160;
    int pbase = (tt & 1) * 128;
    const __half* Bsrc = g_cxf + (size_t)bimg * (NP * CTX);

    auto load_chunk = [&](int buf, int ch) {
        uint32_t base = sb + buf * CV_BUF;
        int tap = ch >> 3, c0 = (ch & 7) << 7;
        int t3 = tap / 3;
        int dy = t3 - 1, dx = tap - t3 * 3 - 1;
        #pragma unroll
        for (int r = 0; r < 10; r++) {
            int id = r * 256 + tid;
            int row = id >> 4, v = id & 15;
            size_t so = (size_t)(mbase + row) * KK + tap * 1024 + c0 + v * 8;
            CP16(base + (uint32_t)(row * 272 + v * 16), g_wf + so, 16);
        }
        #pragma unroll
        for (int r = 0; r < 8; r++) {
            int id = r * 256 + tid;
            int row = id >> 4, v = id & 15;
            int p = pbase + row;
            int yy = (p >> 4) + dy, xx = (p & 15) + dx;
            int ok = ((unsigned)yy < 16u && (unsigned)xx < 16u) ? 16 : 0;
            size_t so = ok ? ((size_t)(yy * 16 + xx) * CTX + c0 + v * 8) : 0;
            CP16(base + CV_B_OFF + (uint32_t)(row * 272 + v * 16), Bsrc + so, ok);
        }
    };

    int w = tid >> 5, l = tid & 31;
    int wm = w >> 2;        // 0..1: m offset 80
    int wn = w & 3;         // 0..3: n offset 32
    int g = l >> 2, tg = l & 3;
    int lrow = l & 15;              // row within 16-row ldmatrix group
    int lcol = (l >> 4) * 16;       // k-half byte offset (0 / 16)

    float acc[5][4][4];
    #pragma unroll
    for (int f = 0; f < 5; f++)
        #pragma unroll
        for (int j = 0; j < 4; j++)
            #pragma unroll
            for (int q = 0; q < 4; q++) acc[f][j][q] = 0.f;

    auto compute = [&](int buf) {
        uint32_t ab = sb + buf * CV_BUF
                    + (uint32_t)((wm * 80 + lrow) * 272 + lcol);
        uint32_t bb = sb + buf * CV_BUF + CV_B_OFF
                    + (uint32_t)((wn * 32 + lrow) * 272 + lcol);
        #pragma unroll
        for (int s = 0; s < 8; s++) {
            uint32_t ah[5][4], bf[2][4];
            #pragma unroll
            for (int f = 0; f < 5; f++) ldm_x4(ah[f], ab + f * (16 * 272) + s * 32);
            #pragma unroll
            for (int jp = 0; jp < 2; jp++) ldm_x4(bf[jp], bb + jp * (16 * 272) + s * 32);
            #pragma unroll
            for (int jp = 0; jp < 2; jp++) {
                uint32_t b0[2] = { bf[jp][0], bf[jp][2] };
                uint32_t b1[2] = { bf[jp][1], bf[jp][3] };
                #pragma unroll
                for (int f = 0; f < 5; f++) {
                    mma_f16(acc[f][jp * 2],     ah[f], b0);
                    mma_f16(acc[f][jp * 2 + 1], ah[f], b1);
                }
            }
        }
    };

    load_chunk(0, 0);
    CP_COMMIT();
    for (int ch = 0; ch < CV_NCH; ch++) {
        if (ch + 1 < CV_NCH) {
            load_chunk((ch + 1) & 1, ch + 1);
            CP_COMMIT();
            CP_WAIT(1);
        } else {
            CP_WAIT(0);
        }
        __syncthreads();
        compute(ch & 1);
        __syncthreads();
    }

    float* dst = g_v + (size_t)bimg * (NC * NP);
    #pragma unroll
    for (int f = 0; f < 5; f++) {
        int o0 = mbase + wm * 80 + f * 16 + g;
        int o1 = o0 + 8;
        float b0 = bias[o0], b1 = bias[o1];
        #pragma unroll
        for (int j = 0; j < 4; j++) {
            int p = pbase + wn * 32 + j * 8 + tg * 2;
            *(float2*)(dst + (size_t)o0 * NP + p)
                = make_float2(acc[f][j][0] + b0, acc[f][j][1] + b0);
            *(float2*)(dst + (size_t)o1 * NP + p)
                = make_float2(acc[f][j][2] + b1, acc[f][j][3] + b1);
        }
    }
}

// ===== k projection (3xBF16 split, high accuracy): k = w_ctx @ kmap ======
// 8 warps as 2(m) x 4(n); warp tile 80x32. ldmatrix fragment loads.
#define SA_LD 23040
#define SB_LD 18432
#define SB_OFF 46080
#define BUFSTRIDE 82944
#define KP_SMEM (2 * BUFSTRIDE)

__global__ void __launch_bounds__(256, 1) k_kproj(const float* __restrict__ bias) {
    const int NCH = 16;
    extern __shared__ char smem[];
    uint32_t sb = smem_u32(smem);
    int tid = threadIdx.x;
    int bimg = blockIdx.x >> 2;
    int tt = blockIdx.x & 3;
    int mbase = (tt >> 1) * 160;
    int pbase = (tt & 1) * 128;

    const __nv_bfloat16* Bh = g_kmh + (size_t)bimg * (NP * CTX);
    const __nv_bfloat16* Bl = g_kml + (size_t)bimg * (NP * CTX);

    auto load_chunk = [&](int buf, int ch) {
        uint32_t base = sb + buf * BUFSTRIDE;
        int c0 = ch << 6;
        #pragma unroll
        for (int r = 0; r < 5; r++) {
            int id = r * 256 + tid;
            int row = id >> 3, v = id & 7;
            size_t so = (size_t)(mbase + row) * CTX + c0 + v * 8;
            uint32_t dst = base + (uint32_t)(row * 144 + v * 16);
            CP16(dst, g_wch + so, 16);
            CP16(dst + SA_LD, g_wcl + so, 16);
        }
        #pragma unroll
        for (int r = 0; r < 4; r++) {
            int id = r * 256 + tid;
            int row = id >> 3, v = id & 7;
            size_t so = (size_t)(pbase + row) * CTX + c0 + v * 8;
            uint32_t dst = base + SB_OFF + (uint32_t)(row * 144 + v * 16);
            CP16(dst, Bh + so, 16);
            CP16(dst + SB_LD, Bl + so, 16);
        }
    };

    int w = tid >> 5, l = tid & 31;
    int wm = w >> 2;
    int wn = w & 3;
    int g = l >> 2, tg = l & 3;
    int lrow = l & 15;
    int lcol = (l >> 4) * 16;

    float acc[5][4][4];
    #pragma unroll
    for (int f = 0; f < 5; f++)
        #pragma unroll
        for (int j = 0; j < 4; j++)
            #pragma unroll
            for (int q = 0; q < 4; q++) acc[f][j][q] = 0.f;

    auto compute = [&](int buf) {
        uint32_t ab = sb + buf * BUFSTRIDE
                    + (uint32_t)((wm * 80 + lrow) * 144 + lcol);
        uint32_t bb = sb + buf * BUFSTRIDE + SB_OFF
                    + (uint32_t)((wn * 32 + lrow) * 144 + lcol);
        #pragma unroll
        for (int s = 0; s < 4; s++) {
            uint32_t ah[5][4], al[5][4], bhf[2][4], blf[2][4];
            #pragma unroll
            for (int f = 0; f < 5; f++) {
                uint32_t a = ab + f * (16 * 144) + s * 32;
                ldm_x4(ah[f], a);
                ldm_x4(al[f], a + SA_LD);
            }
            #pragma unroll
            for (int jp = 0; jp < 2; jp++) {
                uint32_t a = bb + jp * (16 * 144) + s * 32;
                ldm_x4(bhf[jp], a);
                ldm_x4(blf[jp], a + SB_LD);
            }
            #pragma unroll
            for (int jp = 0; jp < 2; jp++) {
                uint32_t bh0[2] = { bhf[jp][0], bhf[jp][2] };
                uint32_t bh1[2] = { bhf[jp][1], bhf[jp][3] };
                uint32_t bl0[2] = { blf[jp][0], blf[jp][2] };
                uint32_t bl1[2] = { blf[jp][1], blf[jp][3] };
                #pragma unroll
                for (int f = 0; f < 5; f++) {
                    mma_bf16(acc[f][jp * 2],     ah[f], bh0);
                    mma_bf16(acc[f][jp * 2],     ah[f], bl0);
                    mma_bf16(acc[f][jp * 2],     al[f], bh0);
                    mma_bf16(acc[f][jp * 2 + 1], ah[f], bh1);
                    mma_bf16(acc[f][jp * 2 + 1], ah[f], bl1);
                    mma_bf16(acc[f][jp * 2 + 1], al[f], bh1);
                }
            }
        }
    };

    load_chunk(0, 0);
    CP_COMMIT();
    for (int ch = 0; ch < NCH; ch++) {
        if (ch + 1 < NCH) {
            load_chunk((ch + 1) & 1, ch + 1);
            CP_COMMIT();
            CP_WAIT(1);
        } else {
            CP_WAIT(0);
        }
        __syncthreads();
        compute(ch & 1);
        __syncthreads();
    }

    float* dst = g_k + (size_t)bimg * (NC * NP);
    #pragma unroll
    for (int f = 0; f < 5; f++) {
        int o0 = mbase + wm * 80 + f * 16 + g;
        int o1 = o0 + 8;
        float b0 = bias[o0], b1 = bias[o1];
        #pragma unroll
        for (int j = 0; j < 4; j++) {
            int p = pbase + wn * 32 + j * 8 + tg * 2;
            *(float2*)(dst + (size_t)o0 * NP + p)
                = make_float2(acc[f][j][0] + b0, acc[f][j][1] + b0);
            *(float2*)(dst + (size_t)o1 * NP + p)
                = make_float2(acc[f][j][2] + b1, acc[f][j][3] + b1);
        }
    }
}

// ====== kernel 1: ctx group norm + fp16 raw + bf16 hi/lo normed =========
__global__ __launch_bounds__(256) void k_ctx(const float* __restrict__ context,
                                             const float* __restrict__ cn_g,
                                             const float* __restrict__ cn_b) {
    int b = blockIdx.x >> 5, g = blockIdx.x & 31;
    __shared__ float s[32 * 257];
    __shared__ float redA[8], redB[8];
    __shared__ float stats[2];
    const float* src = context + (size_t)b * (NP * CTX) + g * 32;
    float sum = 0.f, sq = 0.f;
    for (int i = threadIdx.x; i < 8192; i += 256) {
        int cl = i & 31, p = i >> 5;
        float v = src[(size_t)p * CTX + cl];
        s[cl * 257 + p] = v;
        sum += v; sq += v * v;
    }
    #pragma unroll
    for (int off = 16; off; off >>= 1) {
        sum += __shfl_down_sync(0xffffffffu, sum, off);
        sq  += __shfl_down_sync(0xffffffffu, sq,  off);
    }
    if ((threadIdx.x & 31) == 0) { redA[threadIdx.x >> 5] = sum; redB[threadIdx.x >> 5] = sq; }
    __syncthreads();
    if (threadIdx.x == 0) {
        float a = 0.f, b2 = 0.f;
        #pragma unroll
        for (int w = 0; w < 8; w++) { a += redA[w]; b2 += redB[w]; }
        float mean = a * (1.f / 8192.f);
        float var  = b2 * (1.f / 8192.f) - mean * mean;
        stats[0] = mean; stats[1] = rsqrtf(var + 1e-6f);
    }
    __syncthreads();
    float mean = stats[0], rstd = stats[1];
    int cl = threadIdx.x & 31;
    int c = g * 32 + cl;
    float gam = cn_g[c] * rstd, bet = cn_b[c];
    for (int i = threadIdx.x; i < 8192; i += 256) {
        int p = i >> 5;
        float v = s[cl * 257 + p];
        size_t o = ((size_t)b * NP + p) * CTX + c;
        g_cxf[o] = __float2half(v);
        float nv = (v - mean) * gam + bet;
        __nv_bfloat16 nh = __float2bfloat16(nv);
        g_kmh[o] = nh;
        g_kml[o] = __float2bfloat16(nv - __bfloat162float(nh));
    }
}

// ================= kernel 2a: roi bilinear samples ======================
__global__ __launch_bounds__(256) void k_roi(const float* __restrict__ gx,
                                             const float* __restrict__ bbox,
                                             const float* __restrict__ indicator) {
    int idx = blockIdx.x * 256 + threadIdx.x;
    if (idx >= NB * XNC * NI) return;
    int b = idx / (XNC * NI);
    int r = idx - b * (XNC * NI);
    int c = r / NI;
    int i = r - c * NI;
    float out;
    if (c >= NC) {
        out = indicator[b * 2 + (c - NC)];
    } else {
        float x1 = bbox[b * 4 + 0], y1 = bbox[b * 4 + 1];
        float x2 = bbox[b * 4 + 2], y2 = bbox[b * 4 + 3];
        float rw = fmaxf(x2 - x1, 1.0f), rh = fmaxf(y2 - y1, 1.0f);
        int iy = i / 9, ix = i - iy * 9;
        float xs = x1 + ((float)ix + 0.5f) * (rw * (1.f / 9.f));
        float ys = y1 + ((float)iy + 0.5f) * (rh * (1.f / 9.f));
        float yv = fminf(fmaxf(ys, 0.f), 63.f);
        float xv = fminf(fmaxf(xs, 0.f), 63.f);
        int y0 = (int)floorf(yv), x0 = (int)floorf(xv);
        int y1i = min(y0 + 1, 63), x1i = min(x0 + 1, 63);
        float ly = yv - (float)y0, lx = xv - (float)x0;
        const float* im = gx + (size_t)b * (NC * HH * WW) + (size_t)c * (HH * WW);
        float g00 = im[y0 * WW + x0],  g01 = im[y0 * WW + x1i];
        float g10 = im[y1i * WW + x0], g11 = im[y1i * WW + x1i];
        out = g00 * (1.f - ly) * (1.f - lx) + g01 * (1.f - ly) * lx
            + g10 * ly * (1.f - lx)        + g11 * ly * lx;
    }
    g_xn[idx] = out;
}

// ============ kernel 2b: group norm over roi features ====================
__global__ __launch_bounds__(256) void k_gn_roi(const float* __restrict__ ln_g,
                                                const float* __restrict__ ln_b) {
    int b = blockIdx.x >> 5, g = blockIdx.x & 31;
    float* base = g_xn + (size_t)b * (XNC * NI) + g * 810;
    __shared__ float s[810];
    __shared__ float redA[8], redB[8];
    __shared__ float stats[2];
    float sum = 0.f, sq = 0.f;
    for (int i = threadIdx.x; i < 810; i += 256) {
        float v = base[i];
        s[i] = v; sum += v; sq += v * v;
    }
    #pragma unroll
    for (int off = 16; off; off >>= 1) {
        sum += __shfl_down_sync(0xffffffffu, sum, off);
        sq  += __shfl_down_sync(0xffffffffu, sq,  off);
    }
    if ((threadIdx.x & 31) == 0) { redA[threadIdx.x >> 5] = sum; redB[threadIdx.x >> 5] = sq; }
    __syncthreads();
    if (threadIdx.x == 0) {
        float a = 0.f, b2 = 0.f;
        #pragma unroll
        for (int w = 0; w < 8; w++) { a += redA[w]; b2 += redB[w]; }
        float mean = a * (1.f / 810.f);
        float var  = b2 * (1.f / 810.f) - mean * mean;
        stats[0] = mean; stats[1] = rsqrtf(var + 1e-6f);
    }
    __syncthreads();
    float mean = stats[0], rstd = stats[1];
    for (int i = threadIdx.x; i < 810; i += 256) {
        int c = g * 10 + i / 81;
        base[i] = (s[i] - mean) * rstd * ln_g[c] + ln_b[c];
    }
}

// ================= q projection SGEMM (FFMA, fp32-exact path) ===========
__global__ __launch_bounds__(256) void k_gemm_q(const float* __restrict__ A,
                                                const float* __restrict__ bias) {
    const int K = 322;
    __shared__ float sA[16][68];
    __shared__ float sB[16][128];
    int tid = threadIdx.x;
    int b = blockIdx.x;
    int mbase = blockIdx.y * 64;

    float acc[4][8];
    #pragma unroll
    for (int x = 0; x < 4; x++)
        #pragma unroll
        for (int y = 0; y < 8; y++) acc[x][y] = 0.f;

    int am = tid >> 2;
    int ak = (tid & 3) * 4;
    int bk = tid >> 4;
    int bn = (tid & 15) * 8;
    int tm = tid >> 4, tn = tid & 15;

    const float* abase = A + (size_t)(mbase + am) * K + ak;

    for (int k0 = 0; k0 < K; k0 += 16) {
        #pragma unroll
        for (int j = 0; j < 4; j++) {
            float v = 0.f;
            if (k0 + ak + j < 322) v = abase[k0 + j];
            sA[ak + j][am] = v;
        }
        int kk = k0 + bk;
        const float* bp = g_xn + (size_t)b * (XNC * NI) + (size_t)kk * NI;
        bool kok = kk < 322;
        #pragma unroll
        for (int j = 0; j < 8; j++) {
            int n = bn + j;
            sB[bk][bn + j] = (kok && n < NI) ? bp[n] : 0.f;
        }
        __syncthreads();
        #pragma unroll
        for (int k = 0; k < 16; k++) {
            float4 a4 = *(const float4*)&sA[k][tm * 4];
            float4 b0 = *(const float4*)&sB[k][tn * 8];
            float4 b1 = *(const float4*)&sB[k][tn * 8 + 4];
            float a[4]  = {a4.x, a4.y, a4.z, a4.w};
            float bb[8] = {b0.x, b0.y, b0.z, b0.w, b1.x, b1.y, b1.z, b1.w};
            #pragma unroll
            for (int x = 0; x < 4; x++)
                #pragma unroll
                for (int y = 0; y < 8; y++)
                    acc[x][y] = fmaf(a[x], bb[y], acc[x][y]);
        }
        __syncthreads();
    }
    #pragma unroll
    for (int x = 0; x < 4; x++) {
        int o = mbase + tm * 4 + x;
        float bs = bias[o];
        #pragma unroll
        for (int y = 0; y < 8; y++) {
            int n = tn * 8 + y;
            if (n < NI) g_q[(size_t)b * (NC * NI) + (size_t)o * NI + n] = acc[x][y] + bs;
        }
    }
}

// ======== kernel: sim = q^T k (81x64 per block, K=320), grid (32,4) ======
__global__ __launch_bounds__(256) void k_sim() {
    int b = blockIdx.x;
    int pb = blockIdx.y * 64;
    __shared__ float sq[8][96];
    __shared__ float sk[8][64];
    int tid = threadIdx.x;
    int ti = tid >> 4;
    int tp = tid & 15;
    float acc[6][4];
    #pragma unroll
    for (int x = 0; x < 6; x++)
        #pragma unroll
        for (int y = 0; y < 4; y++) acc[x][y] = 0.f;

    for (int o0 = 0; o0 < NC; o0 += 8) {
        for (int idx = tid; idx < 8 * NI; idx += 256) {
            int ko = idx / NI, i = idx - ko * NI;
            sq[ko][i] = g_q[(size_t)b * (NC * NI) + (size_t)(o0 + ko) * NI + i];
        }
        {
            int ko = tid >> 5;
            int pp = (tid & 31) * 2;
            *(float2*)&sk[ko][pp] = *(const float2*)(g_k + (size_t)b * (NC * NP)
                                       + (size_t)(o0 + ko) * NP + pb + pp);
        }
        __syncthreads();
        #pragma unroll
        for (int ko = 0; ko < 8; ko++) {
            float a[6];
            #pragma unroll
            for (int x = 0; x < 6; x++) a[x] = sq[ko][ti * 6 + x];
            float4 b0 = *(const float4*)&sk[ko][tp * 4];
            float bb[4] = {b0.x, b0.y, b0.z, b0.w};
            #pragma unroll
            for (int x = 0; x < 6; x++)
                #pragma unroll
                for (int y = 0; y < 4; y++)
                    acc[x][y] = fmaf(a[x], bb[y], acc[x][y]);
        }
        __syncthreads();
    }
    #pragma unroll
    for (int x = 0; x < 6; x++) {
        int i = ti * 6 + x;
        if (i < NI) {
            #pragma unroll
            for (int y = 0; y < 4; y++)
                g_sim[(size_t)b * (NI * NP) + (size_t)i * NP + pb + tp * 4 + y] = acc[x][y];
        }
    }
}

// ================= kernel: softmax rows -> attn ==========================
__global__ __launch_bounds__(256) void k_softmax(float* __restrict__ attn_out) {
    int b = blockIdx.x / NI, i = blockIdx.x - b * NI;
    int t = threadIdx.x;
    __shared__ float red[8];
    __shared__ float bc[1];
    float v = g_sim[(size_t)b * (NI * NP) + (size_t)i * NP + t];
    float m = v;
    #pragma unroll
    for (int off = 16; off; off >>= 1) m = fmaxf(m, __shfl_xor_sync(0xffffffffu, m, off));
    if ((t & 31) == 0) red[t >> 5] = m;
    __syncthreads();
    if (t == 0) {
        float mm = red[0];
        #pragma unroll
        for (int w = 1; w < 8; w++) mm = fmaxf(mm, red[w]);
        bc[0] = mm;
    }
    __syncthreads();
    float e = expf(v - bc[0]);
    float s = e;
    #pragma unroll
    for (int off = 16; off; off >>= 1) s += __shfl_xor_sync(0xffffffffu, s, off);
    if ((t & 31) == 0) red[t >> 5] = s;
    __syncthreads();
    if (t == 0) {
        float ss = 0.f;
        #pragma unroll
        for (int w = 0; w < 8; w++) ss += red[w];
        bc[0] = 1.f / ss;
    }
    __syncthreads();
    attn_out[(size_t)b * (NI * NP) + (size_t)i * NP + t] = e * bc[0];
}

// ================= kernel: xo = v_t @ attn^T (320x81, K=256) =============
__global__ __launch_bounds__(256) void k_xo(const float* __restrict__ attn) {
    int b = blockIdx.x;
    int mbase = blockIdx.y * 64;
    __shared__ float sv[16][68];
    __shared__ float sa[16][96];
    int tid = threadIdx.x;
    int am = tid >> 2, ak = (tid & 3) * 4;
    int tm = tid >> 4, tn = tid & 15;
    float acc[4][6];
    #pragma unroll
    for (int x = 0; x < 4; x++)
        #pragma unroll
        for (int y = 0; y < 6; y++) acc[x][y] = 0.f;

    for (int p0 = 0; p0 < NP; p0 += 16) {
        float4 v4 = *(const float4*)(g_v + (size_t)b * (NC * NP)
                                     + (size_t)(mbase + am) * NP + p0 + ak);
        sv[ak + 0][am] = v4.x; sv[ak + 1][am] = v4.y;
        sv[ak + 2][am] = v4.z; sv[ak + 3][am] = v4.w;
        for (int idx = tid; idx < 16 * NI; idx += 256) {
            int ii = idx >> 4, pp = idx & 15;
            sa[pp][ii] = attn[(size_t)b * (NI * NP) + (size_t)ii * NP + p0 + pp];
        }
        __syncthreads();
        #pragma unroll
        for (int p = 0; p < 16; p++) {
            float4 a4 = *(const float4*)&sv[p][tm * 4];
            float a[4] = {a4.x, a4.y, a4.z, a4.w};
            float bb[6];
            #pragma unroll
            for (int y = 0; y < 6; y++) bb[y] = sa[p][tn * 6 + y];
            #pragma unroll
            for (int x = 0; x < 4; x++)
                #pragma unroll
                for (int y = 0; y < 6; y++)
                    acc[x][y] = fmaf(a[x], bb[y], acc[x][y]);
        }
        __syncthreads();
    }
    #pragma unroll
    for (int x = 0; x < 4; x++) {
        int o = mbase + tm * 4 + x;
        #pragma unroll
        for (int y = 0; y < 6; y++) {
            int i = tn * 6 + y;
            if (i < NI) g_xo[(size_t)b * (NC * NI) + (size_t)o * NI + i] = acc[x][y];
        }
    }
}

// ========== kernel: residual + masked scatter (float4) ===================
__global__ __launch_bounds__(256) void k_out(const float* __restrict__ gx,
                                             const float* __restrict__ bbox,
                                             float* __restrict__ out) {
    int t = blockIdx.x * 256 + threadIdx.x;   // handles 4 consecutive x
    int base = t * 4;
    int x0 = base & 63;
    int y = (base >> 6) & 63;
    int bc = base >> 12;
    int b = bc / NC;
    int c = bc - b * NC;
    float4 val = *(const float4*)(gx + base);
    int bx1 = (int)(bbox[b * 4 + 0] * 64.f);
    int by1 = (int)(bbox[b * 4 + 1] * 64.f);
    int bx2 = max((int)(bbox[b * 4 + 2] * 64.f), bx1 + 1);
    int by2 = max((int)(bbox[b * 4 + 3] * 64.f), by1 + 1);
    if (y >= by1 && y < by2) {
        int sy = min(max((y - by1) * 9 / (by2 - by1), 0), 8);
        const float* xrow = g_xo + (size_t)b * (NC * NI) + (size_t)c * NI + sy * 9;
        float* vp = &val.x;
        #pragma unroll
        for (int j = 0; j < 4; j++) {
            int x = x0 + j;
            if (x >= bx1 && x < bx2) {
                int sx = min(max((x - bx1) * 9 / (bx2 - bx1), 0), 8);
                vp[j] += xrow[sx];
            }
        }
    }
    *(float4*)(out + base) = val;
}

// ============================ launch ======================================
extern "C" void kernel_launch(void* const* d_in, const int* in_sizes, int n_in,
                              void* d_out, int out_size) {
    const float* global_x  = (const float*)d_in[0];
    const float* context   = (const float*)d_in[1];
    const float* indicator = (const float*)d_in[2];
    const float* bbox      = (const float*)d_in[3];
    const float* ln_g      = (const float*)d_in[4];
    const float* ln_b      = (const float*)d_in[5];
    const float* cn_g      = (const float*)d_in[6];
    const float* cn_b      = (const float*)d_in[7];
    const float* w_in      = (const float*)d_in[8];
    const float* b_in      = (const float*)d_in[9];
    const float* w_ctx     = (const float*)d_in[10];
    const float* b_ctx     = (const float*)d_in[11];
    const float* w_out     = (const float*)d_in[12];
    const float* b_out     = (const float*)d_in[13];
    float* out  = (float*)d_out;
    float* attn = out + OUT_ATTN_OFF;

    static cudaStream_t s2 = nullptr, s3 = nullptr;
    static cudaEvent_t ev_fork = nullptr, ev_q = nullptr;
    static cudaEvent_t ev_ctx = nullptr, ev_wctx = nullptr, ev_conv = nullptr;
    static bool init_done = false;
    if (!init_done) {
        cudaFuncSetAttribute(k_conv, cudaFuncAttributeMaxDynamicSharedMemorySize,
                             CV_SMEM);
        cudaFuncSetAttribute(k_kproj, cudaFuncAttributeMaxDynamicSharedMemorySize,
                             KP_SMEM);
        cudaStreamCreateWithFlags(&s2, cudaStreamNonBlocking);
        cudaStreamCreateWithFlags(&s3, cudaStreamNonBlocking);
        cudaEventCreateWithFlags(&ev_fork, cudaEventDisableTiming);
        cudaEventCreateWithFlags(&ev_q,    cudaEventDisableTiming);
        cudaEventCreateWithFlags(&ev_ctx,  cudaEventDisableTiming);
        cudaEventCreateWithFlags(&ev_wctx, cudaEventDisableTiming);
        cudaEventCreateWithFlags(&ev_conv, cudaEventDisableTiming);
        init_done = true;
    }

    cudaEventRecord(ev_fork, 0);
    cudaStreamWaitEvent(s2, ev_fork, 0);
    cudaStreamWaitEvent(s3, ev_fork, 0);

    // s2: independent roi -> groupnorm -> q chain
    k_roi<<<(NB * XNC * NI + 255) / 256, 256, 0, s2>>>(global_x, bbox, indicator);
    k_gn_roi<<<NB * 32, 256, 0, s2>>>(ln_g, ln_b);
    k_gemm_q<<<dim3(32, 5), 256, 0, s2>>>(w_in, b_in);
    cudaEventRecord(ev_q, s2);

    // s3: weight conversions (overlap with k_ctx), then conv after ctx ready
    k_cvt_wctx<<<(NC * CTX) / 256, 256, 0, s3>>>(w_ctx);
    cudaEventRecord(ev_wctx, s3);
    k_cvt_w<<<(NC * KK) / 256, 256, 0, s3>>>(w_out);

    // default: context groupnorm + splits
    k_ctx<<<NB * 32, 256>>>(context, cn_g, cn_b);
    cudaEventRecord(ev_ctx, 0);

    // s3: conv (needs g_cxf from k_ctx + g_wf from cvt_w)
    cudaStreamWaitEvent(s3, ev_ctx, 0);
    k_conv<<<128, 256, CV_SMEM, s3>>>(b_out);
    cudaEventRecord(ev_conv, s3);

    // default: k projection (needs kmap from k_ctx + wch/wcl from cvt_wctx)
    cudaStreamWaitEvent(0, ev_wctx, 0);
    k_kproj<<<128, 256, KP_SMEM>>>(b_ctx);

    // attention tail on default
    cudaStreamWaitEvent(0, ev_q, 0);
    k_sim<<<dim3(NB, 4), 256>>>();
    k_softmax<<<NB * NI, 256>>>(attn);
    cudaStreamWaitEvent(0, ev_conv, 0);
    k_xo<<<dim3(NB, 5), 256>>>(attn);
    k_out<<<(NB * NC * HH * WW) / 1024, 256>>>(global_x, bbox, out);
}